// round 12
// baseline (speedup 1.0000x reference)
#include <cuda_runtime.h>
#include <cuda_bf16.h>
#include <cuda_fp16.h>
#include <math.h>
#include <stdint.h>

// Problem constants
#define NN 50000
#define EE 800000
#define GG 512
#define LL 6
#define NGAUSS 50
#define NG_PAD 56
#define TABM 2048                  // table intervals over [0, 7]
#define TABROWS (TABM + 1)
#define TAB_MAX 7.0f
#define TAB_INVSTEP ((float)TABM / TAB_MAX)
#define TAB_STEP (TAB_MAX / (float)TABM)
#define SKIP_D 6.97f
#define LN2F 0.69314718055994530942f
#define PIF 3.14159265358979323846f

// ---------------- scratch (device globals; no allocation allowed) -------------
__device__ __align__(256) float g_h[NN * 64];
__device__ __align__(256) float g_hn[NN * 128];      // K=128 padded
__device__ __align__(256) float g_v[NN * 128];
__device__ __align__(256) float g_vlin[NN * 128];
__device__ __align__(256) float g_agg[NN * 128];
__device__ __align__(256) float g_t1[NN * 128];
__device__ __align__(256) float g_dist[EE];
__device__ __align__(256) float g_demb[TABROWS * NG_PAD];
__device__ __align__(256) float g_tabh[TABROWS * 768];   // all 6 layers, N=768
__device__ __align__(256) float g_tables[LL * TABROWS * 128];
__device__ __align__(256) __half2 g_ptab[LL * TABM * 128];  // fp16 (T[i],T[i+1]) pairs
__device__ __align__(256) float g_bnacc[128];
__device__ __align__(256) float g_u1bpad[128];
__device__ __align__(256) float g_u2bpad[128];
__device__ __align__(256) float g_m1all[NG_PAD * 768];
__device__ __align__(256) float g_b1all[768];
// bf16 hi/lo split, pre-transposed weights [slot][n][k]
// slots 0..23: l*4 + {lin,mlp2,v1,v2}; 24: u1 (N-pad); 25: fe2 (K-pad); 26: u2 (N,K-pad)
__device__ __align__(256) __nv_bfloat16 g_wthi[27 * 128 * 128];
__device__ __align__(256) __nv_bfloat16 g_wtlo[27 * 128 * 128];
// CSR-by-destination edge sort
__device__ __align__(256) int   g_nhist[NN];
__device__ __align__(256) int   g_nstart[NN + 1];
__device__ __align__(256) int   g_ncursor[NN];
__device__ __align__(256) int   g_erow[EE];
__device__ __align__(256) float g_efi[EE];
// grid barrier state (self-resetting across uses & graph replays)
__device__ int g_bar_count;
__device__ int g_bar_gen;

// ---------------- helpers ---------------------------------------------------
__device__ __forceinline__ float sspf(float x) {
    return fmaxf(x, 0.0f) + log1pf(expf(-fabsf(x))) - LN2F;
}
__device__ __forceinline__ unsigned long long bcast2(float x) {
    unsigned long long r;
    asm("mov.b64 %0, {%1, %1};" : "=l"(r) : "f"(x));
    return r;
}
__device__ __forceinline__ void ffma2(unsigned long long& d,
                                      unsigned long long a, unsigned long long b) {
    asm("fma.rn.f32x2 %0, %1, %2, %0;" : "+l"(d) : "l"(a), "l"(b));
}
__device__ __forceinline__ void unpack2(unsigned long long v, float& lo, float& hi) {
    asm("mov.b64 {%0, %1}, %2;" : "=f"(lo), "=f"(hi) : "l"(v));
}
__device__ __forceinline__ uint32_t smem_u32(const void* p) {
    uint32_t a;
    asm("{ .reg .u64 t; cvta.to.shared.u64 t, %1; cvt.u32.u64 %0, t; }" : "=r"(a) : "l"(p));
    return a;
}
__device__ __forceinline__ void mma16816(float* c, const uint32_t* a,
                                         uint32_t b0, uint32_t b1) {
    asm volatile(
        "mma.sync.aligned.m16n8k16.row.col.f32.bf16.bf16.f32 "
        "{%0,%1,%2,%3}, {%4,%5,%6,%7}, {%8,%9}, {%0,%1,%2,%3};"
        : "+f"(c[0]), "+f"(c[1]), "+f"(c[2]), "+f"(c[3])
        : "r"(a[0]), "r"(a[1]), "r"(a[2]), "r"(a[3]), "r"(b0), "r"(b1));
}
__device__ __forceinline__ void ldsm4(uint32_t* r, uint32_t addr) {
    asm volatile("ldmatrix.sync.aligned.m8n8.x4.shared.b16 {%0,%1,%2,%3}, [%4];"
        : "=r"(r[0]), "=r"(r[1]), "=r"(r[2]), "=r"(r[3]) : "r"(addr));
}
__device__ __forceinline__ uint32_t packbf2(float x, float y) {
    __nv_bfloat162 h = __float22bfloat162_rn(make_float2(x, y));
    return *(uint32_t*)&h;
}

// grid-wide barrier: all gridDim.x blocks must be co-resident.
__device__ __forceinline__ void gbar() {
    __syncthreads();
    if (threadIdx.x == 0) {
        int gen = *(volatile int*)&g_bar_gen;
        __threadfence();
        if (atomicAdd(&g_bar_count, 1) == (int)gridDim.x - 1) {
            g_bar_count = 0;
            __threadfence();
            atomicExch(&g_bar_gen, gen + 1);
        } else {
            while (*(volatile int*)&g_bar_gen == gen) { __nanosleep(64); }
        }
        __threadfence();
    }
    __syncthreads();
}

#define MG_STRIDE 136   // bf16 per smem row (272B) — conflict-free ldmatrix
#define MG_A1 (64 * MG_STRIDE * 2)
#define MG_B1 (128 * MG_STRIDE * 2)
#define MG_SMEM (2 * MG_A1 + 2 * MG_B1)
#define FG_SMEM (2 * MG_A1 + 4 * MG_B1)

// ================= bf16x3 HMMA GEMM v3 (pipelined A prefetch) ================
__global__ void __launch_bounds__(256, 2) mgemm(
    const float* __restrict__ A, const __nv_bfloat16* __restrict__ Bhi,
    const __nv_bfloat16* __restrict__ Blo, const float* __restrict__ bias,
    const float* __restrict__ res, float* __restrict__ C, int M, int act,
    int tiles_per_mat, int nmats, int lda) {
    extern __shared__ char smem[];
    __nv_bfloat16* Ahs = (__nv_bfloat16*)(smem);
    __nv_bfloat16* Als = (__nv_bfloat16*)(smem + MG_A1);
    __nv_bfloat16* Bhs = (__nv_bfloat16*)(smem + 2 * MG_A1);
    __nv_bfloat16* Bls = (__nv_bfloat16*)(smem + 2 * MG_A1 + MG_B1);
    const uint32_t sb = smem_u32(smem);
    const uint32_t sAh = sb, sAl = sb + MG_A1;
    const uint32_t sBh = sb + 2 * MG_A1, sBl = sb + 2 * MG_A1 + MG_B1;

    const int t = threadIdx.x;
    const int lane = t & 31;
    const int w = t >> 5;
    const int wm = (w & 3) * 16;
    const int wn = (w >> 2) * 64;
    const int gid = lane >> 2;
    const int tg = lane & 3;

    const int arow_l = t >> 2;
    const int aseg = (t & 3) * 32;

    const int lrow = ((t >> 3) & 1) * 8 + (t & 7);
    const int lkb  = ((t >> 4) & 1) * 16;
    const uint32_t offA0 = (uint32_t)(wm + lrow) * 272 + lkb;
    const int brow = ((t >> 4) & 1) * 8 + (t & 7);
    const int bkb  = ((t >> 3) & 1) * 16;
    uint32_t offB[4];
#pragma unroll
    for (int p = 0; p < 4; p++) offB[p] = (uint32_t)(wn + p * 16 + brow) * 272 + bkb;

    const int total_tiles = tiles_per_mat * nmats;
    int cur_mat = -1;
    const float4 z4 = make_float4(0, 0, 0, 0);

    float4 pa[8];
    if (blockIdx.x < total_tiles) {
        int tl = blockIdx.x;
        int mat = (nmats == 1) ? 0 : (tl / tiles_per_mat);
        int lt  = (nmats == 1) ? tl : (tl % tiles_per_mat);
        int grow = lt * 64 + arow_l;
        bool valid = grow < M;
        const float4* ap = (const float4*)(A + (size_t)(valid ? grow : 0) * lda + mat * 128 + aseg);
#pragma unroll
        for (int c = 0; c < 8; c++) pa[c] = valid ? ap[c] : z4;
    }

    for (int tile = blockIdx.x; tile < total_tiles; tile += gridDim.x) {
        const int mat = (nmats == 1) ? 0 : (tile / tiles_per_mat);
        const int lt  = (nmats == 1) ? tile : (tile % tiles_per_mat);
        const int bm = lt * 64;

        if (mat != cur_mat) {
            cur_mat = mat;
            const __nv_bfloat16* bh = Bhi + (size_t)mat * 4 * 16384;
            const __nv_bfloat16* bl = Blo + (size_t)mat * 4 * 16384;
            int row = t >> 1, half = (t & 1) * 64;
            const uint4* bhp = (const uint4*)(bh + (size_t)row * 128 + half);
            const uint4* blp = (const uint4*)(bl + (size_t)row * 128 + half);
            __nv_bfloat16* dbh = Bhs + row * MG_STRIDE + half;
            __nv_bfloat16* dbl = Bls + row * MG_STRIDE + half;
#pragma unroll
            for (int c = 0; c < 8; c++) {
                *(uint4*)(dbh + c * 8) = bhp[c];
                *(uint4*)(dbl + c * 8) = blp[c];
            }
        }

        {
            __nv_bfloat16* ahp = Ahs + arow_l * MG_STRIDE + aseg;
            __nv_bfloat16* alp = Als + arow_l * MG_STRIDE + aseg;
#pragma unroll
            for (int c = 0; c < 8; c++) {
                float4 v = pa[c];
                uint32_t h0 = packbf2(v.x, v.y);
                uint32_t h1 = packbf2(v.z, v.w);
                __nv_bfloat162* h0p = (__nv_bfloat162*)&h0;
                __nv_bfloat162* h1p = (__nv_bfloat162*)&h1;
                uint32_t l0 = packbf2(v.x - __bfloat162float(h0p->x), v.y - __bfloat162float(h0p->y));
                uint32_t l1 = packbf2(v.z - __bfloat162float(h1p->x), v.w - __bfloat162float(h1p->y));
                *(uint2*)(ahp + c * 4) = make_uint2(h0, h1);
                *(uint2*)(alp + c * 4) = make_uint2(l0, l1);
            }
        }
        __syncthreads();

        {
            int ntile = tile + gridDim.x;
            if (ntile < total_tiles) {
                int nmat = (nmats == 1) ? 0 : (ntile / tiles_per_mat);
                int nlt  = (nmats == 1) ? ntile : (ntile % tiles_per_mat);
                int grow = nlt * 64 + arow_l;
                bool valid = grow < M;
                const float4* ap = (const float4*)(A + (size_t)(valid ? grow : 0) * lda + nmat * 128 + aseg);
#pragma unroll
                for (int c = 0; c < 8; c++) pa[c] = valid ? ap[c] : z4;
            }
        }

        float acc[8][4];
#pragma unroll
        for (int ni = 0; ni < 8; ni++)
#pragma unroll
            for (int q = 0; q < 4; q++) acc[ni][q] = 0.0f;

#pragma unroll
        for (int k0 = 0; k0 < 8; k0++) {
            const uint32_t ko = k0 * 32;
            uint32_t ah[4], al[4];
            ldsm4(ah, sAh + offA0 + ko);
            ldsm4(al, sAl + offA0 + ko);
#pragma unroll
            for (int p = 0; p < 4; p++) {
                uint32_t bh[4], bl[4];
                ldsm4(bh, sBh + offB[p] + ko);
                ldsm4(bl, sBl + offB[p] + ko);
                mma16816(acc[2 * p],     ah, bh[0], bh[1]);
                mma16816(acc[2 * p],     ah, bl[0], bl[1]);
                mma16816(acc[2 * p],     al, bh[0], bh[1]);
                mma16816(acc[2 * p + 1], ah, bh[2], bh[3]);
                mma16816(acc[2 * p + 1], ah, bl[2], bl[3]);
                mma16816(acc[2 * p + 1], al, bh[2], bh[3]);
            }
        }

        const float* mbias = bias ? (bias + (size_t)mat * 128) : nullptr;
        float* mC = C;
        if (nmats > 1) mC = C + (size_t)mat * (size_t)TABROWS * 128;
        {
            int r0 = bm + wm + gid;
            int r1 = r0 + 8;
            float sc0 = 1.0f, sc1 = 1.0f;
            if (act == 3) {
                sc0 = 0.5f * (cosf((float)r0 * TAB_STEP * (PIF / 6.0f)) + 1.0f);
                sc1 = 0.5f * (cosf((float)r1 * TAB_STEP * (PIF / 6.0f)) + 1.0f);
            }
#pragma unroll
            for (int ni = 0; ni < 8; ni++) {
                int cb = wn + ni * 8 + tg * 2;
                float b0 = mbias ? __ldg(mbias + cb) : 0.0f;
                float b1 = mbias ? __ldg(mbias + cb + 1) : 0.0f;
                float* a4 = acc[ni];
                float v00 = a4[0] + b0, v01 = a4[1] + b1;
                float v10 = a4[2] + b0, v11 = a4[3] + b1;
                if (act == 1) {
                    v00 = fmaxf(v00, 0.0f); v01 = fmaxf(v01, 0.0f);
                    v10 = fmaxf(v10, 0.0f); v11 = fmaxf(v11, 0.0f);
                } else if (act == 2) {
                    v00 = sspf(v00); v01 = sspf(v01); v10 = sspf(v10); v11 = sspf(v11);
                } else if (act == 3) {
                    v00 *= sc0; v01 *= sc0; v10 *= sc1; v11 *= sc1;
                }
                if (r0 < M) {
                    if (res) {
                        float2 rr = *(const float2*)(res + (size_t)r0 * 128 + cb);
                        v00 += rr.x; v01 += rr.y;
                    }
                    *(float2*)(mC + (size_t)r0 * 128 + cb) = make_float2(v00, v01);
                }
                if (r1 < M) {
                    if (res) {
                        float2 rr = *(const float2*)(res + (size_t)r1 * 128 + cb);
                        v10 += rr.x; v11 += rr.y;
                    }
                    *(float2*)(mC + (size_t)r1 * 128 + cb) = make_float2(v10, v11);
                }
            }
        }
        __syncthreads();
    }
}

// ================= fused double-GEMM (separate launch, used for readout) =====
__global__ void __launch_bounds__(256, 1) fgemm(
    const float* __restrict__ A,
    const __nv_bfloat16* __restrict__ B1hi, const __nv_bfloat16* __restrict__ B1lo,
    const __nv_bfloat16* __restrict__ B2hi, const __nv_bfloat16* __restrict__ B2lo,
    const float* __restrict__ bias1, const float* __restrict__ bias2,
    const float* __restrict__ res, float* __restrict__ C, int M, int tiles) {
    extern __shared__ char smem[];
    __nv_bfloat16* Ahs  = (__nv_bfloat16*)(smem);
    __nv_bfloat16* Als  = (__nv_bfloat16*)(smem + MG_A1);
    __nv_bfloat16* B1hs = (__nv_bfloat16*)(smem + 2 * MG_A1);
    __nv_bfloat16* B1ls = (__nv_bfloat16*)(smem + 2 * MG_A1 + MG_B1);
    __nv_bfloat16* B2hs = (__nv_bfloat16*)(smem + 2 * MG_A1 + 2 * MG_B1);
    __nv_bfloat16* B2ls = (__nv_bfloat16*)(smem + 2 * MG_A1 + 3 * MG_B1);
    const uint32_t sb = smem_u32(smem);
    const uint32_t sAh = sb, sAl = sb + MG_A1;
    const uint32_t sB1h = sb + 2 * MG_A1, sB1l = sb + 2 * MG_A1 + MG_B1;
    const uint32_t sB2h = sb + 2 * MG_A1 + 2 * MG_B1, sB2l = sb + 2 * MG_A1 + 3 * MG_B1;

    const int t = threadIdx.x;
    const int lane = t & 31;
    const int w = t >> 5;
    const int wm = (w & 3) * 16;
    const int wn = (w >> 2) * 64;
    const int gid = lane >> 2;
    const int tg = lane & 3;
    const int arow_l = t >> 2;
    const int aseg = (t & 3) * 32;
    const int lrow = ((t >> 3) & 1) * 8 + (t & 7);
    const int lkb  = ((t >> 4) & 1) * 16;
    const uint32_t offA0 = (uint32_t)(wm + lrow) * 272 + lkb;
    const int brow = ((t >> 4) & 1) * 8 + (t & 7);
    const int bkb  = ((t >> 3) & 1) * 16;
    uint32_t offB[4];
#pragma unroll
    for (int p = 0; p < 4; p++) offB[p] = (uint32_t)(wn + p * 16 + brow) * 272 + bkb;

    {
        int row = t >> 1, half = (t & 1) * 64;
        const uint4* b1h = (const uint4*)(B1hi + (size_t)row * 128 + half);
        const uint4* b1l = (const uint4*)(B1lo + (size_t)row * 128 + half);
        const uint4* b2h = (const uint4*)(B2hi + (size_t)row * 128 + half);
        const uint4* b2l = (const uint4*)(B2lo + (size_t)row * 128 + half);
        __nv_bfloat16* d1h = B1hs + row * MG_STRIDE + half;
        __nv_bfloat16* d1l = B1ls + row * MG_STRIDE + half;
        __nv_bfloat16* d2h = B2hs + row * MG_STRIDE + half;
        __nv_bfloat16* d2l = B2ls + row * MG_STRIDE + half;
#pragma unroll
        for (int c = 0; c < 8; c++) {
            *(uint4*)(d1h + c * 8) = b1h[c];
            *(uint4*)(d1l + c * 8) = b1l[c];
            *(uint4*)(d2h + c * 8) = b2h[c];
            *(uint4*)(d2l + c * 8) = b2l[c];
        }
    }

    const float4 z4 = make_float4(0, 0, 0, 0);
    float4 pa[8];
    if (blockIdx.x < tiles) {
        int grow = blockIdx.x * 64 + arow_l;
        bool valid = grow < M;
        const float4* ap = (const float4*)(A + (size_t)(valid ? grow : 0) * 128 + aseg);
#pragma unroll
        for (int c = 0; c < 8; c++) pa[c] = valid ? ap[c] : z4;
    }

    for (int tile = blockIdx.x; tile < tiles; tile += gridDim.x) {
        const int bm = tile * 64;
        {
            __nv_bfloat16* ahp = Ahs + arow_l * MG_STRIDE + aseg;
            __nv_bfloat16* alp = Als + arow_l * MG_STRIDE + aseg;
#pragma unroll
            for (int c = 0; c < 8; c++) {
                float4 v = pa[c];
                uint32_t h0 = packbf2(v.x, v.y);
                uint32_t h1 = packbf2(v.z, v.w);
                __nv_bfloat162* h0p = (__nv_bfloat162*)&h0;
                __nv_bfloat162* h1p = (__nv_bfloat162*)&h1;
                uint32_t l0 = packbf2(v.x - __bfloat162float(h0p->x), v.y - __bfloat162float(h0p->y));
                uint32_t l1 = packbf2(v.z - __bfloat162float(h1p->x), v.w - __bfloat162float(h1p->y));
                *(uint2*)(ahp + c * 4) = make_uint2(h0, h1);
                *(uint2*)(alp + c * 4) = make_uint2(l0, l1);
            }
        }
        __syncthreads();
        {
            int ntile = tile + gridDim.x;
            if (ntile < tiles) {
                int grow = ntile * 64 + arow_l;
                bool valid = grow < M;
                const float4* ap = (const float4*)(A + (size_t)(valid ? grow : 0) * 128 + aseg);
#pragma unroll
                for (int c = 0; c < 8; c++) pa[c] = valid ? ap[c] : z4;
            }
        }

        float acc[8][4];
#pragma unroll
        for (int ni = 0; ni < 8; ni++)
#pragma unroll
            for (int q = 0; q < 4; q++) acc[ni][q] = 0.0f;
#pragma unroll
        for (int k0 = 0; k0 < 8; k0++) {
            const uint32_t ko = k0 * 32;
            uint32_t ah[4], al[4];
            ldsm4(ah, sAh + offA0 + ko);
            ldsm4(al, sAl + offA0 + ko);
#pragma unroll
            for (int p = 0; p < 4; p++) {
                uint32_t bh[4], bl[4];
                ldsm4(bh, sB1h + offB[p] + ko);
                ldsm4(bl, sB1l + offB[p] + ko);
                mma16816(acc[2 * p],     ah, bh[0], bh[1]);
                mma16816(acc[2 * p],     ah, bl[0], bl[1]);
                mma16816(acc[2 * p],     al, bh[0], bh[1]);
                mma16816(acc[2 * p + 1], ah, bh[2], bh[3]);
                mma16816(acc[2 * p + 1], ah, bl[2], bl[3]);
                mma16816(acc[2 * p + 1], al, bh[2], bh[3]);
            }
        }
        __syncthreads();
        {
            int r0 = wm + gid;
            int r1 = r0 + 8;
#pragma unroll
            for (int ni = 0; ni < 8; ni++) {
                int cb = wn + ni * 8 + tg * 2;
                float b0 = __ldg(bias1 + cb);
                float b1 = __ldg(bias1 + cb + 1);
                float* a4 = acc[ni];
                float v00 = sspf(a4[0] + b0), v01 = sspf(a4[1] + b1);
                float v10 = sspf(a4[2] + b0), v11 = sspf(a4[3] + b1);
                uint32_t h0 = packbf2(v00, v01);
                uint32_t h1 = packbf2(v10, v11);
                __nv_bfloat162* h0p = (__nv_bfloat162*)&h0;
                __nv_bfloat162* h1p = (__nv_bfloat162*)&h1;
                uint32_t l0 = packbf2(v00 - __bfloat162float(h0p->x), v01 - __bfloat162float(h0p->y));
                uint32_t l1 = packbf2(v10 - __bfloat162float(h1p->x), v11 - __bfloat162float(h1p->y));
                *(uint32_t*)(Ahs + r0 * MG_STRIDE + cb) = h0;
                *(uint32_t*)(Ahs + r1 * MG_STRIDE + cb) = h1;
                *(uint32_t*)(Als + r0 * MG_STRIDE + cb) = l0;
                *(uint32_t*)(Als + r1 * MG_STRIDE + cb) = l1;
            }
        }
        __syncthreads();
#pragma unroll
        for (int ni = 0; ni < 8; ni++)
#pragma unroll
            for (int q = 0; q < 4; q++) acc[ni][q] = 0.0f;
#pragma unroll
        for (int k0 = 0; k0 < 8; k0++) {
            const uint32_t ko = k0 * 32;
            uint32_t ah[4], al[4];
            ldsm4(ah, sAh + offA0 + ko);
            ldsm4(al, sAl + offA0 + ko);
#pragma unroll
            for (int p = 0; p < 4; p++) {
                uint32_t bh[4], bl[4];
                ldsm4(bh, sB2h + offB[p] + ko);
                ldsm4(bl, sB2l + offB[p] + ko);
                mma16816(acc[2 * p],     ah, bh[0], bh[1]);
                mma16816(acc[2 * p],     ah, bl[0], bl[1]);
                mma16816(acc[2 * p],     al, bh[0], bh[1]);
                mma16816(acc[2 * p + 1], ah, bh[2], bh[3]);
                mma16816(acc[2 * p + 1], ah, bl[2], bl[3]);
                mma16816(acc[2 * p + 1], al, bh[2], bh[3]);
            }
        }
        {
            int r0 = bm + wm + gid;
            int r1 = r0 + 8;
#pragma unroll
            for (int ni = 0; ni < 8; ni++) {
                int cb = wn + ni * 8 + tg * 2;
                float b0 = __ldg(bias2 + cb);
                float b1 = __ldg(bias2 + cb + 1);
                float* a4 = acc[ni];
                float v00 = a4[0] + b0, v01 = a4[1] + b1;
                float v10 = a4[2] + b0, v11 = a4[3] + b1;
                if (r0 < M) {
                    if (res) {
                        float2 rr = *(const float2*)(res + (size_t)r0 * 128 + cb);
                        v00 += rr.x; v01 += rr.y;
                    }
                    *(float2*)(C + (size_t)r0 * 128 + cb) = make_float2(v00, v01);
                }
                if (r1 < M) {
                    if (res) {
                        float2 rr = *(const float2*)(res + (size_t)r1 * 128 + cb);
                        v10 += rr.x; v11 += rr.y;
                    }
                    *(float2*)(C + (size_t)r1 * 128 + cb) = make_float2(v10, v11);
                }
            }
        }
        __syncthreads();
    }
}

// ================= persistent megakernel: all 6 interaction layers ===========
// grid = #SMs (1 CTA/SM via 174KB smem). Cross-block data via L2 (__ldcg).
__global__ void __launch_bounds__(256, 1) mega(
    const __nv_bfloat16* __restrict__ whi, const __nv_bfloat16* __restrict__ wlo,
    const float* __restrict__ v1_b, const float* __restrict__ v2_b,
    float* __restrict__ v, float* __restrict__ vlin, float* __restrict__ agg,
    const __half2* __restrict__ ptab, int n, int tiles) {
    extern __shared__ char smem[];
    __nv_bfloat16* Ahs  = (__nv_bfloat16*)(smem);
    __nv_bfloat16* Als  = (__nv_bfloat16*)(smem + MG_A1);
    __nv_bfloat16* B1hs = (__nv_bfloat16*)(smem + 2 * MG_A1);
    __nv_bfloat16* B1ls = (__nv_bfloat16*)(smem + 2 * MG_A1 + MG_B1);
    __nv_bfloat16* B2hs = (__nv_bfloat16*)(smem + 2 * MG_A1 + 2 * MG_B1);
    __nv_bfloat16* B2ls = (__nv_bfloat16*)(smem + 2 * MG_A1 + 3 * MG_B1);
    const uint32_t sb = smem_u32(smem);
    const uint32_t sAh = sb, sAl = sb + MG_A1;
    const uint32_t sB1h = sb + 2 * MG_A1, sB1l = sb + 2 * MG_A1 + MG_B1;
    const uint32_t sB2h = sb + 2 * MG_A1 + 2 * MG_B1, sB2l = sb + 2 * MG_A1 + 3 * MG_B1;

    const int t = threadIdx.x;
    const int lane = t & 31;
    const int w = t >> 5;
    const int wm = (w & 3) * 16;
    const int wn = (w >> 2) * 64;
    const int gid = lane >> 2;
    const int tg = lane & 3;
    const int arow_l = t >> 2;
    const int aseg = (t & 3) * 32;
    const int lrow = ((t >> 3) & 1) * 8 + (t & 7);
    const int lkb  = ((t >> 4) & 1) * 16;
    const uint32_t offA0 = (uint32_t)(wm + lrow) * 272 + lkb;
    const int brow = ((t >> 4) & 1) * 8 + (t & 7);
    const int bkb  = ((t >> 3) & 1) * 16;
    uint32_t offB[4];
#pragma unroll
    for (int p = 0; p < 4; p++) offB[p] = (uint32_t)(wn + p * 16 + brow) * 272 + bkb;
    const int srow = t >> 1, shalf = (t & 1) * 64;   // B staging coords
    const float4 z4 = make_float4(0, 0, 0, 0);

    for (int l = 0; l < LL; l++) {
        const __nv_bfloat16* lw_hi = whi + (size_t)(l * 4 + 0) * 16384;
        const __nv_bfloat16* lw_lo = wlo + (size_t)(l * 4 + 0) * 16384;
        const __nv_bfloat16* w1_hi = whi + (size_t)(l * 4 + 2) * 16384;
        const __nv_bfloat16* w1_lo = wlo + (size_t)(l * 4 + 2) * 16384;
        const __nv_bfloat16* w2_hi = whi + (size_t)(l * 4 + 3) * 16384;
        const __nv_bfloat16* w2_lo = wlo + (size_t)(l * 4 + 3) * 16384;
        const float* b1 = v1_b + (size_t)l * 128;
        const float* b2 = v2_b + (size_t)l * 128;
        const __half2* pt = ptab + (size_t)l * TABM * 128;

        // ======== phase A: vlin = v @ lin ========
        {
            const uint4* bhp = (const uint4*)(lw_hi + (size_t)srow * 128 + shalf);
            const uint4* blp = (const uint4*)(lw_lo + (size_t)srow * 128 + shalf);
            __nv_bfloat16* dbh = B1hs + srow * MG_STRIDE + shalf;
            __nv_bfloat16* dbl = B1ls + srow * MG_STRIDE + shalf;
#pragma unroll
            for (int c = 0; c < 8; c++) {
                *(uint4*)(dbh + c * 8) = __ldg(bhp + c);
                *(uint4*)(dbl + c * 8) = __ldg(blp + c);
            }
        }
        __syncthreads();
        {
            float4 pa[8];
            int tile0 = blockIdx.x;
            if (tile0 < tiles) {
                int grow = tile0 * 64 + arow_l;
                bool valid = grow < n;
                const float4* ap = (const float4*)(v + (size_t)(valid ? grow : 0) * 128 + aseg);
#pragma unroll
                for (int c = 0; c < 8; c++) pa[c] = valid ? __ldcg(ap + c) : z4;
            }
            for (int tile = tile0; tile < tiles; tile += gridDim.x) {
                const int bm = tile * 64;
                {
                    __nv_bfloat16* ahp = Ahs + arow_l * MG_STRIDE + aseg;
                    __nv_bfloat16* alp = Als + arow_l * MG_STRIDE + aseg;
#pragma unroll
                    for (int c = 0; c < 8; c++) {
                        float4 vv = pa[c];
                        uint32_t h0 = packbf2(vv.x, vv.y);
                        uint32_t h1 = packbf2(vv.z, vv.w);
                        __nv_bfloat162* h0p = (__nv_bfloat162*)&h0;
                        __nv_bfloat162* h1p = (__nv_bfloat162*)&h1;
                        uint32_t l0 = packbf2(vv.x - __bfloat162float(h0p->x), vv.y - __bfloat162float(h0p->y));
                        uint32_t l1 = packbf2(vv.z - __bfloat162float(h1p->x), vv.w - __bfloat162float(h1p->y));
                        *(uint2*)(ahp + c * 4) = make_uint2(h0, h1);
                        *(uint2*)(alp + c * 4) = make_uint2(l0, l1);
                    }
                }
                __syncthreads();
                {
                    int ntile = tile + gridDim.x;
                    if (ntile < tiles) {
                        int grow = ntile * 64 + arow_l;
                        bool valid = grow < n;
                        const float4* ap = (const float4*)(v + (size_t)(valid ? grow : 0) * 128 + aseg);
#pragma unroll
                        for (int c = 0; c < 8; c++) pa[c] = valid ? __ldcg(ap + c) : z4;
                    }
                }
                float acc[8][4];
#pragma unroll
                for (int ni = 0; ni < 8; ni++)
#pragma unroll
                    for (int q = 0; q < 4; q++) acc[ni][q] = 0.0f;
#pragma unroll
                for (int k0 = 0; k0 < 8; k0++) {
                    const uint32_t ko = k0 * 32;
                    uint32_t ah[4], al[4];
                    ldsm4(ah, sAh + offA0 + ko);
                    ldsm4(al, sAl + offA0 + ko);
#pragma unroll
                    for (int p = 0; p < 4; p++) {
                        uint32_t bh[4], bl[4];
                        ldsm4(bh, sB1h + offB[p] + ko);
                        ldsm4(bl, sB1l + offB[p] + ko);
                        mma16816(acc[2 * p],     ah, bh[0], bh[1]);
                        mma16816(acc[2 * p],     ah, bl[0], bl[1]);
                        mma16816(acc[2 * p],     al, bh[0], bh[1]);
                        mma16816(acc[2 * p + 1], ah, bh[2], bh[3]);
                        mma16816(acc[2 * p + 1], ah, bl[2], bl[3]);
                        mma16816(acc[2 * p + 1], al, bh[2], bh[3]);
                    }
                }
                {
                    int r0 = bm + wm + gid;
                    int r1 = r0 + 8;
#pragma unroll
                    for (int ni = 0; ni < 8; ni++) {
                        int cb = wn + ni * 8 + tg * 2;
                        float* a4 = acc[ni];
                        if (r0 < n) *(float2*)(vlin + (size_t)r0 * 128 + cb) = make_float2(a4[0], a4[1]);
                        if (r1 < n) *(float2*)(vlin + (size_t)r1 * 128 + cb) = make_float2(a4[2], a4[3]);
                    }
                }
                __syncthreads();
            }
        }
        gbar();

        // ======== phase B: agg = gather(vlin, table) ========
        for (int node = blockIdx.x * 8 + w; node < n; node += gridDim.x * 8) {
            int j = __ldg(g_nstart + node);
            int end = __ldg(g_nstart + node + 1);
            float a0 = 0.0f, a1 = 0.0f, a2 = 0.0f, a3 = 0.0f;
            for (; j + 4 <= end; j += 4) {
                int ri[4]; float fi[4]; int ii[4]; float fr[4];
                uint4 tp[4]; float4 vv[4];
#pragma unroll
                for (int q = 0; q < 4; q++) {
                    ri[q] = __ldg(g_erow + j + q);
                    fi[q] = __ldg(g_efi + j + q);
                    ii[q] = (int)fi[q];
                    fr[q] = fi[q] - (float)ii[q];
                }
#pragma unroll
                for (int q = 0; q < 4; q++) {
                    tp[q] = __ldg(reinterpret_cast<const uint4*>(pt + (size_t)ii[q] * 128) + lane);
                    vv[q] = __ldcg(reinterpret_cast<const float4*>(vlin + (size_t)ri[q] * 128) + lane);
                }
#pragma unroll
                for (int q = 0; q < 4; q++) {
                    float2 p0 = __half22float2(*(__half2*)&tp[q].x);
                    float2 p1 = __half22float2(*(__half2*)&tp[q].y);
                    float2 p2 = __half22float2(*(__half2*)&tp[q].z);
                    float2 p3 = __half22float2(*(__half2*)&tp[q].w);
                    a0 = fmaf(vv[q].x, p0.x + fr[q] * (p0.y - p0.x), a0);
                    a1 = fmaf(vv[q].y, p1.x + fr[q] * (p1.y - p1.x), a1);
                    a2 = fmaf(vv[q].z, p2.x + fr[q] * (p2.y - p2.x), a2);
                    a3 = fmaf(vv[q].w, p3.x + fr[q] * (p3.y - p3.x), a3);
                }
            }
            for (; j < end; j++) {
                int   r0 = __ldg(g_erow + j);
                float f0 = __ldg(g_efi + j);
                int   i0 = (int)f0;
                float fr0 = f0 - (float)i0;
                uint4 tq = __ldg(reinterpret_cast<const uint4*>(pt + (size_t)i0 * 128) + lane);
                float4 vv0 = __ldcg(reinterpret_cast<const float4*>(vlin + (size_t)r0 * 128) + lane);
                float2 p0 = __half22float2(*(__half2*)&tq.x);
                float2 p1 = __half22float2(*(__half2*)&tq.y);
                float2 p2 = __half22float2(*(__half2*)&tq.z);
                float2 p3 = __half22float2(*(__half2*)&tq.w);
                a0 = fmaf(vv0.x, p0.x + fr0 * (p0.y - p0.x), a0);
                a1 = fmaf(vv0.y, p1.x + fr0 * (p1.y - p1.x), a1);
                a2 = fmaf(vv0.z, p2.x + fr0 * (p2.y - p2.x), a2);
                a3 = fmaf(vv0.w, p3.x + fr0 * (p3.y - p3.x), a3);
            }
            *(float4*)(agg + (size_t)node * 128 + lane * 4) = make_float4(a0, a1, a2, a3);
        }
        gbar();

        // ======== phase C: v = v + ssp(agg@w1 + b1) @ w2 + b2 ========
        {
            const uint4* b1h = (const uint4*)(w1_hi + (size_t)srow * 128 + shalf);
            const uint4* b1l = (const uint4*)(w1_lo + (size_t)srow * 128 + shalf);
            const uint4* b2h = (const uint4*)(w2_hi + (size_t)srow * 128 + shalf);
            const uint4* b2l = (const uint4*)(w2_lo + (size_t)srow * 128 + shalf);
            __nv_bfloat16* d1h = B1hs + srow * MG_STRIDE + shalf;
            __nv_bfloat16* d1l = B1ls + srow * MG_STRIDE + shalf;
            __nv_bfloat16* d2h = B2hs + srow * MG_STRIDE + shalf;
            __nv_bfloat16* d2l = B2ls + srow * MG_STRIDE + shalf;
#pragma unroll
            for (int c = 0; c < 8; c++) {
                *(uint4*)(d1h + c * 8) = __ldg(b1h + c);
                *(uint4*)(d1l + c * 8) = __ldg(b1l + c);
                *(uint4*)(d2h + c * 8) = __ldg(b2h + c);
                *(uint4*)(d2l + c * 8) = __ldg(b2l + c);
            }
        }
        __syncthreads();
        {
            float4 pa[8];
            int tile0 = blockIdx.x;
            if (tile0 < tiles) {
                int grow = tile0 * 64 + arow_l;
                bool valid = grow < n;
                const float4* ap = (const float4*)(agg + (size_t)(valid ? grow : 0) * 128 + aseg);
#pragma unroll
                for (int c = 0; c < 8; c++) pa[c] = valid ? __ldcg(ap + c) : z4;
            }
            for (int tile = tile0; tile < tiles; tile += gridDim.x) {
                const int bm = tile * 64;
                {
                    __nv_bfloat16* ahp = Ahs + arow_l * MG_STRIDE + aseg;
                    __nv_bfloat16* alp = Als + arow_l * MG_STRIDE + aseg;
#pragma unroll
                    for (int c = 0; c < 8; c++) {
                        float4 vv = pa[c];
                        uint32_t h0 = packbf2(vv.x, vv.y);
                        uint32_t h1 = packbf2(vv.z, vv.w);
                        __nv_bfloat162* h0p = (__nv_bfloat162*)&h0;
                        __nv_bfloat162* h1p = (__nv_bfloat162*)&h1;
                        uint32_t l0 = packbf2(vv.x - __bfloat162float(h0p->x), vv.y - __bfloat162float(h0p->y));
                        uint32_t l1 = packbf2(vv.z - __bfloat162float(h1p->x), vv.w - __bfloat162float(h1p->y));
                        *(uint2*)(ahp + c * 4) = make_uint2(h0, h1);
                        *(uint2*)(alp + c * 4) = make_uint2(l0, l1);
                    }
                }
                __syncthreads();
                {
                    int ntile = tile + gridDim.x;
                    if (ntile < tiles) {
                        int grow = ntile * 64 + arow_l;
                        bool valid = grow < n;
                        const float4* ap = (const float4*)(agg + (size_t)(valid ? grow : 0) * 128 + aseg);
#pragma unroll
                        for (int c = 0; c < 8; c++) pa[c] = valid ? __ldcg(ap + c) : z4;
                    }
                }
                float acc[8][4];
#pragma unroll
                for (int ni = 0; ni < 8; ni++)
#pragma unroll
                    for (int q = 0; q < 4; q++) acc[ni][q] = 0.0f;
#pragma unroll
                for (int k0 = 0; k0 < 8; k0++) {
                    const uint32_t ko = k0 * 32;
                    uint32_t ah[4], al[4];
                    ldsm4(ah, sAh + offA0 + ko);
                    ldsm4(al, sAl + offA0 + ko);
#pragma unroll
                    for (int p = 0; p < 4; p++) {
                        uint32_t bh[4], bl[4];
                        ldsm4(bh, sB1h + offB[p] + ko);
                        ldsm4(bl, sB1l + offB[p] + ko);
                        mma16816(acc[2 * p],     ah, bh[0], bh[1]);
                        mma16816(acc[2 * p],     ah, bl[0], bl[1]);
                        mma16816(acc[2 * p],     al, bh[0], bh[1]);
                        mma16816(acc[2 * p + 1], ah, bh[2], bh[3]);
                        mma16816(acc[2 * p + 1], ah, bl[2], bl[3]);
                        mma16816(acc[2 * p + 1], al, bh[2], bh[3]);
                    }
                }
                __syncthreads();
                {
                    int r0 = wm + gid;
                    int r1 = r0 + 8;
#pragma unroll
                    for (int ni = 0; ni < 8; ni++) {
                        int cb = wn + ni * 8 + tg * 2;
                        float bb0 = __ldg(b1 + cb);
                        float bb1 = __ldg(b1 + cb + 1);
                        float* a4 = acc[ni];
                        float v00 = sspf(a4[0] + bb0), v01 = sspf(a4[1] + bb1);
                        float v10 = sspf(a4[2] + bb0), v11 = sspf(a4[3] + bb1);
                        uint32_t h0 = packbf2(v00, v01);
                        uint32_t h1 = packbf2(v10, v11);
                        __nv_bfloat162* h0p = (__nv_bfloat162*)&h0;
                        __nv_bfloat162* h1p = (__nv_bfloat162*)&h1;
                        uint32_t l0 = packbf2(v00 - __bfloat162float(h0p->x), v01 - __bfloat162float(h0p->y));
                        uint32_t l1 = packbf2(v10 - __bfloat162float(h1p->x), v11 - __bfloat162float(h1p->y));
                        *(uint32_t*)(Ahs + r0 * MG_STRIDE + cb) = h0;
                        *(uint32_t*)(Ahs + r1 * MG_STRIDE + cb) = h1;
                        *(uint32_t*)(Als + r0 * MG_STRIDE + cb) = l0;
                        *(uint32_t*)(Als + r1 * MG_STRIDE + cb) = l1;
                    }
                }
                __syncthreads();
#pragma unroll
                for (int ni = 0; ni < 8; ni++)
#pragma unroll
                    for (int q = 0; q < 4; q++) acc[ni][q] = 0.0f;
#pragma unroll
                for (int k0 = 0; k0 < 8; k0++) {
                    const uint32_t ko = k0 * 32;
                    uint32_t ah[4], al[4];
                    ldsm4(ah, sAh + offA0 + ko);
                    ldsm4(al, sAl + offA0 + ko);
#pragma unroll
                    for (int p = 0; p < 4; p++) {
                        uint32_t bh[4], bl[4];
                        ldsm4(bh, sB2h + offB[p] + ko);
                        ldsm4(bl, sB2l + offB[p] + ko);
                        mma16816(acc[2 * p],     ah, bh[0], bh[1]);
                        mma16816(acc[2 * p],     ah, bl[0], bl[1]);
                        mma16816(acc[2 * p],     al, bh[0], bh[1]);
                        mma16816(acc[2 * p + 1], ah, bh[2], bh[3]);
                        mma16816(acc[2 * p + 1], ah, bl[2], bl[3]);
                        mma16816(acc[2 * p + 1], al, bh[2], bh[3]);
                    }
                }
                {
                    int r0 = bm + wm + gid;
                    int r1 = r0 + 8;
#pragma unroll
                    for (int ni = 0; ni < 8; ni++) {
                        int cb = wn + ni * 8 + tg * 2;
                        float bb0 = __ldg(b2 + cb);
                        float bb1 = __ldg(b2 + cb + 1);
                        float* a4 = acc[ni];
                        float v00 = a4[0] + bb0, v01 = a4[1] + bb1;
                        float v10 = a4[2] + bb0, v11 = a4[3] + bb1;
                        if (r0 < n) {
                            float2 rr;
                            rr.x = __ldcg(v + (size_t)r0 * 128 + cb);
                            rr.y = __ldcg(v + (size_t)r0 * 128 + cb + 1);
                            *(float2*)(v + (size_t)r0 * 128 + cb) = make_float2(v00 + rr.x, v01 + rr.y);
                        }
                        if (r1 < n) {
                            float2 rr;
                            rr.x = __ldcg(v + (size_t)r1 * 128 + cb);
                            rr.y = __ldcg(v + (size_t)r1 * 128 + cb + 1);
                            *(float2*)(v + (size_t)r1 * 128 + cb) = make_float2(v10 + rr.x, v11 + rr.y);
                        }
                    }
                }
                __syncthreads();
            }
        }
        gbar();
    }
}

// ---------------- merged preprocessing --------------------------------------
__global__ void prep_all(const float* __restrict__ lin_w, const float* __restrict__ mlp_w2,
                         const float* __restrict__ v1_w, const float* __restrict__ v2_w,
                         const float* __restrict__ u1_w, const float* __restrict__ fe_w2,
                         const float* __restrict__ u2_w,
                         const float* __restrict__ u1_b, const float* __restrict__ u2_b,
                         const float* __restrict__ mlp_w1, const float* __restrict__ mlp_b1) {
    int idx = blockIdx.x * blockDim.x + threadIdx.x;
    if (idx < 128) {
        g_u1bpad[idx] = (idx < 64) ? u1_b[idx] : 0.0f;
        g_u2bpad[idx] = (idx < 32) ? u2_b[idx] : 0.0f;
        g_bnacc[idx] = 0.0f;
    }
    if (idx < NN) g_nhist[idx] = 0;
    if (idx < 768) g_b1all[idx] = mlp_b1[(idx >> 7) * 128 + (idx & 127)];
    if (idx < NG_PAD * 768) {
        int k = idx / 768;
        int c = idx % 768;
        int l = c >> 7, nn2 = c & 127;
        g_m1all[idx] = (k < NGAUSS) ? mlp_w1[(size_t)l * NGAUSS * 128 + k * 128 + nn2] : 0.0f;
    }
    if (idx < TABROWS * NG_PAD) {
        int m = idx / NG_PAD;
        int g = idx % NG_PAD;
        float val = 0.0f;
        if (g < NGAUSS) {
            float d = (float)m * TAB_STEP;
            float off = (float)g * (6.0f / 49.0f);
            float tt = d - off;
            const float coeff = -0.5f / ((6.0f / 49.0f) * (6.0f / 49.0f));
            val = expf(coeff * tt * tt);
        }
        g_demb[idx] = val;
    }
    if (idx < 27 * 16384) {
        int slot = idx >> 14;
        int r = idx & 16383;
        int n = r >> 7;
        int k = r & 127;
        float a;
        if (slot < 24) {
            int l = slot >> 2, w = slot & 3;
            const float* src = (w == 0) ? lin_w : (w == 1) ? mlp_w2 : (w == 2) ? v1_w : v2_w;
            a = src[(size_t)l * 16384 + k * 128 + n];
        } else if (slot == 24) {
            a = (n < 64) ? u1_w[k * 64 + n] : 0.0f;
        } else if (slot == 25) {
            a = (k < 64) ? fe_w2[k * 128 + n] : 0.0f;
        } else {
            a = (k < 64 && n < 32) ? u2_w[k * 32 + n] : 0.0f;
        }
        __nv_bfloat16 hi = __float2bfloat16_rn(a);
        __nv_bfloat16 lo = __float2bfloat16_rn(a - __bfloat162float(hi));
        g_wthi[idx] = hi;
        g_wtlo[idx] = lo;
    }
}

// ---------------- fp16 pair-table pack ---------------------------------------
__global__ void pack_table() {
    int idx = blockIdx.x * blockDim.x + threadIdx.x;
    if (idx >= LL * TABM * 128) return;
    int c = idx & 127;
    int rest = idx >> 7;
    int i = rest % TABM;
    int l = rest / TABM;
    const float* tab = g_tables + (size_t)l * TABROWS * 128;
    float a = tab[(size_t)i * 128 + c];
    float b = tab[(size_t)(i + 1) * 128 + c];
    g_ptab[idx] = __floats2half2_rn(a, b);
}

// ---------------- edge geometry + per-destination histogram ------------------
__global__ void edge_geom_hist(const int* __restrict__ ei, const float* __restrict__ pos,
                               float* __restrict__ dist, int e_total) {
    int e = blockIdx.x * blockDim.x + threadIdx.x;
    if (e >= e_total) return;
    int r = ei[e];
    int c = ei[e_total + e];
    float dx = pos[r * 3 + 0] - pos[c * 3 + 0];
    float dy = pos[r * 3 + 1] - pos[c * 3 + 1];
    float dz = pos[r * 3 + 2] - pos[c * 3 + 2];
    float d = sqrtf(dx * dx + dy * dy + dz * dz);
    dist[e] = d;
    if (d < SKIP_D) atomicAdd(&g_nhist[c], 1);
}

__global__ void scan_nodes(int n) {
    __shared__ int part[256];
    int t = threadIdx.x;
    int chunk = (n + 255) / 256;
    int lo = t * chunk;
    int hi = min(lo + chunk, n);
    int s = 0;
    for (int i = lo; i < hi; i++) s += g_nhist[i];
    part[t] = s;
    __syncthreads();
    if (t == 0) {
        int acc = 0;
        for (int i = 0; i < 256; i++) { int c = part[i]; part[i] = acc; acc += c; }
    }
    __syncthreads();
    int acc = part[t];
    for (int i = lo; i < hi; i++) {
        int c = g_nhist[i];
        g_nstart[i] = acc;
        g_ncursor[i] = acc;
        acc += c;
    }
    if (hi == n) g_nstart[n] = acc;
}

__global__ void edge_build(const int* __restrict__ ei, const float* __restrict__ dist,
                           int e_total) {
    int e = blockIdx.x * blockDim.x + threadIdx.x;
    if (e >= e_total) return;
    float d = dist[e];
    if (d >= SKIP_D) return;
    int c = ei[e_total + e];
    int p = atomicAdd(&g_ncursor[c], 1);
    g_erow[p] = ei[e];
    g_efi[p] = d * TAB_INVSTEP;
}

// ---------------- SIMT fp32 SGEMM with f32x2 (small/odd shapes) -------------
__global__ void __launch_bounds__(256, 2) sgemm(
    const float* __restrict__ A, const float* __restrict__ B,
    const float* __restrict__ bias, const float* __restrict__ res,
    float* __restrict__ C, int M, int N, int K, int Kb, int act) {
    __shared__ float As[2][8][128];
    __shared__ float Bs[2][8][128];
    const int tid = threadIdx.x;
    const int bm = blockIdx.y * 128;
    const int bn = blockIdx.x * 128;
    const int tx = tid & 15;
    const int ty = tid >> 4;
    const int ar = tid >> 1;
    const int ak = (tid & 1) * 4;
    const int bk = tid >> 5;
    const int bn4 = (tid & 31) * 4;
    const int arow = bm + ar;
    const int bcol = bn + bn4;
    const int KT = (K + 7) >> 3;

    unsigned long long acc[8][4];
#pragma unroll
    for (int i = 0; i < 8; i++)
#pragma unroll
        for (int j = 0; j < 4; j++) acc[i][j] = 0ull;

    float4 pa = make_float4(0, 0, 0, 0);
    float4 pb = make_float4(0, 0, 0, 0);
    if (arow < M && ak < K) pa = *(const float4*)(A + (size_t)arow * K + ak);
    if (bk < Kb && bcol < N) pb = *(const float4*)(B + (size_t)bk * N + bcol);
    As[0][ak + 0][ar] = pa.x; As[0][ak + 1][ar] = pa.y;
    As[0][ak + 2][ar] = pa.z; As[0][ak + 3][ar] = pa.w;
    *(float4*)&Bs[0][bk][bn4] = pb;
    __syncthreads();

    for (int kt = 0; kt < KT; kt++) {
        const int s = kt & 1;
        if (kt + 1 < KT) {
            int k0 = (kt + 1) * 8;
            pa = make_float4(0, 0, 0, 0);
            pb = make_float4(0, 0, 0, 0);
            if (arow < M && (k0 + ak) < K) pa = *(const float4*)(A + (size_t)arow * K + k0 + ak);
            if ((k0 + bk) < Kb && bcol < N) pb = *(const float4*)(B + (size_t)(k0 + bk) * N + bcol);
        }
#pragma unroll
        for (int k = 0; k < 8; k++) {
            float a[8];
            *(float4*)&a[0] = *(const float4*)&As[s][k][ty * 8];
            *(float4*)&a[4] = *(const float4*)&As[s][k][ty * 8 + 4];
            ulonglong2 bl = *(const ulonglong2*)&Bs[s][k][tx * 8];
            ulonglong2 bh = *(const ulonglong2*)&Bs[s][k][tx * 8 + 4];
#pragma unroll
            for (int i = 0; i < 8; i++) {
                unsigned long long ai = bcast2(a[i]);
                ffma2(acc[i][0], ai, bl.x);
                ffma2(acc[i][1], ai, bl.y);
                ffma2(acc[i][2], ai, bh.x);
                ffma2(acc[i][3], ai, bh.y);
            }
        }
        if (kt + 1 < KT) {
            const int so = (kt + 1) & 1;
            As[so][ak + 0][ar] = pa.x; As[so][ak + 1][ar] = pa.y;
            As[so][ak + 2][ar] = pa.z; As[so][ak + 3][ar] = pa.w;
            *(float4*)&Bs[so][bk][bn4] = pb;
            __syncthreads();
        }
    }

    const int cbase = bn + tx * 8;
    float bv[8];
#pragma unroll
    for (int j = 0; j < 8; j++) bv[j] = (bias && (cbase + j) < N) ? bias[cbase + j] : 0.0f;

#pragma unroll
    for (int i = 0; i < 8; i++) {
        int row = bm + ty * 8 + i;
        if (row >= M) continue;
        float c[8];
        unpack2(acc[i][0], c[0], c[1]);
        unpack2(acc[i][1], c[2], c[3]);
        unpack2(acc[i][2], c[4], c[5]);
        unpack2(acc[i][3], c[6], c[7]);
#pragma unroll
        for (int j = 0; j < 8; j++) {
            float v = c[j] + bv[j];
            if (act == 1) v = fmaxf(v, 0.0f);
            else if (act == 2) v = sspf(v);
            c[j] = v;
        }
        if (res) {
#pragma unroll
            for (int j = 0; j < 8; j++)
                if ((cbase + j) < N) c[j] += res[(size_t)row * N + cbase + j];
        }
        if (cbase < N)
            *(float4*)(C + (size_t)row * N + cbase) = make_float4(c[0], c[1], c[2], c[3]);
        if (cbase + 4 < N)
            *(float4*)(C + (size_t)row * N + cbase + 4) = make_float4(c[4], c[5], c[6], c[7]);
    }
}

// ---------------- batchnorm ---------------------------------------------------
__global__ void bn_reduce(const float* __restrict__ h, int n) {
    __shared__ float ss[4][64];
    __shared__ float sq[4][64];
    int c = threadIdx.x & 63;
    int g = threadIdx.x >> 6;
    float s = 0.0f, q = 0.0f;
    for (int row = blockIdx.x * 4 + g; row < n; row += gridDim.x * 4) {
        float v = h[row * 64 + c];
        s += v;
        q += v * v;
    }
    ss[g][c] = s;
    sq[g][c] = q;
    __syncthreads();
    if (g == 0) {
        atomicAdd(&g_bnacc[c], ss[0][c] + ss[1][c] + ss[2][c] + ss[3][c]);
        atomicAdd(&g_bnacc[64 + c], sq[0][c] + sq[1][c] + sq[2][c] + sq[3][c]);
    }
}

__global__ void bn_apply(const float* __restrict__ h, float* __restrict__ hn,
                         const float* __restrict__ gamma, const float* __restrict__ beta,
                         int n) {
    int idx = blockIdx.x * blockDim.x + threadIdx.x;
    if (idx >= n * 128) return;
    int c = idx & 127;
    float y = 0.0f;
    if (c < 64) {
        float invN = 1.0f / (float)n;
        float mu = g_bnacc[c] * invN;
        float var = g_bnacc[64 + c] * invN - mu * mu;
        y = (h[(idx >> 7) * 64 + c] - mu) / sqrtf(var + 1e-5f) * gamma[c] + beta[c];
        y = fmaxf(y, 0.0f);
    }
    hn[idx] = y;
}

// ---------------- final per-graph scatter (batch sorted; s stride 128) --------
__global__ void node_out(const float* __restrict__ s, const int* __restrict__ batch,
                         float* __restrict__ out, int n) {
    int w = (blockIdx.x * blockDim.x + threadIdx.x) >> 5;
    int lane = threadIdx.x & 31;
    int start = w * 128;
    if (start >= n) return;
    int end = min(start + 128, n);
    int cur = __ldg(batch + start);
    float acc = 0.0f;
    for (int node = start; node < end; node++) {
        int b = __ldg(batch + node);
        if (b != cur) {
            atomicAdd(&out[cur * 32 + lane], acc);
            acc = 0.0f;
            cur = b;
        }
        acc += s[(size_t)node * 128 + lane];
    }
    atomicAdd(&out[cur * 32 + lane], acc);
}

// ---------------- host ---------------------------------------------------------
static float* sym(const void* s) {
    void* p = nullptr;
    cudaGetSymbolAddress(&p, s);
    return (float*)p;
}

extern "C" void kernel_launch(void* const* d_in, const int* in_sizes, int n_in,
                              void* d_out, int out_size) {
    const float* x       = (const float*)d_in[0];
    const float* pos     = (const float*)d_in[1];
    const int*   batch   = (const int*)d_in[2];
    const int*   ei      = (const int*)d_in[3];
    const float* fe_w1   = (const float*)d_in[4];
    const float* fe_b1   = (const float*)d_in[5];
    const float* bng     = (const float*)d_in[6];
    const float* bnb     = (const float*)d_in[7];
    const float* fe_w2   = (const float*)d_in[8];
    const float* fe_b2   = (const float*)d_in[9];
    const float* lin_w   = (const float*)d_in[10];
    const float* mlp_w1  = (const float*)d_in[11];
    const float* mlp_b1  = (const float*)d_in[12];
    const float* mlp_w2  = (const float*)d_in[13];
    const float* mlp_b2  = (const float*)d_in[14];
    const float* v1_w    = (const float*)d_in[15];
    const float* v1_b    = (const float*)d_in[16];
    const float* v2_w    = (const float*)d_in[17];
    const float* v2_b    = (const float*)d_in[18];
    const float* u1_w    = (const float*)d_in[19];
    const float* u1_b    = (const float*)d_in[20];
    const float* u2_w    = (const float*)d_in[21];
    const float* u2_b    = (const float*)d_in[22];
    float* out = (float*)d_out;

    int n = in_sizes[0] / 28;
    int e = in_sizes[3] / 2;

    float* p_h      = sym(g_h);
    float* p_hn     = sym(g_hn);
    float* p_v      = sym(g_v);
    float* p_vlin   = sym(g_vlin);
    float* p_agg    = sym(g_agg);
    float* p_t1     = sym(g_t1);
    float* p_dist   = sym(g_dist);
    float* p_demb   = sym(g_demb);
    float* p_tabh   = sym(g_tabh);
    float* p_tables = sym(g_tables);
    __half2* p_ptab = (__half2*)sym(g_ptab);
    float* p_u1b    = sym(g_u1bpad);
    float* p_u2b    = sym(g_u2bpad);
    float* p_m1all  = sym(g_m1all);
    float* p_b1all  = sym(g_b1all);
    __nv_bfloat16* p_whi = (__nv_bfloat16*)sym(g_wthi);
    __nv_bfloat16* p_wlo = (__nv_bfloat16*)sym(g_wtlo);

    cudaFuncSetAttribute(mgemm, cudaFuncAttributeMaxDynamicSharedMemorySize, MG_SMEM);
    cudaFuncSetAttribute(fgemm, cudaFuncAttributeMaxDynamicSharedMemorySize, FG_SMEM);
    cudaFuncSetAttribute(mega,  cudaFuncAttributeMaxDynamicSharedMemorySize, FG_SMEM);

    int sms = 148;
    cudaDeviceGetAttribute(&sms, cudaDevAttrMultiProcessorCount, 0);

    dim3 gemm_t(256);
    auto gemm_grid = [](int M, int N) {
        return dim3((unsigned)((N + 127) / 128), (unsigned)((M + 127) / 128));
    };
    int mtiles = (n + 63) / 64;
    int ttiles = (TABROWS + 63) / 64;
    int mgrid = mtiles < 2 * sms ? mtiles : 2 * sms;
    int fgrid = mtiles < sms ? mtiles : sms;

    // ---- phase 1: merged prep + batched table build + fp16 pair pack ----
    prep_all<<<(27 * 16384 + 255) / 256, 256>>>(lin_w, mlp_w2, v1_w, v2_w, u1_w,
                                                fe_w2, u2_w, u1_b, u2_b, mlp_w1, mlp_b1);
    sgemm<<<gemm_grid(TABROWS, 768), gemm_t>>>(p_demb, p_m1all, p_b1all, nullptr,
                                               p_tabh, TABROWS, 768, NG_PAD, NG_PAD, 2);
    mgemm<<<ttiles * LL, 256, MG_SMEM>>>(p_tabh, p_whi + (size_t)1 * 16384,
                                         p_wlo + (size_t)1 * 16384, mlp_b2, nullptr,
                                         p_tables, TABROWS, 3, ttiles, LL, 768);
    pack_table<<<(LL * TABM * 128 + 255) / 256, 256>>>();

    // ---- phase 2: edge geometry + CSR-by-destination sort ----
    edge_geom_hist<<<(e + 255) / 256, 256>>>(ei, pos, p_dist, e);
    scan_nodes<<<1, 256>>>(n);
    edge_build<<<(e + 255) / 256, 256>>>(ei, p_dist, e);

    // ---- phase 3: feature embedding ----
    sgemm<<<gemm_grid(n, 64), gemm_t>>>(x, fe_w1, fe_b1, nullptr, p_h, n, 64, 28, 28, 0);
    bn_reduce<<<512, 256>>>(p_h, n);
    bn_apply<<<(n * 128 + 255) / 256, 256>>>(p_h, p_hn, bng, bnb, n);
    mgemm<<<mgrid, 256, MG_SMEM>>>(p_hn, p_whi + (size_t)25 * 16384,
                                   p_wlo + (size_t)25 * 16384, fe_b2, nullptr,
                                   p_v, n, 1, mtiles, 1, 128);

    // ---- phase 4: all 6 interaction layers in ONE persistent kernel ----
    mega<<<sms, 256, FG_SMEM>>>(p_whi, p_wlo, v1_b, v2_b,
                                p_v, p_vlin, p_agg, p_ptab, n, mtiles);

    // ---- phase 5: readout ----
    fgemm<<<fgrid, 256, FG_SMEM>>>(p_v,
                                   p_whi + (size_t)24 * 16384, p_wlo + (size_t)24 * 16384,
                                   p_whi + (size_t)26 * 16384, p_wlo + (size_t)26 * 16384,
                                   p_u1b, p_u2b, nullptr, p_t1, n, mtiles);
    cudaMemsetAsync(out, 0, (size_t)out_size * sizeof(float));
    node_out<<<((n + 127) / 128 * 32 + 255) / 256, 256>>>(p_t1, batch, out, n);
}

// round 13
// speedup vs baseline: 1.1930x; 1.1930x over previous
#include <cuda_runtime.h>
#include <cuda_bf16.h>
#include <cuda_fp16.h>
#include <math.h>
#include <stdint.h>

// Problem constants
#define NN 50000
#define EE 800000
#define GG 512
#define LL 6
#define NGAUSS 50
#define NG_PAD 56
#define TABM 2048                  // table intervals over [0, 7]
#define TABROWS (TABM + 1)
#define TAB_MAX 7.0f
#define TAB_INVSTEP ((float)TABM / TAB_MAX)
#define TAB_STEP (TAB_MAX / (float)TABM)
#define SKIP_D 6.97f
#define LN2F 0.69314718055994530942f
#define PIF 3.14159265358979323846f

// ---------------- scratch (device globals; no allocation allowed) -------------
__device__ __align__(256) float g_h[NN * 64];
__device__ __align__(256) float g_hn[NN * 128];      // K=128 padded
__device__ __align__(256) float g_v[NN * 128];
__device__ __align__(256) float g_vlin[NN * 128];
__device__ __align__(256) float g_agg[NN * 128];
__device__ __align__(256) float g_t1[NN * 128];
__device__ __align__(256) float g_dist[EE];
__device__ __align__(256) float g_demb[TABROWS * NG_PAD];
__device__ __align__(256) float g_tabh[TABROWS * 768];   // all 6 layers, N=768
__device__ __align__(256) float g_tables[LL * TABROWS * 128];
__device__ __align__(256) __half2 g_ptab[LL * TABM * 128];  // fp16 (T[i],T[i+1]) pairs
__device__ __align__(256) float g_bnacc[128];
__device__ __align__(256) float g_u1bpad[128];
__device__ __align__(256) float g_u2bpad[128];
__device__ __align__(256) float g_m1all[NG_PAD * 768];
__device__ __align__(256) float g_b1all[768];
// bf16 hi/lo split, pre-transposed weights [slot][n][k]
// slots 0..23: l*4 + {lin,mlp2,v1,v2}; 24: u1 (N-pad); 25: fe2 (K-pad); 26: u2 (N,K-pad)
__device__ __align__(256) __nv_bfloat16 g_wthi[27 * 128 * 128];
__device__ __align__(256) __nv_bfloat16 g_wtlo[27 * 128 * 128];
// CSR-by-destination edge sort
__device__ __align__(256) int   g_nhist[NN];
__device__ __align__(256) int   g_nstart[NN + 1];
__device__ __align__(256) int   g_ncursor[NN];
__device__ __align__(256) int   g_erow[EE];
__device__ __align__(256) float g_efi[EE];

// ---------------- helpers ---------------------------------------------------
__device__ __forceinline__ float sspf(float x) {
    return fmaxf(x, 0.0f) + log1pf(expf(-fabsf(x))) - LN2F;
}
__device__ __forceinline__ unsigned long long bcast2(float x) {
    unsigned long long r;
    asm("mov.b64 %0, {%1, %1};" : "=l"(r) : "f"(x));
    return r;
}
__device__ __forceinline__ void ffma2(unsigned long long& d,
                                      unsigned long long a, unsigned long long b) {
    asm("fma.rn.f32x2 %0, %1, %2, %0;" : "+l"(d) : "l"(a), "l"(b));
}
__device__ __forceinline__ void unpack2(unsigned long long v, float& lo, float& hi) {
    asm("mov.b64 {%0, %1}, %2;" : "=f"(lo), "=f"(hi) : "l"(v));
}
__device__ __forceinline__ uint32_t smem_u32(const void* p) {
    uint32_t a;
    asm("{ .reg .u64 t; cvta.to.shared.u64 t, %1; cvt.u32.u64 %0, t; }" : "=r"(a) : "l"(p));
    return a;
}
__device__ __forceinline__ void mma16816(float* c, const uint32_t* a,
                                         uint32_t b0, uint32_t b1) {
    asm volatile(
        "mma.sync.aligned.m16n8k16.row.col.f32.bf16.bf16.f32 "
        "{%0,%1,%2,%3}, {%4,%5,%6,%7}, {%8,%9}, {%0,%1,%2,%3};"
        : "+f"(c[0]), "+f"(c[1]), "+f"(c[2]), "+f"(c[3])
        : "r"(a[0]), "r"(a[1]), "r"(a[2]), "r"(a[3]), "r"(b0), "r"(b1));
}
__device__ __forceinline__ void ldsm4(uint32_t* r, uint32_t addr) {
    asm volatile("ldmatrix.sync.aligned.m8n8.x4.shared.b16 {%0,%1,%2,%3}, [%4];"
        : "=r"(r[0]), "=r"(r[1]), "=r"(r[2]), "=r"(r[3]) : "r"(addr));
}
__device__ __forceinline__ uint32_t packbf2(float x, float y) {
    __nv_bfloat162 h = __float22bfloat162_rn(make_float2(x, y));
    return *(uint32_t*)&h;
}

#define MG_STRIDE 136   // bf16 per smem row (272B) — conflict-free ldmatrix
#define MG_A1 (64 * MG_STRIDE * 2)
#define MG_B1 (128 * MG_STRIDE * 2)
#define MG_SMEM (2 * MG_A1 + 2 * MG_B1)
// fgemm v2: A (128 rows, hi/lo) + W1 (hi/lo) + W2 (hi/lo), all 128x128
#define FG_A1 MG_B1
#define FG_SMEM (6 * FG_A1)

// ================= bf16x3 HMMA GEMM v3 (pipelined A prefetch) ================
__global__ void __launch_bounds__(256, 2) mgemm(
    const float* __restrict__ A, const __nv_bfloat16* __restrict__ Bhi,
    const __nv_bfloat16* __restrict__ Blo, const float* __restrict__ bias,
    const float* __restrict__ res, float* __restrict__ C, int M, int act,
    int tiles_per_mat, int nmats, int lda) {
    extern __shared__ char smem[];
    __nv_bfloat16* Ahs = (__nv_bfloat16*)(smem);
    __nv_bfloat16* Als = (__nv_bfloat16*)(smem + MG_A1);
    __nv_bfloat16* Bhs = (__nv_bfloat16*)(smem + 2 * MG_A1);
    __nv_bfloat16* Bls = (__nv_bfloat16*)(smem + 2 * MG_A1 + MG_B1);
    const uint32_t sb = smem_u32(smem);
    const uint32_t sAh = sb, sAl = sb + MG_A1;
    const uint32_t sBh = sb + 2 * MG_A1, sBl = sb + 2 * MG_A1 + MG_B1;

    const int t = threadIdx.x;
    const int lane = t & 31;
    const int w = t >> 5;
    const int wm = (w & 3) * 16;
    const int wn = (w >> 2) * 64;
    const int gid = lane >> 2;
    const int tg = lane & 3;

    const int arow_l = t >> 2;
    const int aseg = (t & 3) * 32;

    const int lrow = ((t >> 3) & 1) * 8 + (t & 7);
    const int lkb  = ((t >> 4) & 1) * 16;
    const uint32_t offA0 = (uint32_t)(wm + lrow) * 272 + lkb;
    const int brow = ((t >> 4) & 1) * 8 + (t & 7);
    const int bkb  = ((t >> 3) & 1) * 16;
    uint32_t offB[4];
#pragma unroll
    for (int p = 0; p < 4; p++) offB[p] = (uint32_t)(wn + p * 16 + brow) * 272 + bkb;

    const int total_tiles = tiles_per_mat * nmats;
    int cur_mat = -1;
    const float4 z4 = make_float4(0, 0, 0, 0);

    float4 pa[8];
    if (blockIdx.x < total_tiles) {
        int tl = blockIdx.x;
        int mat = (nmats == 1) ? 0 : (tl / tiles_per_mat);
        int lt  = (nmats == 1) ? tl : (tl % tiles_per_mat);
        int grow = lt * 64 + arow_l;
        bool valid = grow < M;
        const float4* ap = (const float4*)(A + (size_t)(valid ? grow : 0) * lda + mat * 128 + aseg);
#pragma unroll
        for (int c = 0; c < 8; c++) pa[c] = valid ? ap[c] : z4;
    }

    for (int tile = blockIdx.x; tile < total_tiles; tile += gridDim.x) {
        const int mat = (nmats == 1) ? 0 : (tile / tiles_per_mat);
        const int lt  = (nmats == 1) ? tile : (tile % tiles_per_mat);
        const int bm = lt * 64;

        if (mat != cur_mat) {
            cur_mat = mat;
            const __nv_bfloat16* bh = Bhi + (size_t)mat * 4 * 16384;
            const __nv_bfloat16* bl = Blo + (size_t)mat * 4 * 16384;
            int row = t >> 1, half = (t & 1) * 64;
            const uint4* bhp = (const uint4*)(bh + (size_t)row * 128 + half);
            const uint4* blp = (const uint4*)(bl + (size_t)row * 128 + half);
            __nv_bfloat16* dbh = Bhs + row * MG_STRIDE + half;
            __nv_bfloat16* dbl = Bls + row * MG_STRIDE + half;
#pragma unroll
            for (int c = 0; c < 8; c++) {
                *(uint4*)(dbh + c * 8) = bhp[c];
                *(uint4*)(dbl + c * 8) = blp[c];
            }
        }

        {
            __nv_bfloat16* ahp = Ahs + arow_l * MG_STRIDE + aseg;
            __nv_bfloat16* alp = Als + arow_l * MG_STRIDE + aseg;
#pragma unroll
            for (int c = 0; c < 8; c++) {
                float4 v = pa[c];
                uint32_t h0 = packbf2(v.x, v.y);
                uint32_t h1 = packbf2(v.z, v.w);
                __nv_bfloat162* h0p = (__nv_bfloat162*)&h0;
                __nv_bfloat162* h1p = (__nv_bfloat162*)&h1;
                uint32_t l0 = packbf2(v.x - __bfloat162float(h0p->x), v.y - __bfloat162float(h0p->y));
                uint32_t l1 = packbf2(v.z - __bfloat162float(h1p->x), v.w - __bfloat162float(h1p->y));
                *(uint2*)(ahp + c * 4) = make_uint2(h0, h1);
                *(uint2*)(alp + c * 4) = make_uint2(l0, l1);
            }
        }
        __syncthreads();

        {
            int ntile = tile + gridDim.x;
            if (ntile < total_tiles) {
                int nmat = (nmats == 1) ? 0 : (ntile / tiles_per_mat);
                int nlt  = (nmats == 1) ? ntile : (ntile % tiles_per_mat);
                int grow = nlt * 64 + arow_l;
                bool valid = grow < M;
                const float4* ap = (const float4*)(A + (size_t)(valid ? grow : 0) * lda + nmat * 128 + aseg);
#pragma unroll
                for (int c = 0; c < 8; c++) pa[c] = valid ? ap[c] : z4;
            }
        }

        float acc[8][4];
#pragma unroll
        for (int ni = 0; ni < 8; ni++)
#pragma unroll
            for (int q = 0; q < 4; q++) acc[ni][q] = 0.0f;

#pragma unroll
        for (int k0 = 0; k0 < 8; k0++) {
            const uint32_t ko = k0 * 32;
            uint32_t ah[4], al[4];
            ldsm4(ah, sAh + offA0 + ko);
            ldsm4(al, sAl + offA0 + ko);
#pragma unroll
            for (int p = 0; p < 4; p++) {
                uint32_t bh[4], bl[4];
                ldsm4(bh, sBh + offB[p] + ko);
                ldsm4(bl, sBl + offB[p] + ko);
                mma16816(acc[2 * p],     ah, bh[0], bh[1]);
                mma16816(acc[2 * p],     ah, bl[0], bl[1]);
                mma16816(acc[2 * p],     al, bh[0], bh[1]);
                mma16816(acc[2 * p + 1], ah, bh[2], bh[3]);
                mma16816(acc[2 * p + 1], ah, bl[2], bl[3]);
                mma16816(acc[2 * p + 1], al, bh[2], bh[3]);
            }
        }

        const float* mbias = bias ? (bias + (size_t)mat * 128) : nullptr;
        float* mC = C;
        if (nmats > 1) mC = C + (size_t)mat * (size_t)TABROWS * 128;
        {
            int r0 = bm + wm + gid;
            int r1 = r0 + 8;
            float sc0 = 1.0f, sc1 = 1.0f;
            if (act == 3) {
                sc0 = 0.5f * (cosf((float)r0 * TAB_STEP * (PIF / 6.0f)) + 1.0f);
                sc1 = 0.5f * (cosf((float)r1 * TAB_STEP * (PIF / 6.0f)) + 1.0f);
            }
#pragma unroll
            for (int ni = 0; ni < 8; ni++) {
                int cb = wn + ni * 8 + tg * 2;
                float b0 = mbias ? __ldg(mbias + cb) : 0.0f;
                float b1 = mbias ? __ldg(mbias + cb + 1) : 0.0f;
                float* a4 = acc[ni];
                float v00 = a4[0] + b0, v01 = a4[1] + b1;
                float v10 = a4[2] + b0, v11 = a4[3] + b1;
                if (act == 1) {
                    v00 = fmaxf(v00, 0.0f); v01 = fmaxf(v01, 0.0f);
                    v10 = fmaxf(v10, 0.0f); v11 = fmaxf(v11, 0.0f);
                } else if (act == 2) {
                    v00 = sspf(v00); v01 = sspf(v01); v10 = sspf(v10); v11 = sspf(v11);
                } else if (act == 3) {
                    v00 *= sc0; v01 *= sc0; v10 *= sc1; v11 *= sc1;
                }
                if (r0 < M) {
                    if (res) {
                        float2 rr = *(const float2*)(res + (size_t)r0 * 128 + cb);
                        v00 += rr.x; v01 += rr.y;
                    }
                    *(float2*)(mC + (size_t)r0 * 128 + cb) = make_float2(v00, v01);
                }
                if (r1 < M) {
                    if (res) {
                        float2 rr = *(const float2*)(res + (size_t)r1 * 128 + cb);
                        v10 += rr.x; v11 += rr.y;
                    }
                    *(float2*)(mC + (size_t)r1 * 128 + cb) = make_float2(v10, v11);
                }
            }
        }
        __syncthreads();
    }
}

// ===== fused double-GEMM v2 (512 threads, M=128 tiles, 16 warps/SM) ==========
// C = (ssp(A@W1+b1))@W2 + b2 (+res); t1 tile stays in smem (A buffers reused).
__global__ void __launch_bounds__(512, 1) fgemm(
    const float* __restrict__ A,
    const __nv_bfloat16* __restrict__ B1hi, const __nv_bfloat16* __restrict__ B1lo,
    const __nv_bfloat16* __restrict__ B2hi, const __nv_bfloat16* __restrict__ B2lo,
    const float* __restrict__ bias1, const float* __restrict__ bias2,
    const float* __restrict__ res, float* __restrict__ C, int M, int tiles) {
    extern __shared__ char smem[];
    __nv_bfloat16* Ahs  = (__nv_bfloat16*)(smem);
    __nv_bfloat16* Als  = (__nv_bfloat16*)(smem + FG_A1);
    const uint32_t sb = smem_u32(smem);
    const uint32_t sAh = sb, sAl = sb + FG_A1;
    const uint32_t sB1h = sb + 2 * FG_A1, sB1l = sb + 3 * FG_A1;
    const uint32_t sB2h = sb + 4 * FG_A1, sB2l = sb + 5 * FG_A1;
    __nv_bfloat16* B1hs = (__nv_bfloat16*)(smem + 2 * FG_A1);
    __nv_bfloat16* B1ls = (__nv_bfloat16*)(smem + 3 * FG_A1);
    __nv_bfloat16* B2hs = (__nv_bfloat16*)(smem + 4 * FG_A1);
    __nv_bfloat16* B2ls = (__nv_bfloat16*)(smem + 5 * FG_A1);

    const int t = threadIdx.x;
    const int lane = t & 31;
    const int w = t >> 5;           // 0..15
    const int wm = (w >> 1) * 16;   // 8 M-slots of 16 rows
    const int wn = (w & 1) * 64;    // 2 N-halves
    const int gid = lane >> 2;
    const int tg = lane & 3;
    const int arow_l = t >> 2;      // 0..127
    const int aseg = (t & 3) * 32;
    const int lrow = ((lane >> 3) & 1) * 8 + (lane & 7);
    const int lkb  = ((lane >> 4) & 1) * 16;
    const uint32_t offA0 = (uint32_t)(wm + lrow) * 272 + lkb;
    const int brow = ((lane >> 4) & 1) * 8 + (lane & 7);
    const int bkb  = ((lane >> 3) & 1) * 16;
    uint32_t offB[4];
#pragma unroll
    for (int p = 0; p < 4; p++) offB[p] = (uint32_t)(wn + p * 16 + brow) * 272 + bkb;

    // stage both weight matrices once (512 threads: each does 32 cols/matrix)
    {
        const int srow = t >> 2, shalf = (t & 3) * 32;
        const uint4* b1h = (const uint4*)(B1hi + (size_t)srow * 128 + shalf);
        const uint4* b1l = (const uint4*)(B1lo + (size_t)srow * 128 + shalf);
        const uint4* b2h = (const uint4*)(B2hi + (size_t)srow * 128 + shalf);
        const uint4* b2l = (const uint4*)(B2lo + (size_t)srow * 128 + shalf);
        __nv_bfloat16* d1h = B1hs + srow * MG_STRIDE + shalf;
        __nv_bfloat16* d1l = B1ls + srow * MG_STRIDE + shalf;
        __nv_bfloat16* d2h = B2hs + srow * MG_STRIDE + shalf;
        __nv_bfloat16* d2l = B2ls + srow * MG_STRIDE + shalf;
#pragma unroll
        for (int c = 0; c < 4; c++) {
            *(uint4*)(d1h + c * 8) = b1h[c];
            *(uint4*)(d1l + c * 8) = b1l[c];
            *(uint4*)(d2h + c * 8) = b2h[c];
            *(uint4*)(d2l + c * 8) = b2l[c];
        }
    }

    const float4 z4 = make_float4(0, 0, 0, 0);
    float4 pa[8];
    if (blockIdx.x < tiles) {
        int grow = blockIdx.x * 128 + arow_l;
        bool valid = grow < M;
        const float4* ap = (const float4*)(A + (size_t)(valid ? grow : 0) * 128 + aseg);
#pragma unroll
        for (int c = 0; c < 8; c++) pa[c] = valid ? ap[c] : z4;
    }

    for (int tile = blockIdx.x; tile < tiles; tile += gridDim.x) {
        const int bm = tile * 128;

        // stage A (converted from prefetch registers)
        {
            __nv_bfloat16* ahp = Ahs + arow_l * MG_STRIDE + aseg;
            __nv_bfloat16* alp = Als + arow_l * MG_STRIDE + aseg;
#pragma unroll
            for (int c = 0; c < 8; c++) {
                float4 v = pa[c];
                uint32_t h0 = packbf2(v.x, v.y);
                uint32_t h1 = packbf2(v.z, v.w);
                __nv_bfloat162* h0p = (__nv_bfloat162*)&h0;
                __nv_bfloat162* h1p = (__nv_bfloat162*)&h1;
                uint32_t l0 = packbf2(v.x - __bfloat162float(h0p->x), v.y - __bfloat162float(h0p->y));
                uint32_t l1 = packbf2(v.z - __bfloat162float(h1p->x), v.w - __bfloat162float(h1p->y));
                *(uint2*)(ahp + c * 4) = make_uint2(h0, h1);
                *(uint2*)(alp + c * 4) = make_uint2(l0, l1);
            }
        }
        __syncthreads();

        // prefetch next tile's A
        {
            int ntile = tile + gridDim.x;
            if (ntile < tiles) {
                int grow = ntile * 128 + arow_l;
                bool valid = grow < M;
                const float4* ap = (const float4*)(A + (size_t)(valid ? grow : 0) * 128 + aseg);
#pragma unroll
                for (int c = 0; c < 8; c++) pa[c] = valid ? ap[c] : z4;
            }
        }

        float acc[8][4];
#pragma unroll
        for (int ni = 0; ni < 8; ni++)
#pragma unroll
            for (int q = 0; q < 4; q++) acc[ni][q] = 0.0f;

        // ---- MMA1: A @ W1 ----
#pragma unroll
        for (int k0 = 0; k0 < 8; k0++) {
            const uint32_t ko = k0 * 32;
            uint32_t ah[4], al[4];
            ldsm4(ah, sAh + offA0 + ko);
            ldsm4(al, sAl + offA0 + ko);
#pragma unroll
            for (int p = 0; p < 4; p++) {
                uint32_t bh[4], bl[4];
                ldsm4(bh, sB1h + offB[p] + ko);
                ldsm4(bl, sB1l + offB[p] + ko);
                mma16816(acc[2 * p],     ah, bh[0], bh[1]);
                mma16816(acc[2 * p],     ah, bl[0], bl[1]);
                mma16816(acc[2 * p],     al, bh[0], bh[1]);
                mma16816(acc[2 * p + 1], ah, bh[2], bh[3]);
                mma16816(acc[2 * p + 1], ah, bl[2], bl[3]);
                mma16816(acc[2 * p + 1], al, bh[2], bh[3]);
            }
        }
        __syncthreads();   // all MMA1 A-reads done before t1 overwrites A buffers

        // ---- epilogue1: t1 = ssp(acc + b1) -> bf16 hi/lo back into A buffers --
        {
            int r0 = wm + gid;
            int r1 = r0 + 8;
#pragma unroll
            for (int ni = 0; ni < 8; ni++) {
                int cb = wn + ni * 8 + tg * 2;
                float b0 = __ldg(bias1 + cb);
                float b1 = __ldg(bias1 + cb + 1);
                float* a4 = acc[ni];
                float v00 = sspf(a4[0] + b0), v01 = sspf(a4[1] + b1);
                float v10 = sspf(a4[2] + b0), v11 = sspf(a4[3] + b1);
                uint32_t h0 = packbf2(v00, v01);
                uint32_t h1 = packbf2(v10, v11);
                __nv_bfloat162* h0p = (__nv_bfloat162*)&h0;
                __nv_bfloat162* h1p = (__nv_bfloat162*)&h1;
                uint32_t l0 = packbf2(v00 - __bfloat162float(h0p->x), v01 - __bfloat162float(h0p->y));
                uint32_t l1 = packbf2(v10 - __bfloat162float(h1p->x), v11 - __bfloat162float(h1p->y));
                *(uint32_t*)(Ahs + r0 * MG_STRIDE + cb) = h0;
                *(uint32_t*)(Ahs + r1 * MG_STRIDE + cb) = h1;
                *(uint32_t*)(Als + r0 * MG_STRIDE + cb) = l0;
                *(uint32_t*)(Als + r1 * MG_STRIDE + cb) = l1;
            }
        }
        __syncthreads();   // t1 fully written (cross-warp columns)

        // ---- MMA2: t1 @ W2 ----
#pragma unroll
        for (int ni = 0; ni < 8; ni++)
#pragma unroll
            for (int q = 0; q < 4; q++) acc[ni][q] = 0.0f;
#pragma unroll
        for (int k0 = 0; k0 < 8; k0++) {
            const uint32_t ko = k0 * 32;
            uint32_t ah[4], al[4];
            ldsm4(ah, sAh + offA0 + ko);
            ldsm4(al, sAl + offA0 + ko);
#pragma unroll
            for (int p = 0; p < 4; p++) {
                uint32_t bh[4], bl[4];
                ldsm4(bh, sB2h + offB[p] + ko);
                ldsm4(bl, sB2l + offB[p] + ko);
                mma16816(acc[2 * p],     ah, bh[0], bh[1]);
                mma16816(acc[2 * p],     ah, bl[0], bl[1]);
                mma16816(acc[2 * p],     al, bh[0], bh[1]);
                mma16816(acc[2 * p + 1], ah, bh[2], bh[3]);
                mma16816(acc[2 * p + 1], ah, bl[2], bl[3]);
                mma16816(acc[2 * p + 1], al, bh[2], bh[3]);
            }
        }

        // ---- epilogue2: + b2 (+res) -> C ----
        {
            int r0 = bm + wm + gid;
            int r1 = r0 + 8;
#pragma unroll
            for (int ni = 0; ni < 8; ni++) {
                int cb = wn + ni * 8 + tg * 2;
                float b0 = __ldg(bias2 + cb);
                float b1 = __ldg(bias2 + cb + 1);
                float* a4 = acc[ni];
                float v00 = a4[0] + b0, v01 = a4[1] + b1;
                float v10 = a4[2] + b0, v11 = a4[3] + b1;
                if (r0 < M) {
                    if (res) {
                        float2 rr = *(const float2*)(res + (size_t)r0 * 128 + cb);
                        v00 += rr.x; v01 += rr.y;
                    }
                    *(float2*)(C + (size_t)r0 * 128 + cb) = make_float2(v00, v01);
                }
                if (r1 < M) {
                    if (res) {
                        float2 rr = *(const float2*)(res + (size_t)r1 * 128 + cb);
                        v10 += rr.x; v11 += rr.y;
                    }
                    *(float2*)(C + (size_t)r1 * 128 + cb) = make_float2(v10, v11);
                }
            }
        }
        __syncthreads();   // protect A buffers before next tile's staging
    }
}

// ---------------- merged preprocessing --------------------------------------
__global__ void prep_all(const float* __restrict__ lin_w, const float* __restrict__ mlp_w2,
                         const float* __restrict__ v1_w, const float* __restrict__ v2_w,
                         const float* __restrict__ u1_w, const float* __restrict__ fe_w2,
                         const float* __restrict__ u2_w,
                         const float* __restrict__ u1_b, const float* __restrict__ u2_b,
                         const float* __restrict__ mlp_w1, const float* __restrict__ mlp_b1) {
    int idx = blockIdx.x * blockDim.x + threadIdx.x;
    if (idx < 128) {
        g_u1bpad[idx] = (idx < 64) ? u1_b[idx] : 0.0f;
        g_u2bpad[idx] = (idx < 32) ? u2_b[idx] : 0.0f;
        g_bnacc[idx] = 0.0f;
    }
    if (idx < NN) g_nhist[idx] = 0;
    if (idx < 768) g_b1all[idx] = mlp_b1[(idx >> 7) * 128 + (idx & 127)];
    if (idx < NG_PAD * 768) {
        int k = idx / 768;
        int c = idx % 768;
        int l = c >> 7, nn2 = c & 127;
        g_m1all[idx] = (k < NGAUSS) ? mlp_w1[(size_t)l * NGAUSS * 128 + k * 128 + nn2] : 0.0f;
    }
    if (idx < TABROWS * NG_PAD) {
        int m = idx / NG_PAD;
        int g = idx % NG_PAD;
        float val = 0.0f;
        if (g < NGAUSS) {
            float d = (float)m * TAB_STEP;
            float off = (float)g * (6.0f / 49.0f);
            float tt = d - off;
            const float coeff = -0.5f / ((6.0f / 49.0f) * (6.0f / 49.0f));
            val = expf(coeff * tt * tt);
        }
        g_demb[idx] = val;
    }
    if (idx < 27 * 16384) {
        int slot = idx >> 14;
        int r = idx & 16383;
        int n = r >> 7;
        int k = r & 127;
        float a;
        if (slot < 24) {
            int l = slot >> 2, w = slot & 3;
            const float* src = (w == 0) ? lin_w : (w == 1) ? mlp_w2 : (w == 2) ? v1_w : v2_w;
            a = src[(size_t)l * 16384 + k * 128 + n];
        } else if (slot == 24) {
            a = (n < 64) ? u1_w[k * 64 + n] : 0.0f;
        } else if (slot == 25) {
            a = (k < 64) ? fe_w2[k * 128 + n] : 0.0f;
        } else {
            a = (k < 64 && n < 32) ? u2_w[k * 32 + n] : 0.0f;
        }
        __nv_bfloat16 hi = __float2bfloat16_rn(a);
        __nv_bfloat16 lo = __float2bfloat16_rn(a - __bfloat162float(hi));
        g_wthi[idx] = hi;
        g_wtlo[idx] = lo;
    }
}

// ---------------- fp16 pair-table pack ---------------------------------------
__global__ void pack_table() {
    int idx = blockIdx.x * blockDim.x + threadIdx.x;
    if (idx >= LL * TABM * 128) return;
    int c = idx & 127;
    int rest = idx >> 7;
    int i = rest % TABM;
    int l = rest / TABM;
    const float* tab = g_tables + (size_t)l * TABROWS * 128;
    float a = tab[(size_t)i * 128 + c];
    float b = tab[(size_t)(i + 1) * 128 + c];
    g_ptab[idx] = __floats2half2_rn(a, b);
}

// ---------------- edge geometry + per-destination histogram ------------------
__global__ void edge_geom_hist(const int* __restrict__ ei, const float* __restrict__ pos,
                               float* __restrict__ dist, int e_total) {
    int e = blockIdx.x * blockDim.x + threadIdx.x;
    if (e >= e_total) return;
    int r = ei[e];
    int c = ei[e_total + e];
    float dx = pos[r * 3 + 0] - pos[c * 3 + 0];
    float dy = pos[r * 3 + 1] - pos[c * 3 + 1];
    float dz = pos[r * 3 + 2] - pos[c * 3 + 2];
    float d = sqrtf(dx * dx + dy * dy + dz * dz);
    dist[e] = d;
    if (d < SKIP_D) atomicAdd(&g_nhist[c], 1);
}

__global__ void scan_nodes(int n) {
    __shared__ int part[256];
    int t = threadIdx.x;
    int chunk = (n + 255) / 256;
    int lo = t * chunk;
    int hi = min(lo + chunk, n);
    int s = 0;
    for (int i = lo; i < hi; i++) s += g_nhist[i];
    part[t] = s;
    __syncthreads();
    if (t == 0) {
        int acc = 0;
        for (int i = 0; i < 256; i++) { int c = part[i]; part[i] = acc; acc += c; }
    }
    __syncthreads();
    int acc = part[t];
    for (int i = lo; i < hi; i++) {
        int c = g_nhist[i];
        g_nstart[i] = acc;
        g_ncursor[i] = acc;
        acc += c;
    }
    if (hi == n) g_nstart[n] = acc;
}

__global__ void edge_build(const int* __restrict__ ei, const float* __restrict__ dist,
                           int e_total) {
    int e = blockIdx.x * blockDim.x + threadIdx.x;
    if (e >= e_total) return;
    float d = dist[e];
    if (d >= SKIP_D) return;
    int c = ei[e_total + e];
    int p = atomicAdd(&g_ncursor[c], 1);
    g_erow[p] = ei[e];
    g_efi[p] = d * TAB_INVSTEP;
}

// ---------------- SIMT fp32 SGEMM with f32x2 (small/odd shapes) -------------
__global__ void __launch_bounds__(256, 2) sgemm(
    const float* __restrict__ A, const float* __restrict__ B,
    const float* __restrict__ bias, const float* __restrict__ res,
    float* __restrict__ C, int M, int N, int K, int Kb, int act) {
    __shared__ float As[2][8][128];
    __shared__ float Bs[2][8][128];
    const int tid = threadIdx.x;
    const int bm = blockIdx.y * 128;
    const int bn = blockIdx.x * 128;
    const int tx = tid & 15;
    const int ty = tid >> 4;
    const int ar = tid >> 1;
    const int ak = (tid & 1) * 4;
    const int bk = tid >> 5;
    const int bn4 = (tid & 31) * 4;
    const int arow = bm + ar;
    const int bcol = bn + bn4;
    const int KT = (K + 7) >> 3;

    unsigned long long acc[8][4];
#pragma unroll
    for (int i = 0; i < 8; i++)
#pragma unroll
        for (int j = 0; j < 4; j++) acc[i][j] = 0ull;

    float4 pa = make_float4(0, 0, 0, 0);
    float4 pb = make_float4(0, 0, 0, 0);
    if (arow < M && ak < K) pa = *(const float4*)(A + (size_t)arow * K + ak);
    if (bk < Kb && bcol < N) pb = *(const float4*)(B + (size_t)bk * N + bcol);
    As[0][ak + 0][ar] = pa.x; As[0][ak + 1][ar] = pa.y;
    As[0][ak + 2][ar] = pa.z; As[0][ak + 3][ar] = pa.w;
    *(float4*)&Bs[0][bk][bn4] = pb;
    __syncthreads();

    for (int kt = 0; kt < KT; kt++) {
        const int s = kt & 1;
        if (kt + 1 < KT) {
            int k0 = (kt + 1) * 8;
            pa = make_float4(0, 0, 0, 0);
            pb = make_float4(0, 0, 0, 0);
            if (arow < M && (k0 + ak) < K) pa = *(const float4*)(A + (size_t)arow * K + k0 + ak);
            if ((k0 + bk) < Kb && bcol < N) pb = *(const float4*)(B + (size_t)(k0 + bk) * N + bcol);
        }
#pragma unroll
        for (int k = 0; k < 8; k++) {
            float a[8];
            *(float4*)&a[0] = *(const float4*)&As[s][k][ty * 8];
            *(float4*)&a[4] = *(const float4*)&As[s][k][ty * 8 + 4];
            ulonglong2 bl = *(const ulonglong2*)&Bs[s][k][tx * 8];
            ulonglong2 bh = *(const ulonglong2*)&Bs[s][k][tx * 8 + 4];
#pragma unroll
            for (int i = 0; i < 8; i++) {
                unsigned long long ai = bcast2(a[i]);
                ffma2(acc[i][0], ai, bl.x);
                ffma2(acc[i][1], ai, bl.y);
                ffma2(acc[i][2], ai, bh.x);
                ffma2(acc[i][3], ai, bh.y);
            }
        }
        if (kt + 1 < KT) {
            const int so = (kt + 1) & 1;
            As[so][ak + 0][ar] = pa.x; As[so][ak + 1][ar] = pa.y;
            As[so][ak + 2][ar] = pa.z; As[so][ak + 3][ar] = pa.w;
            *(float4*)&Bs[so][bk][bn4] = pb;
            __syncthreads();
        }
    }

    const int cbase = bn + tx * 8;
    float bv[8];
#pragma unroll
    for (int j = 0; j < 8; j++) bv[j] = (bias && (cbase + j) < N) ? bias[cbase + j] : 0.0f;

#pragma unroll
    for (int i = 0; i < 8; i++) {
        int row = bm + ty * 8 + i;
        if (row >= M) continue;
        float c[8];
        unpack2(acc[i][0], c[0], c[1]);
        unpack2(acc[i][1], c[2], c[3]);
        unpack2(acc[i][2], c[4], c[5]);
        unpack2(acc[i][3], c[6], c[7]);
#pragma unroll
        for (int j = 0; j < 8; j++) {
            float v = c[j] + bv[j];
            if (act == 1) v = fmaxf(v, 0.0f);
            else if (act == 2) v = sspf(v);
            c[j] = v;
        }
        if (res) {
#pragma unroll
            for (int j = 0; j < 8; j++)
                if ((cbase + j) < N) c[j] += res[(size_t)row * N + cbase + j];
        }
        if (cbase < N)
            *(float4*)(C + (size_t)row * N + cbase) = make_float4(c[0], c[1], c[2], c[3]);
        if (cbase + 4 < N)
            *(float4*)(C + (size_t)row * N + cbase + 4) = make_float4(c[4], c[5], c[6], c[7]);
    }
}

// ---------------- batchnorm ---------------------------------------------------
__global__ void bn_reduce(const float* __restrict__ h, int n) {
    __shared__ float ss[4][64];
    __shared__ float sq[4][64];
    int c = threadIdx.x & 63;
    int g = threadIdx.x >> 6;
    float s = 0.0f, q = 0.0f;
    for (int row = blockIdx.x * 4 + g; row < n; row += gridDim.x * 4) {
        float v = h[row * 64 + c];
        s += v;
        q += v * v;
    }
    ss[g][c] = s;
    sq[g][c] = q;
    __syncthreads();
    if (g == 0) {
        atomicAdd(&g_bnacc[c], ss[0][c] + ss[1][c] + ss[2][c] + ss[3][c]);
        atomicAdd(&g_bnacc[64 + c], sq[0][c] + sq[1][c] + sq[2][c] + sq[3][c]);
    }
}

__global__ void bn_apply(const float* __restrict__ h, float* __restrict__ hn,
                         const float* __restrict__ gamma, const float* __restrict__ beta,
                         int n) {
    int idx = blockIdx.x * blockDim.x + threadIdx.x;
    if (idx >= n * 128) return;
    int c = idx & 127;
    float y = 0.0f;
    if (c < 64) {
        float invN = 1.0f / (float)n;
        float mu = g_bnacc[c] * invN;
        float var = g_bnacc[64 + c] * invN - mu * mu;
        y = (h[(idx >> 7) * 64 + c] - mu) / sqrtf(var + 1e-5f) * gamma[c] + beta[c];
        y = fmaxf(y, 0.0f);
    }
    hn[idx] = y;
}

// ---------------- edge gather: one warp per destination node (fp16 pairs) ----
__global__ void __launch_bounds__(256) edge_gather(
    const float* __restrict__ vlin, const __half2* __restrict__ ptab,
    float* __restrict__ agg, int n) {
    int node = (blockIdx.x * blockDim.x + threadIdx.x) >> 5;
    int lane = threadIdx.x & 31;
    if (node >= n) return;
    int j = g_nstart[node];
    int end = g_nstart[node + 1];

    float a0 = 0.0f, a1 = 0.0f, a2 = 0.0f, a3 = 0.0f;

    for (; j + 4 <= end; j += 4) {
        int ri[4]; float fi[4]; int ii[4]; float fr[4];
        uint4 tp[4]; float4 vv[4];
#pragma unroll
        for (int q = 0; q < 4; q++) {
            ri[q] = __ldg(g_erow + j + q);
            fi[q] = __ldg(g_efi + j + q);
            ii[q] = (int)fi[q];
            fr[q] = fi[q] - (float)ii[q];
        }
#pragma unroll
        for (int q = 0; q < 4; q++) {
            tp[q] = __ldg(reinterpret_cast<const uint4*>(ptab + (size_t)ii[q] * 128) + lane);
            vv[q] = __ldg(reinterpret_cast<const float4*>(vlin + (size_t)ri[q] * 128) + lane);
        }
#pragma unroll
        for (int q = 0; q < 4; q++) {
            float2 p0 = __half22float2(*(__half2*)&tp[q].x);
            float2 p1 = __half22float2(*(__half2*)&tp[q].y);
            float2 p2 = __half22float2(*(__half2*)&tp[q].z);
            float2 p3 = __half22float2(*(__half2*)&tp[q].w);
            a0 = fmaf(vv[q].x, p0.x + fr[q] * (p0.y - p0.x), a0);
            a1 = fmaf(vv[q].y, p1.x + fr[q] * (p1.y - p1.x), a1);
            a2 = fmaf(vv[q].z, p2.x + fr[q] * (p2.y - p2.x), a2);
            a3 = fmaf(vv[q].w, p3.x + fr[q] * (p3.y - p3.x), a3);
        }
    }
    for (; j < end; j++) {
        int   r0 = __ldg(g_erow + j);
        float f0 = __ldg(g_efi + j);
        int   i0 = (int)f0;
        float fr0 = f0 - (float)i0;
        uint4 tq = __ldg(reinterpret_cast<const uint4*>(ptab + (size_t)i0 * 128) + lane);
        float4 vv0 = __ldg(reinterpret_cast<const float4*>(vlin + (size_t)r0 * 128) + lane);
        float2 p0 = __half22float2(*(__half2*)&tq.x);
        float2 p1 = __half22float2(*(__half2*)&tq.y);
        float2 p2 = __half22float2(*(__half2*)&tq.z);
        float2 p3 = __half22float2(*(__half2*)&tq.w);
        a0 = fmaf(vv0.x, p0.x + fr0 * (p0.y - p0.x), a0);
        a1 = fmaf(vv0.y, p1.x + fr0 * (p1.y - p1.x), a1);
        a2 = fmaf(vv0.z, p2.x + fr0 * (p2.y - p2.x), a2);
        a3 = fmaf(vv0.w, p3.x + fr0 * (p3.y - p3.x), a3);
    }

    *(float4*)(agg + (size_t)node * 128 + lane * 4) = make_float4(a0, a1, a2, a3);
}

// ---------------- final per-graph scatter (batch sorted; s stride 128) --------
__global__ void node_out(const float* __restrict__ s, const int* __restrict__ batch,
                         float* __restrict__ out, int n) {
    int w = (blockIdx.x * blockDim.x + threadIdx.x) >> 5;
    int lane = threadIdx.x & 31;
    int start = w * 128;
    if (start >= n) return;
    int end = min(start + 128, n);
    int cur = __ldg(batch + start);
    float acc = 0.0f;
    for (int node = start; node < end; node++) {
        int b = __ldg(batch + node);
        if (b != cur) {
            atomicAdd(&out[cur * 32 + lane], acc);
            acc = 0.0f;
            cur = b;
        }
        acc += s[(size_t)node * 128 + lane];
    }
    atomicAdd(&out[cur * 32 + lane], acc);
}

// ---------------- host ---------------------------------------------------------
static float* sym(const void* s) {
    void* p = nullptr;
    cudaGetSymbolAddress(&p, s);
    return (float*)p;
}

extern "C" void kernel_launch(void* const* d_in, const int* in_sizes, int n_in,
                              void* d_out, int out_size) {
    const float* x       = (const float*)d_in[0];
    const float* pos     = (const float*)d_in[1];
    const int*   batch   = (const int*)d_in[2];
    const int*   ei      = (const int*)d_in[3];
    const float* fe_w1   = (const float*)d_in[4];
    const float* fe_b1   = (const float*)d_in[5];
    const float* bng     = (const float*)d_in[6];
    const float* bnb     = (const float*)d_in[7];
    const float* fe_w2   = (const float*)d_in[8];
    const float* fe_b2   = (const float*)d_in[9];
    const float* lin_w   = (const float*)d_in[10];
    const float* mlp_w1  = (const float*)d_in[11];
    const float* mlp_b1  = (const float*)d_in[12];
    const float* mlp_w2  = (const float*)d_in[13];
    const float* mlp_b2  = (const float*)d_in[14];
    const float* v1_w    = (const float*)d_in[15];
    const float* v1_b    = (const float*)d_in[16];
    const float* v2_w    = (const float*)d_in[17];
    const float* v2_b    = (const float*)d_in[18];
    const float* u1_w    = (const float*)d_in[19];
    const float* u1_b    = (const float*)d_in[20];
    const float* u2_w    = (const float*)d_in[21];
    const float* u2_b    = (const float*)d_in[22];
    float* out = (float*)d_out;

    int n = in_sizes[0] / 28;
    int e = in_sizes[3] / 2;

    float* p_h      = sym(g_h);
    float* p_hn     = sym(g_hn);
    float* p_v      = sym(g_v);
    float* p_vlin   = sym(g_vlin);
    float* p_agg    = sym(g_agg);
    float* p_t1     = sym(g_t1);
    float* p_dist   = sym(g_dist);
    float* p_demb   = sym(g_demb);
    float* p_tabh   = sym(g_tabh);
    float* p_tables = sym(g_tables);
    __half2* p_ptab = (__half2*)sym(g_ptab);
    float* p_u1b    = sym(g_u1bpad);
    float* p_u2b    = sym(g_u2bpad);
    float* p_m1all  = sym(g_m1all);
    float* p_b1all  = sym(g_b1all);
    __nv_bfloat16* p_whi = (__nv_bfloat16*)sym(g_wthi);
    __nv_bfloat16* p_wlo = (__nv_bfloat16*)sym(g_wtlo);

    cudaFuncSetAttribute(mgemm, cudaFuncAttributeMaxDynamicSharedMemorySize, MG_SMEM);
    cudaFuncSetAttribute(fgemm, cudaFuncAttributeMaxDynamicSharedMemorySize, FG_SMEM);

    int sms = 148;
    cudaDeviceGetAttribute(&sms, cudaDevAttrMultiProcessorCount, 0);

    dim3 gemm_t(256);
    auto gemm_grid = [](int M, int N) {
        return dim3((unsigned)((N + 127) / 128), (unsigned)((M + 127) / 128));
    };
    int mtiles = (n + 63) / 64;
    int ftiles = (n + 127) / 128;
    int ttiles = (TABROWS + 63) / 64;
    int mgrid = mtiles < 2 * sms ? mtiles : 2 * sms;
    int fgrid = ftiles < sms ? ftiles : sms;
    int ggrid = (n + 7) / 8;

    // ---- phase 1: merged prep + batched table build + fp16 pair pack ----
    prep_all<<<(27 * 16384 + 255) / 256, 256>>>(lin_w, mlp_w2, v1_w, v2_w, u1_w,
                                                fe_w2, u2_w, u1_b, u2_b, mlp_w1, mlp_b1);
    sgemm<<<gemm_grid(TABROWS, 768), gemm_t>>>(p_demb, p_m1all, p_b1all, nullptr,
                                               p_tabh, TABROWS, 768, NG_PAD, NG_PAD, 2);
    mgemm<<<ttiles * LL, 256, MG_SMEM>>>(p_tabh, p_whi + (size_t)1 * 16384,
                                         p_wlo + (size_t)1 * 16384, mlp_b2, nullptr,
                                         p_tables, TABROWS, 3, ttiles, LL, 768);
    pack_table<<<(LL * TABM * 128 + 255) / 256, 256>>>();

    // ---- phase 2: edge geometry + CSR-by-destination sort ----
    edge_geom_hist<<<(e + 255) / 256, 256>>>(ei, pos, p_dist, e);
    scan_nodes<<<1, 256>>>(n);
    edge_build<<<(e + 255) / 256, 256>>>(ei, p_dist, e);

    // ---- phase 3: feature embedding ----
    sgemm<<<gemm_grid(n, 64), gemm_t>>>(x, fe_w1, fe_b1, nullptr, p_h, n, 64, 28, 28, 0);
    bn_reduce<<<512, 256>>>(p_h, n);
    bn_apply<<<(n * 128 + 255) / 256, 256>>>(p_h, p_hn, bng, bnb, n);
    mgemm<<<mgrid, 256, MG_SMEM>>>(p_hn, p_whi + (size_t)25 * 16384,
                                   p_wlo + (size_t)25 * 16384, fe_b2, nullptr,
                                   p_v, n, 1, mtiles, 1, 128);

    // ---- phase 4: interaction layers ----
    for (int l = 0; l < LL; l++) {
        const float* w1b = v1_b + (size_t)l * 128;
        const float* w2b = v2_b + (size_t)l * 128;
        __nv_bfloat16* lw_hi = p_whi + (size_t)(l * 4 + 0) * 16384;
        __nv_bfloat16* lw_lo = p_wlo + (size_t)(l * 4 + 0) * 16384;
        __nv_bfloat16* w1_hi = p_whi + (size_t)(l * 4 + 2) * 16384;
        __nv_bfloat16* w1_lo = p_wlo + (size_t)(l * 4 + 2) * 16384;
        __nv_bfloat16* w2_hi = p_whi + (size_t)(l * 4 + 3) * 16384;
        __nv_bfloat16* w2_lo = p_wlo + (size_t)(l * 4 + 3) * 16384;

        mgemm<<<mgrid, 256, MG_SMEM>>>(p_v, lw_hi, lw_lo, nullptr, nullptr,
                                       p_vlin, n, 0, mtiles, 1, 128);
        edge_gather<<<ggrid, 256>>>(p_vlin, p_ptab + (size_t)l * TABM * 128,
                                    p_agg, n);
        fgemm<<<fgrid, 512, FG_SMEM>>>(p_agg, w1_hi, w1_lo, w2_hi, w2_lo,
                                       w1b, w2b, p_v, p_v, n, ftiles);
    }

    // ---- phase 5: readout ----
    fgemm<<<fgrid, 512, FG_SMEM>>>(p_v,
                                   p_whi + (size_t)24 * 16384, p_wlo + (size_t)24 * 16384,
                                   p_whi + (size_t)26 * 16384, p_wlo + (size_t)26 * 16384,
                                   p_u1b, p_u2b, nullptr, p_t1, n, ftiles);
    cudaMemsetAsync(out, 0, (size_t)out_size * sizeof(float));
    node_out<<<((n + 127) / 128 * 32 + 255) / 256, 256>>>(p_t1, batch, out, n);
}

// round 14
// speedup vs baseline: 1.2685x; 1.0633x over previous
#include <cuda_runtime.h>
#include <cuda_bf16.h>
#include <cuda_fp16.h>
#include <math.h>
#include <stdint.h>

// Problem constants
#define NN 50000
#define EE 800000
#define GG 512
#define LL 6
#define NGAUSS 50
#define NG_PAD 56
#define TABM 1024                  // table intervals over [0, 7]
#define TABROWS (TABM + 1)
#define TAB_MAX 7.0f
#define TAB_INVSTEP ((float)TABM / TAB_MAX)
#define TAB_STEP (TAB_MAX / (float)TABM)
#define SKIP_D 6.97f
#define LN2F 0.69314718055994530942f
#define PIF 3.14159265358979323846f

// ---------------- scratch (device globals; no allocation allowed) -------------
__device__ __align__(256) float g_h[NN * 64];
__device__ __align__(256) float g_hn[NN * 128];      // K=128 padded
__device__ __align__(256) float g_v[NN * 128];
__device__ __align__(256) __half g_vlinh[NN * 128];  // fp16 vlin
__device__ __align__(256) float g_agg[NN * 128];
__device__ __align__(256) float g_t1[NN * 128];
__device__ __align__(256) float g_dist[EE];
__device__ __align__(256) float g_demb[TABROWS * NG_PAD];
__device__ __align__(256) float g_tabh[TABROWS * 768];   // all 6 layers, N=768
__device__ __align__(256) float g_tables[LL * TABROWS * 128];
__device__ __align__(256) __half2 g_ptab[LL * TABM * 128];  // fp16 (T[i],T[i+1]) pairs
__device__ __align__(256) float g_bnacc[128];
__device__ __align__(256) float g_u1bpad[128];
__device__ __align__(256) float g_u2bpad[128];
__device__ __align__(256) float g_m1all[NG_PAD * 768];
__device__ __align__(256) float g_b1all[768];
// bf16 hi/lo split, pre-transposed weights [slot][n][k]
// slots 0..23: l*4 + {lin,mlp2,v1,v2}; 24: u1 (N-pad); 25: fe2 (K-pad); 26: u2 (N,K-pad)
__device__ __align__(256) __nv_bfloat16 g_wthi[27 * 128 * 128];
__device__ __align__(256) __nv_bfloat16 g_wtlo[27 * 128 * 128];
// CSR-by-destination edge sort
__device__ __align__(256) int   g_nhist[NN];
__device__ __align__(256) int   g_nstart[NN + 1];
__device__ __align__(256) int   g_ncursor[NN];
__device__ __align__(256) int   g_erow[EE];
__device__ __align__(256) float g_efi[EE];

// ---------------- helpers ---------------------------------------------------
__device__ __forceinline__ float sspf(float x) {
    return fmaxf(x, 0.0f) + log1pf(expf(-fabsf(x))) - LN2F;
}
__device__ __forceinline__ unsigned long long bcast2(float x) {
    unsigned long long r;
    asm("mov.b64 %0, {%1, %1};" : "=l"(r) : "f"(x));
    return r;
}
__device__ __forceinline__ void ffma2(unsigned long long& d,
                                      unsigned long long a, unsigned long long b) {
    asm("fma.rn.f32x2 %0, %1, %2, %0;" : "+l"(d) : "l"(a), "l"(b));
}
__device__ __forceinline__ void unpack2(unsigned long long v, float& lo, float& hi) {
    asm("mov.b64 {%0, %1}, %2;" : "=f"(lo), "=f"(hi) : "l"(v));
}
__device__ __forceinline__ uint32_t smem_u32(const void* p) {
    uint32_t a;
    asm("{ .reg .u64 t; cvta.to.shared.u64 t, %1; cvt.u32.u64 %0, t; }" : "=r"(a) : "l"(p));
    return a;
}
__device__ __forceinline__ void mma16816(float* c, const uint32_t* a,
                                         uint32_t b0, uint32_t b1) {
    asm volatile(
        "mma.sync.aligned.m16n8k16.row.col.f32.bf16.bf16.f32 "
        "{%0,%1,%2,%3}, {%4,%5,%6,%7}, {%8,%9}, {%0,%1,%2,%3};"
        : "+f"(c[0]), "+f"(c[1]), "+f"(c[2]), "+f"(c[3])
        : "r"(a[0]), "r"(a[1]), "r"(a[2]), "r"(a[3]), "r"(b0), "r"(b1));
}
__device__ __forceinline__ void ldsm4(uint32_t* r, uint32_t addr) {
    asm volatile("ldmatrix.sync.aligned.m8n8.x4.shared.b16 {%0,%1,%2,%3}, [%4];"
        : "=r"(r[0]), "=r"(r[1]), "=r"(r[2]), "=r"(r[3]) : "r"(addr));
}
__device__ __forceinline__ uint32_t packbf2(float x, float y) {
    __nv_bfloat162 h = __float22bfloat162_rn(make_float2(x, y));
    return *(uint32_t*)&h;
}

#define MG_STRIDE 136   // bf16 per smem row (272B) — conflict-free ldmatrix
#define MG_A1 (64 * MG_STRIDE * 2)
#define MG_B1 (128 * MG_STRIDE * 2)
#define MG_SMEM (2 * MG_A1 + 2 * MG_B1)
// fgemm v2: A (128 rows, hi/lo) + W1 (hi/lo) + W2 (hi/lo), all 128x128
#define FG_A1 MG_B1
#define FG_SMEM (6 * FG_A1)

// ================= bf16x3 HMMA GEMM v3 (pipelined A prefetch) ================
// outh: store C as packed fp16 instead of fp32 (act must be 0, no res).
__global__ void __launch_bounds__(256, 2) mgemm(
    const float* __restrict__ A, const __nv_bfloat16* __restrict__ Bhi,
    const __nv_bfloat16* __restrict__ Blo, const float* __restrict__ bias,
    const float* __restrict__ res, float* __restrict__ C, int M, int act,
    int tiles_per_mat, int nmats, int lda, int outh) {
    extern __shared__ char smem[];
    __nv_bfloat16* Ahs = (__nv_bfloat16*)(smem);
    __nv_bfloat16* Als = (__nv_bfloat16*)(smem + MG_A1);
    __nv_bfloat16* Bhs = (__nv_bfloat16*)(smem + 2 * MG_A1);
    __nv_bfloat16* Bls = (__nv_bfloat16*)(smem + 2 * MG_A1 + MG_B1);
    const uint32_t sb = smem_u32(smem);
    const uint32_t sAh = sb, sAl = sb + MG_A1;
    const uint32_t sBh = sb + 2 * MG_A1, sBl = sb + 2 * MG_A1 + MG_B1;

    const int t = threadIdx.x;
    const int lane = t & 31;
    const int w = t >> 5;
    const int wm = (w & 3) * 16;
    const int wn = (w >> 2) * 64;
    const int gid = lane >> 2;
    const int tg = lane & 3;

    const int arow_l = t >> 2;
    const int aseg = (t & 3) * 32;

    const int lrow = ((t >> 3) & 1) * 8 + (t & 7);
    const int lkb  = ((t >> 4) & 1) * 16;
    const uint32_t offA0 = (uint32_t)(wm + lrow) * 272 + lkb;
    const int brow = ((t >> 4) & 1) * 8 + (t & 7);
    const int bkb  = ((t >> 3) & 1) * 16;
    uint32_t offB[4];
#pragma unroll
    for (int p = 0; p < 4; p++) offB[p] = (uint32_t)(wn + p * 16 + brow) * 272 + bkb;

    const int total_tiles = tiles_per_mat * nmats;
    int cur_mat = -1;
    const float4 z4 = make_float4(0, 0, 0, 0);

    float4 pa[8];
    if (blockIdx.x < total_tiles) {
        int tl = blockIdx.x;
        int mat = (nmats == 1) ? 0 : (tl / tiles_per_mat);
        int lt  = (nmats == 1) ? tl : (tl % tiles_per_mat);
        int grow = lt * 64 + arow_l;
        bool valid = grow < M;
        const float4* ap = (const float4*)(A + (size_t)(valid ? grow : 0) * lda + mat * 128 + aseg);
#pragma unroll
        for (int c = 0; c < 8; c++) pa[c] = valid ? ap[c] : z4;
    }

    for (int tile = blockIdx.x; tile < total_tiles; tile += gridDim.x) {
        const int mat = (nmats == 1) ? 0 : (tile / tiles_per_mat);
        const int lt  = (nmats == 1) ? tile : (tile % tiles_per_mat);
        const int bm = lt * 64;

        if (mat != cur_mat) {
            cur_mat = mat;
            const __nv_bfloat16* bh = Bhi + (size_t)mat * 4 * 16384;
            const __nv_bfloat16* bl = Blo + (size_t)mat * 4 * 16384;
            int row = t >> 1, half = (t & 1) * 64;
            const uint4* bhp = (const uint4*)(bh + (size_t)row * 128 + half);
            const uint4* blp = (const uint4*)(bl + (size_t)row * 128 + half);
            __nv_bfloat16* dbh = Bhs + row * MG_STRIDE + half;
            __nv_bfloat16* dbl = Bls + row * MG_STRIDE + half;
#pragma unroll
            for (int c = 0; c < 8; c++) {
                *(uint4*)(dbh + c * 8) = bhp[c];
                *(uint4*)(dbl + c * 8) = blp[c];
            }
        }

        {
            __nv_bfloat16* ahp = Ahs + arow_l * MG_STRIDE + aseg;
            __nv_bfloat16* alp = Als + arow_l * MG_STRIDE + aseg;
#pragma unroll
            for (int c = 0; c < 8; c++) {
                float4 v = pa[c];
                uint32_t h0 = packbf2(v.x, v.y);
                uint32_t h1 = packbf2(v.z, v.w);
                __nv_bfloat162* h0p = (__nv_bfloat162*)&h0;
                __nv_bfloat162* h1p = (__nv_bfloat162*)&h1;
                uint32_t l0 = packbf2(v.x - __bfloat162float(h0p->x), v.y - __bfloat162float(h0p->y));
                uint32_t l1 = packbf2(v.z - __bfloat162float(h1p->x), v.w - __bfloat162float(h1p->y));
                *(uint2*)(ahp + c * 4) = make_uint2(h0, h1);
                *(uint2*)(alp + c * 4) = make_uint2(l0, l1);
            }
        }
        __syncthreads();

        {
            int ntile = tile + gridDim.x;
            if (ntile < total_tiles) {
                int nmat = (nmats == 1) ? 0 : (ntile / tiles_per_mat);
                int nlt  = (nmats == 1) ? ntile : (ntile % tiles_per_mat);
                int grow = nlt * 64 + arow_l;
                bool valid = grow < M;
                const float4* ap = (const float4*)(A + (size_t)(valid ? grow : 0) * lda + nmat * 128 + aseg);
#pragma unroll
                for (int c = 0; c < 8; c++) pa[c] = valid ? ap[c] : z4;
            }
        }

        float acc[8][4];
#pragma unroll
        for (int ni = 0; ni < 8; ni++)
#pragma unroll
            for (int q = 0; q < 4; q++) acc[ni][q] = 0.0f;

#pragma unroll
        for (int k0 = 0; k0 < 8; k0++) {
            const uint32_t ko = k0 * 32;
            uint32_t ah[4], al[4];
            ldsm4(ah, sAh + offA0 + ko);
            ldsm4(al, sAl + offA0 + ko);
#pragma unroll
            for (int p = 0; p < 4; p++) {
                uint32_t bh[4], bl[4];
                ldsm4(bh, sBh + offB[p] + ko);
                ldsm4(bl, sBl + offB[p] + ko);
                mma16816(acc[2 * p],     ah, bh[0], bh[1]);
                mma16816(acc[2 * p],     ah, bl[0], bl[1]);
                mma16816(acc[2 * p],     al, bh[0], bh[1]);
                mma16816(acc[2 * p + 1], ah, bh[2], bh[3]);
                mma16816(acc[2 * p + 1], ah, bl[2], bl[3]);
                mma16816(acc[2 * p + 1], al, bh[2], bh[3]);
            }
        }

        const float* mbias = bias ? (bias + (size_t)mat * 128) : nullptr;
        float* mC = C;
        if (nmats > 1) mC = C + (size_t)mat * (size_t)TABROWS * 128;
        {
            int r0 = bm + wm + gid;
            int r1 = r0 + 8;
            float sc0 = 1.0f, sc1 = 1.0f;
            if (act == 3) {
                sc0 = 0.5f * (cosf((float)r0 * TAB_STEP * (PIF / 6.0f)) + 1.0f);
                sc1 = 0.5f * (cosf((float)r1 * TAB_STEP * (PIF / 6.0f)) + 1.0f);
            }
#pragma unroll
            for (int ni = 0; ni < 8; ni++) {
                int cb = wn + ni * 8 + tg * 2;
                float b0 = mbias ? __ldg(mbias + cb) : 0.0f;
                float b1 = mbias ? __ldg(mbias + cb + 1) : 0.0f;
                float* a4 = acc[ni];
                float v00 = a4[0] + b0, v01 = a4[1] + b1;
                float v10 = a4[2] + b0, v11 = a4[3] + b1;
                if (act == 1) {
                    v00 = fmaxf(v00, 0.0f); v01 = fmaxf(v01, 0.0f);
                    v10 = fmaxf(v10, 0.0f); v11 = fmaxf(v11, 0.0f);
                } else if (act == 2) {
                    v00 = sspf(v00); v01 = sspf(v01); v10 = sspf(v10); v11 = sspf(v11);
                } else if (act == 3) {
                    v00 *= sc0; v01 *= sc0; v10 *= sc1; v11 *= sc1;
                }
                if (outh) {
                    __half* hC = (__half*)mC;
                    if (r0 < M)
                        *(__half2*)(hC + (size_t)r0 * 128 + cb) = __floats2half2_rn(v00, v01);
                    if (r1 < M)
                        *(__half2*)(hC + (size_t)r1 * 128 + cb) = __floats2half2_rn(v10, v11);
                } else {
                    if (r0 < M) {
                        if (res) {
                            float2 rr = *(const float2*)(res + (size_t)r0 * 128 + cb);
                            v00 += rr.x; v01 += rr.y;
                        }
                        *(float2*)(mC + (size_t)r0 * 128 + cb) = make_float2(v00, v01);
                    }
                    if (r1 < M) {
                        if (res) {
                            float2 rr = *(const float2*)(res + (size_t)r1 * 128 + cb);
                            v10 += rr.x; v11 += rr.y;
                        }
                        *(float2*)(mC + (size_t)r1 * 128 + cb) = make_float2(v10, v11);
                    }
                }
            }
        }
        __syncthreads();
    }
}

// ===== fused double-GEMM v2 (512 threads, M=128 tiles, 16 warps/SM) ==========
__global__ void __launch_bounds__(512, 1) fgemm(
    const float* __restrict__ A,
    const __nv_bfloat16* __restrict__ B1hi, const __nv_bfloat16* __restrict__ B1lo,
    const __nv_bfloat16* __restrict__ B2hi, const __nv_bfloat16* __restrict__ B2lo,
    const float* __restrict__ bias1, const float* __restrict__ bias2,
    const float* __restrict__ res, float* __restrict__ C, int M, int tiles) {
    extern __shared__ char smem[];
    __nv_bfloat16* Ahs  = (__nv_bfloat16*)(smem);
    __nv_bfloat16* Als  = (__nv_bfloat16*)(smem + FG_A1);
    const uint32_t sb = smem_u32(smem);
    const uint32_t sAh = sb, sAl = sb + FG_A1;
    const uint32_t sB1h = sb + 2 * FG_A1, sB1l = sb + 3 * FG_A1;
    const uint32_t sB2h = sb + 4 * FG_A1, sB2l = sb + 5 * FG_A1;
    __nv_bfloat16* B1hs = (__nv_bfloat16*)(smem + 2 * FG_A1);
    __nv_bfloat16* B1ls = (__nv_bfloat16*)(smem + 3 * FG_A1);
    __nv_bfloat16* B2hs = (__nv_bfloat16*)(smem + 4 * FG_A1);
    __nv_bfloat16* B2ls = (__nv_bfloat16*)(smem + 5 * FG_A1);

    const int t = threadIdx.x;
    const int lane = t & 31;
    const int w = t >> 5;           // 0..15
    const int wm = (w >> 1) * 16;   // 8 M-slots of 16 rows
    const int wn = (w & 1) * 64;    // 2 N-halves
    const int gid = lane >> 2;
    const int tg = lane & 3;
    const int arow_l = t >> 2;      // 0..127
    const int aseg = (t & 3) * 32;
    const int lrow = ((lane >> 3) & 1) * 8 + (lane & 7);
    const int lkb  = ((lane >> 4) & 1) * 16;
    const uint32_t offA0 = (uint32_t)(wm + lrow) * 272 + lkb;
    const int brow = ((lane >> 4) & 1) * 8 + (lane & 7);
    const int bkb  = ((lane >> 3) & 1) * 16;
    uint32_t offB[4];
#pragma unroll
    for (int p = 0; p < 4; p++) offB[p] = (uint32_t)(wn + p * 16 + brow) * 272 + bkb;

    // stage both weight matrices once (512 threads: each does 32 cols/matrix)
    {
        const int srow = t >> 2, shalf = (t & 3) * 32;
        const uint4* b1h = (const uint4*)(B1hi + (size_t)srow * 128 + shalf);
        const uint4* b1l = (const uint4*)(B1lo + (size_t)srow * 128 + shalf);
        const uint4* b2h = (const uint4*)(B2hi + (size_t)srow * 128 + shalf);
        const uint4* b2l = (const uint4*)(B2lo + (size_t)srow * 128 + shalf);
        __nv_bfloat16* d1h = B1hs + srow * MG_STRIDE + shalf;
        __nv_bfloat16* d1l = B1ls + srow * MG_STRIDE + shalf;
        __nv_bfloat16* d2h = B2hs + srow * MG_STRIDE + shalf;
        __nv_bfloat16* d2l = B2ls + srow * MG_STRIDE + shalf;
#pragma unroll
        for (int c = 0; c < 4; c++) {
            *(uint4*)(d1h + c * 8) = b1h[c];
            *(uint4*)(d1l + c * 8) = b1l[c];
            *(uint4*)(d2h + c * 8) = b2h[c];
            *(uint4*)(d2l + c * 8) = b2l[c];
        }
    }

    const float4 z4 = make_float4(0, 0, 0, 0);
    float4 pa[8];
    if (blockIdx.x < tiles) {
        int grow = blockIdx.x * 128 + arow_l;
        bool valid = grow < M;
        const float4* ap = (const float4*)(A + (size_t)(valid ? grow : 0) * 128 + aseg);
#pragma unroll
        for (int c = 0; c < 8; c++) pa[c] = valid ? ap[c] : z4;
    }

    for (int tile = blockIdx.x; tile < tiles; tile += gridDim.x) {
        const int bm = tile * 128;

        {
            __nv_bfloat16* ahp = Ahs + arow_l * MG_STRIDE + aseg;
            __nv_bfloat16* alp = Als + arow_l * MG_STRIDE + aseg;
#pragma unroll
            for (int c = 0; c < 8; c++) {
                float4 v = pa[c];
                uint32_t h0 = packbf2(v.x, v.y);
                uint32_t h1 = packbf2(v.z, v.w);
                __nv_bfloat162* h0p = (__nv_bfloat162*)&h0;
                __nv_bfloat162* h1p = (__nv_bfloat162*)&h1;
                uint32_t l0 = packbf2(v.x - __bfloat162float(h0p->x), v.y - __bfloat162float(h0p->y));
                uint32_t l1 = packbf2(v.z - __bfloat162float(h1p->x), v.w - __bfloat162float(h1p->y));
                *(uint2*)(ahp + c * 4) = make_uint2(h0, h1);
                *(uint2*)(alp + c * 4) = make_uint2(l0, l1);
            }
        }
        __syncthreads();

        {
            int ntile = tile + gridDim.x;
            if (ntile < tiles) {
                int grow = ntile * 128 + arow_l;
                bool valid = grow < M;
                const float4* ap = (const float4*)(A + (size_t)(valid ? grow : 0) * 128 + aseg);
#pragma unroll
                for (int c = 0; c < 8; c++) pa[c] = valid ? ap[c] : z4;
            }
        }

        float acc[8][4];
#pragma unroll
        for (int ni = 0; ni < 8; ni++)
#pragma unroll
            for (int q = 0; q < 4; q++) acc[ni][q] = 0.0f;

        // ---- MMA1: A @ W1 ----
#pragma unroll
        for (int k0 = 0; k0 < 8; k0++) {
            const uint32_t ko = k0 * 32;
            uint32_t ah[4], al[4];
            ldsm4(ah, sAh + offA0 + ko);
            ldsm4(al, sAl + offA0 + ko);
#pragma unroll
            for (int p = 0; p < 4; p++) {
                uint32_t bh[4], bl[4];
                ldsm4(bh, sB1h + offB[p] + ko);
                ldsm4(bl, sB1l + offB[p] + ko);
                mma16816(acc[2 * p],     ah, bh[0], bh[1]);
                mma16816(acc[2 * p],     ah, bl[0], bl[1]);
                mma16816(acc[2 * p],     al, bh[0], bh[1]);
                mma16816(acc[2 * p + 1], ah, bh[2], bh[3]);
                mma16816(acc[2 * p + 1], ah, bl[2], bl[3]);
                mma16816(acc[2 * p + 1], al, bh[2], bh[3]);
            }
        }
        __syncthreads();

        // ---- epilogue1: t1 = ssp(acc + b1) -> bf16 hi/lo back into A buffers --
        {
            int r0 = wm + gid;
            int r1 = r0 + 8;
#pragma unroll
            for (int ni = 0; ni < 8; ni++) {
                int cb = wn + ni * 8 + tg * 2;
                float b0 = __ldg(bias1 + cb);
                float b1 = __ldg(bias1 + cb + 1);
                float* a4 = acc[ni];
                float v00 = sspf(a4[0] + b0), v01 = sspf(a4[1] + b1);
                float v10 = sspf(a4[2] + b0), v11 = sspf(a4[3] + b1);
                uint32_t h0 = packbf2(v00, v01);
                uint32_t h1 = packbf2(v10, v11);
                __nv_bfloat162* h0p = (__nv_bfloat162*)&h0;
                __nv_bfloat162* h1p = (__nv_bfloat162*)&h1;
                uint32_t l0 = packbf2(v00 - __bfloat162float(h0p->x), v01 - __bfloat162float(h0p->y));
                uint32_t l1 = packbf2(v10 - __bfloat162float(h1p->x), v11 - __bfloat162float(h1p->y));
                *(uint32_t*)(Ahs + r0 * MG_STRIDE + cb) = h0;
                *(uint32_t*)(Ahs + r1 * MG_STRIDE + cb) = h1;
                *(uint32_t*)(Als + r0 * MG_STRIDE + cb) = l0;
                *(uint32_t*)(Als + r1 * MG_STRIDE + cb) = l1;
            }
        }
        __syncthreads();

        // ---- MMA2: t1 @ W2 ----
#pragma unroll
        for (int ni = 0; ni < 8; ni++)
#pragma unroll
            for (int q = 0; q < 4; q++) acc[ni][q] = 0.0f;
#pragma unroll
        for (int k0 = 0; k0 < 8; k0++) {
            const uint32_t ko = k0 * 32;
            uint32_t ah[4], al[4];
            ldsm4(ah, sAh + offA0 + ko);
            ldsm4(al, sAl + offA0 + ko);
#pragma unroll
            for (int p = 0; p < 4; p++) {
                uint32_t bh[4], bl[4];
                ldsm4(bh, sB2h + offB[p] + ko);
                ldsm4(bl, sB2l + offB[p] + ko);
                mma16816(acc[2 * p],     ah, bh[0], bh[1]);
                mma16816(acc[2 * p],     ah, bl[0], bl[1]);
                mma16816(acc[2 * p],     al, bh[0], bh[1]);
                mma16816(acc[2 * p + 1], ah, bh[2], bh[3]);
                mma16816(acc[2 * p + 1], ah, bl[2], bl[3]);
                mma16816(acc[2 * p + 1], al, bh[2], bh[3]);
            }
        }

        // ---- epilogue2: + b2 (+res) -> C ----
        {
            int r0 = bm + wm + gid;
            int r1 = r0 + 8;
#pragma unroll
            for (int ni = 0; ni < 8; ni++) {
                int cb = wn + ni * 8 + tg * 2;
                float b0 = __ldg(bias2 + cb);
                float b1 = __ldg(bias2 + cb + 1);
                float* a4 = acc[ni];
                float v00 = a4[0] + b0, v01 = a4[1] + b1;
                float v10 = a4[2] + b0, v11 = a4[3] + b1;
                if (r0 < M) {
                    if (res) {
                        float2 rr = *(const float2*)(res + (size_t)r0 * 128 + cb);
                        v00 += rr.x; v01 += rr.y;
                    }
                    *(float2*)(C + (size_t)r0 * 128 + cb) = make_float2(v00, v01);
                }
                if (r1 < M) {
                    if (res) {
                        float2 rr = *(const float2*)(res + (size_t)r1 * 128 + cb);
                        v10 += rr.x; v11 += rr.y;
                    }
                    *(float2*)(C + (size_t)r1 * 128 + cb) = make_float2(v10, v11);
                }
            }
        }
        __syncthreads();
    }
}

// ---------------- merged preprocessing --------------------------------------
__global__ void prep_all(const float* __restrict__ lin_w, const float* __restrict__ mlp_w2,
                         const float* __restrict__ v1_w, const float* __restrict__ v2_w,
                         const float* __restrict__ u1_w, const float* __restrict__ fe_w2,
                         const float* __restrict__ u2_w,
                         const float* __restrict__ u1_b, const float* __restrict__ u2_b,
                         const float* __restrict__ mlp_w1, const float* __restrict__ mlp_b1) {
    int idx = blockIdx.x * blockDim.x + threadIdx.x;
    if (idx < 128) {
        g_u1bpad[idx] = (idx < 64) ? u1_b[idx] : 0.0f;
        g_u2bpad[idx] = (idx < 32) ? u2_b[idx] : 0.0f;
        g_bnacc[idx] = 0.0f;
    }
    if (idx < NN) g_nhist[idx] = 0;
    if (idx < 768) g_b1all[idx] = mlp_b1[(idx >> 7) * 128 + (idx & 127)];
    if (idx < NG_PAD * 768) {
        int k = idx / 768;
        int c = idx % 768;
        int l = c >> 7, nn2 = c & 127;
        g_m1all[idx] = (k < NGAUSS) ? mlp_w1[(size_t)l * NGAUSS * 128 + k * 128 + nn2] : 0.0f;
    }
    if (idx < TABROWS * NG_PAD) {
        int m = idx / NG_PAD;
        int g = idx % NG_PAD;
        float val = 0.0f;
        if (g < NGAUSS) {
            float d = (float)m * TAB_STEP;
            float off = (float)g * (6.0f / 49.0f);
            float tt = d - off;
            const float coeff = -0.5f / ((6.0f / 49.0f) * (6.0f / 49.0f));
            val = expf(coeff * tt * tt);
        }
        g_demb[idx] = val;
    }
    if (idx < 27 * 16384) {
        int slot = idx >> 14;
        int r = idx & 16383;
        int n = r >> 7;
        int k = r & 127;
        float a;
        if (slot < 24) {
            int l = slot >> 2, w = slot & 3;
            const float* src = (w == 0) ? lin_w : (w == 1) ? mlp_w2 : (w == 2) ? v1_w : v2_w;
            a = src[(size_t)l * 16384 + k * 128 + n];
        } else if (slot == 24) {
            a = (n < 64) ? u1_w[k * 64 + n] : 0.0f;
        } else if (slot == 25) {
            a = (k < 64) ? fe_w2[k * 128 + n] : 0.0f;
        } else {
            a = (k < 64 && n < 32) ? u2_w[k * 32 + n] : 0.0f;
        }
        __nv_bfloat16 hi = __float2bfloat16_rn(a);
        __nv_bfloat16 lo = __float2bfloat16_rn(a - __bfloat162float(hi));
        g_wthi[idx] = hi;
        g_wtlo[idx] = lo;
    }
}

// ---------------- fp16 pair-table pack ---------------------------------------
__global__ void pack_table() {
    int idx = blockIdx.x * blockDim.x + threadIdx.x;
    if (idx >= LL * TABM * 128) return;
    int c = idx & 127;
    int rest = idx >> 7;
    int i = rest % TABM;
    int l = rest / TABM;
    const float* tab = g_tables + (size_t)l * TABROWS * 128;
    float a = tab[(size_t)i * 128 + c];
    float b = tab[(size_t)(i + 1) * 128 + c];
    g_ptab[idx] = __floats2half2_rn(a, b);
}

// ---------------- edge geometry + per-destination histogram ------------------
__global__ void edge_geom_hist(const int* __restrict__ ei, const float* __restrict__ pos,
                               float* __restrict__ dist, int e_total) {
    int e = blockIdx.x * blockDim.x + threadIdx.x;
    if (e >= e_total) return;
    int r = ei[e];
    int c = ei[e_total + e];
    float dx = pos[r * 3 + 0] - pos[c * 3 + 0];
    float dy = pos[r * 3 + 1] - pos[c * 3 + 1];
    float dz = pos[r * 3 + 2] - pos[c * 3 + 2];
    float d = sqrtf(dx * dx + dy * dy + dz * dz);
    dist[e] = d;
    if (d < SKIP_D) atomicAdd(&g_nhist[c], 1);
}

__global__ void scan_nodes(int n) {
    __shared__ int part[256];
    int t = threadIdx.x;
    int chunk = (n + 255) / 256;
    int lo = t * chunk;
    int hi = min(lo + chunk, n);
    int s = 0;
    for (int i = lo; i < hi; i++) s += g_nhist[i];
    part[t] = s;
    __syncthreads();
    if (t == 0) {
        int acc = 0;
        for (int i = 0; i < 256; i++) { int c = part[i]; part[i] = acc; acc += c; }
    }
    __syncthreads();
    int acc = part[t];
    for (int i = lo; i < hi; i++) {
        int c = g_nhist[i];
        g_nstart[i] = acc;
        g_ncursor[i] = acc;
        acc += c;
    }
    if (hi == n) g_nstart[n] = acc;
}

__global__ void edge_build(const int* __restrict__ ei, const float* __restrict__ dist,
                           int e_total) {
    int e = blockIdx.x * blockDim.x + threadIdx.x;
    if (e >= e_total) return;
    float d = dist[e];
    if (d >= SKIP_D) return;
    int c = ei[e_total + e];
    int p = atomicAdd(&g_ncursor[c], 1);
    g_erow[p] = ei[e];
    g_efi[p] = d * TAB_INVSTEP;
}

// ---------------- SIMT fp32 SGEMM with f32x2 (small/odd shapes) -------------
__global__ void __launch_bounds__(256, 2) sgemm(
    const float* __restrict__ A, const float* __restrict__ B,
    const float* __restrict__ bias, const float* __restrict__ res,
    float* __restrict__ C, int M, int N, int K, int Kb, int act) {
    __shared__ float As[2][8][128];
    __shared__ float Bs[2][8][128];
    const int tid = threadIdx.x;
    const int bm = blockIdx.y * 128;
    const int bn = blockIdx.x * 128;
    const int tx = tid & 15;
    const int ty = tid >> 4;
    const int ar = tid >> 1;
    const int ak = (tid & 1) * 4;
    const int bk = tid >> 5;
    const int bn4 = (tid & 31) * 4;
    const int arow = bm + ar;
    const int bcol = bn + bn4;
    const int KT = (K + 7) >> 3;

    unsigned long long acc[8][4];
#pragma unroll
    for (int i = 0; i < 8; i++)
#pragma unroll
        for (int j = 0; j < 4; j++) acc[i][j] = 0ull;

    float4 pa = make_float4(0, 0, 0, 0);
    float4 pb = make_float4(0, 0, 0, 0);
    if (arow < M && ak < K) pa = *(const float4*)(A + (size_t)arow * K + ak);
    if (bk < Kb && bcol < N) pb = *(const float4*)(B + (size_t)bk * N + bcol);
    As[0][ak + 0][ar] = pa.x; As[0][ak + 1][ar] = pa.y;
    As[0][ak + 2][ar] = pa.z; As[0][ak + 3][ar] = pa.w;
    *(float4*)&Bs[0][bk][bn4] = pb;
    __syncthreads();

    for (int kt = 0; kt < KT; kt++) {
        const int s = kt & 1;
        if (kt + 1 < KT) {
            int k0 = (kt + 1) * 8;
            pa = make_float4(0, 0, 0, 0);
            pb = make_float4(0, 0, 0, 0);
            if (arow < M && (k0 + ak) < K) pa = *(const float4*)(A + (size_t)arow * K + k0 + ak);
            if ((k0 + bk) < Kb && bcol < N) pb = *(const float4*)(B + (size_t)(k0 + bk) * N + bcol);
        }
#pragma unroll
        for (int k = 0; k < 8; k++) {
            float a[8];
            *(float4*)&a[0] = *(const float4*)&As[s][k][ty * 8];
            *(float4*)&a[4] = *(const float4*)&As[s][k][ty * 8 + 4];
            ulonglong2 bl = *(const ulonglong2*)&Bs[s][k][tx * 8];
            ulonglong2 bh = *(const ulonglong2*)&Bs[s][k][tx * 8 + 4];
#pragma unroll
            for (int i = 0; i < 8; i++) {
                unsigned long long ai = bcast2(a[i]);
                ffma2(acc[i][0], ai, bl.x);
                ffma2(acc[i][1], ai, bl.y);
                ffma2(acc[i][2], ai, bh.x);
                ffma2(acc[i][3], ai, bh.y);
            }
        }
        if (kt + 1 < KT) {
            const int so = (kt + 1) & 1;
            As[so][ak + 0][ar] = pa.x; As[so][ak + 1][ar] = pa.y;
            As[so][ak + 2][ar] = pa.z; As[so][ak + 3][ar] = pa.w;
            *(float4*)&Bs[so][bk][bn4] = pb;
            __syncthreads();
        }
    }

    const int cbase = bn + tx * 8;
    float bv[8];
#pragma unroll
    for (int j = 0; j < 8; j++) bv[j] = (bias && (cbase + j) < N) ? bias[cbase + j] : 0.0f;

#pragma unroll
    for (int i = 0; i < 8; i++) {
        int row = bm + ty * 8 + i;
        if (row >= M) continue;
        float c[8];
        unpack2(acc[i][0], c[0], c[1]);
        unpack2(acc[i][1], c[2], c[3]);
        unpack2(acc[i][2], c[4], c[5]);
        unpack2(acc[i][3], c[6], c[7]);
#pragma unroll
        for (int j = 0; j < 8; j++) {
            float v = c[j] + bv[j];
            if (act == 1) v = fmaxf(v, 0.0f);
            else if (act == 2) v = sspf(v);
            c[j] = v;
        }
        if (res) {
#pragma unroll
            for (int j = 0; j < 8; j++)
                if ((cbase + j) < N) c[j] += res[(size_t)row * N + cbase + j];
        }
        if (cbase < N)
            *(float4*)(C + (size_t)row * N + cbase) = make_float4(c[0], c[1], c[2], c[3]);
        if (cbase + 4 < N)
            *(float4*)(C + (size_t)row * N + cbase + 4) = make_float4(c[4], c[5], c[6], c[7]);
    }
}

// ---------------- batchnorm ---------------------------------------------------
__global__ void bn_reduce(const float* __restrict__ h, int n) {
    __shared__ float ss[4][64];
    __shared__ float sq[4][64];
    int c = threadIdx.x & 63;
    int g = threadIdx.x >> 6;
    float s = 0.0f, q = 0.0f;
    for (int row = blockIdx.x * 4 + g; row < n; row += gridDim.x * 4) {
        float v = h[row * 64 + c];
        s += v;
        q += v * v;
    }
    ss[g][c] = s;
    sq[g][c] = q;
    __syncthreads();
    if (g == 0) {
        atomicAdd(&g_bnacc[c], ss[0][c] + ss[1][c] + ss[2][c] + ss[3][c]);
        atomicAdd(&g_bnacc[64 + c], sq[0][c] + sq[1][c] + sq[2][c] + sq[3][c]);
    }
}

__global__ void bn_apply(const float* __restrict__ h, float* __restrict__ hn,
                         const float* __restrict__ gamma, const float* __restrict__ beta,
                         int n) {
    int idx = blockIdx.x * blockDim.x + threadIdx.x;
    if (idx >= n * 128) return;
    int c = idx & 127;
    float y = 0.0f;
    if (c < 64) {
        float invN = 1.0f / (float)n;
        float mu = g_bnacc[c] * invN;
        float var = g_bnacc[64 + c] * invN - mu * mu;
        y = (h[(idx >> 7) * 64 + c] - mu) / sqrtf(var + 1e-5f) * gamma[c] + beta[c];
        y = fmaxf(y, 0.0f);
    }
    hn[idx] = y;
}

// ------- edge gather: one warp per destination node (fp16 table + fp16 vlin) --
__global__ void __launch_bounds__(256) edge_gather(
    const __half* __restrict__ vlinh, const __half2* __restrict__ ptab,
    float* __restrict__ agg, int n) {
    int node = (blockIdx.x * blockDim.x + threadIdx.x) >> 5;
    int lane = threadIdx.x & 31;
    if (node >= n) return;
    int j = g_nstart[node];
    int end = g_nstart[node + 1];

    float a0 = 0.0f, a1 = 0.0f, a2 = 0.0f, a3 = 0.0f;

    for (; j + 4 <= end; j += 4) {
        int ri[4]; float fi[4]; int ii[4]; float fr[4];
        uint4 tp[4]; uint2 hv[4];
#pragma unroll
        for (int q = 0; q < 4; q++) {
            ri[q] = __ldg(g_erow + j + q);
            fi[q] = __ldg(g_efi + j + q);
            ii[q] = (int)fi[q];
            fr[q] = fi[q] - (float)ii[q];
        }
#pragma unroll
        for (int q = 0; q < 4; q++) {
            tp[q] = __ldg(reinterpret_cast<const uint4*>(ptab + (size_t)ii[q] * 128) + lane);
            hv[q] = __ldg(reinterpret_cast<const uint2*>(vlinh + (size_t)ri[q] * 128) + lane);
        }
#pragma unroll
        for (int q = 0; q < 4; q++) {
            float2 p0 = __half22float2(*(__half2*)&tp[q].x);
            float2 p1 = __half22float2(*(__half2*)&tp[q].y);
            float2 p2 = __half22float2(*(__half2*)&tp[q].z);
            float2 p3 = __half22float2(*(__half2*)&tp[q].w);
            float2 v01 = __half22float2(*(__half2*)&hv[q].x);
            float2 v23 = __half22float2(*(__half2*)&hv[q].y);
            a0 = fmaf(v01.x, p0.x + fr[q] * (p0.y - p0.x), a0);
            a1 = fmaf(v01.y, p1.x + fr[q] * (p1.y - p1.x), a1);
            a2 = fmaf(v23.x, p2.x + fr[q] * (p2.y - p2.x), a2);
            a3 = fmaf(v23.y, p3.x + fr[q] * (p3.y - p3.x), a3);
        }
    }
    for (; j < end; j++) {
        int   r0 = __ldg(g_erow + j);
        float f0 = __ldg(g_efi + j);
        int   i0 = (int)f0;
        float fr0 = f0 - (float)i0;
        uint4 tq = __ldg(reinterpret_cast<const uint4*>(ptab + (size_t)i0 * 128) + lane);
        uint2 hq = __ldg(reinterpret_cast<const uint2*>(vlinh + (size_t)r0 * 128) + lane);
        float2 p0 = __half22float2(*(__half2*)&tq.x);
        float2 p1 = __half22float2(*(__half2*)&tq.y);
        float2 p2 = __half22float2(*(__half2*)&tq.z);
        float2 p3 = __half22float2(*(__half2*)&tq.w);
        float2 v01 = __half22float2(*(__half2*)&hq.x);
        float2 v23 = __half22float2(*(__half2*)&hq.y);
        a0 = fmaf(v01.x, p0.x + fr0 * (p0.y - p0.x), a0);
        a1 = fmaf(v01.y, p1.x + fr0 * (p1.y - p1.x), a1);
        a2 = fmaf(v23.x, p2.x + fr0 * (p2.y - p2.x), a2);
        a3 = fmaf(v23.y, p3.x + fr0 * (p3.y - p3.x), a3);
    }

    *(float4*)(agg + (size_t)node * 128 + lane * 4) = make_float4(a0, a1, a2, a3);
}

// ---------------- final per-graph scatter (batch sorted; s stride 128) --------
__global__ void node_out(const float* __restrict__ s, const int* __restrict__ batch,
                         float* __restrict__ out, int n) {
    int w = (blockIdx.x * blockDim.x + threadIdx.x) >> 5;
    int lane = threadIdx.x & 31;
    int start = w * 128;
    if (start >= n) return;
    int end = min(start + 128, n);
    int cur = __ldg(batch + start);
    float acc = 0.0f;
    for (int node = start; node < end; node++) {
        int b = __ldg(batch + node);
        if (b != cur) {
            atomicAdd(&out[cur * 32 + lane], acc);
            acc = 0.0f;
            cur = b;
        }
        acc += s[(size_t)node * 128 + lane];
    }
    atomicAdd(&out[cur * 32 + lane], acc);
}

// ---------------- host ---------------------------------------------------------
static float* sym(const void* s) {
    void* p = nullptr;
    cudaGetSymbolAddress(&p, s);
    return (float*)p;
}

extern "C" void kernel_launch(void* const* d_in, const int* in_sizes, int n_in,
                              void* d_out, int out_size) {
    const float* x       = (const float*)d_in[0];
    const float* pos     = (const float*)d_in[1];
    const int*   batch   = (const int*)d_in[2];
    const int*   ei      = (const int*)d_in[3];
    const float* fe_w1   = (const float*)d_in[4];
    const float* fe_b1   = (const float*)d_in[5];
    const float* bng     = (const float*)d_in[6];
    const float* bnb     = (const float*)d_in[7];
    const float* fe_w2   = (const float*)d_in[8];
    const float* fe_b2   = (const float*)d_in[9];
    const float* lin_w   = (const float*)d_in[10];
    const float* mlp_w1  = (const float*)d_in[11];
    const float* mlp_b1  = (const float*)d_in[12];
    const float* mlp_w2  = (const float*)d_in[13];
    const float* mlp_b2  = (const float*)d_in[14];
    const float* v1_w    = (const float*)d_in[15];
    const float* v1_b    = (const float*)d_in[16];
    const float* v2_w    = (const float*)d_in[17];
    const float* v2_b    = (const float*)d_in[18];
    const float* u1_w    = (const float*)d_in[19];
    const float* u1_b    = (const float*)d_in[20];
    const float* u2_w    = (const float*)d_in[21];
    const float* u2_b    = (const float*)d_in[22];
    float* out = (float*)d_out;

    int n = in_sizes[0] / 28;
    int e = in_sizes[3] / 2;

    float* p_h      = sym(g_h);
    float* p_hn     = sym(g_hn);
    float* p_v      = sym(g_v);
    __half* p_vlinh = (__half*)sym(g_vlinh);
    float* p_agg    = sym(g_agg);
    float* p_t1     = sym(g_t1);
    float* p_dist   = sym(g_dist);
    float* p_demb   = sym(g_demb);
    float* p_tabh   = sym(g_tabh);
    float* p_tables = sym(g_tables);
    __half2* p_ptab = (__half2*)sym(g_ptab);
    float* p_u1b    = sym(g_u1bpad);
    float* p_u2b    = sym(g_u2bpad);
    float* p_m1all  = sym(g_m1all);
    float* p_b1all  = sym(g_b1all);
    __nv_bfloat16* p_whi = (__nv_bfloat16*)sym(g_wthi);
    __nv_bfloat16* p_wlo = (__nv_bfloat16*)sym(g_wtlo);

    cudaFuncSetAttribute(mgemm, cudaFuncAttributeMaxDynamicSharedMemorySize, MG_SMEM);
    cudaFuncSetAttribute(fgemm, cudaFuncAttributeMaxDynamicSharedMemorySize, FG_SMEM);

    int sms = 148;
    cudaDeviceGetAttribute(&sms, cudaDevAttrMultiProcessorCount, 0);

    dim3 gemm_t(256);
    auto gemm_grid = [](int M, int N) {
        return dim3((unsigned)((N + 127) / 128), (unsigned)((M + 127) / 128));
    };
    int mtiles = (n + 63) / 64;
    int ftiles = (n + 127) / 128;
    int ttiles = (TABROWS + 63) / 64;
    int mgrid = mtiles < 2 * sms ? mtiles : 2 * sms;
    int fgrid = ftiles < sms ? ftiles : sms;
    int ggrid = (n + 7) / 8;

    // ---- phase 1: merged prep + batched table build + fp16 pair pack ----
    prep_all<<<(27 * 16384 + 255) / 256, 256>>>(lin_w, mlp_w2, v1_w, v2_w, u1_w,
                                                fe_w2, u2_w, u1_b, u2_b, mlp_w1, mlp_b1);
    sgemm<<<gemm_grid(TABROWS, 768), gemm_t>>>(p_demb, p_m1all, p_b1all, nullptr,
                                               p_tabh, TABROWS, 768, NG_PAD, NG_PAD, 2);
    mgemm<<<ttiles * LL, 256, MG_SMEM>>>(p_tabh, p_whi + (size_t)1 * 16384,
                                         p_wlo + (size_t)1 * 16384, mlp_b2, nullptr,
                                         p_tables, TABROWS, 3, ttiles, LL, 768, 0);
    pack_table<<<(LL * TABM * 128 + 255) / 256, 256>>>();

    // ---- phase 2: edge geometry + CSR-by-destination sort ----
    edge_geom_hist<<<(e + 255) / 256, 256>>>(ei, pos, p_dist, e);
    scan_nodes<<<1, 256>>>(n);
    edge_build<<<(e + 255) / 256, 256>>>(ei, p_dist, e);

    // ---- phase 3: feature embedding ----
    sgemm<<<gemm_grid(n, 64), gemm_t>>>(x, fe_w1, fe_b1, nullptr, p_h, n, 64, 28, 28, 0);
    bn_reduce<<<512, 256>>>(p_h, n);
    bn_apply<<<(n * 128 + 255) / 256, 256>>>(p_h, p_hn, bng, bnb, n);
    mgemm<<<mgrid, 256, MG_SMEM>>>(p_hn, p_whi + (size_t)25 * 16384,
                                   p_wlo + (size_t)25 * 16384, fe_b2, nullptr,
                                   p_v, n, 1, mtiles, 1, 128, 0);

    // ---- phase 4: interaction layers ----
    for (int l = 0; l < LL; l++) {
        const float* w1b = v1_b + (size_t)l * 128;
        const float* w2b = v2_b + (size_t)l * 128;
        __nv_bfloat16* lw_hi = p_whi + (size_t)(l * 4 + 0) * 16384;
        __nv_bfloat16* lw_lo = p_wlo + (size_t)(l * 4 + 0) * 16384;
        __nv_bfloat16* w1_hi = p_whi + (size_t)(l * 4 + 2) * 16384;
        __nv_bfloat16* w1_lo = p_wlo + (size_t)(l * 4 + 2) * 16384;
        __nv_bfloat16* w2_hi = p_whi + (size_t)(l * 4 + 3) * 16384;
        __nv_bfloat16* w2_lo = p_wlo + (size_t)(l * 4 + 3) * 16384;

        mgemm<<<mgrid, 256, MG_SMEM>>>(p_v, lw_hi, lw_lo, nullptr, nullptr,
                                       (float*)p_vlinh, n, 0, mtiles, 1, 128, 1);
        edge_gather<<<ggrid, 256>>>(p_vlinh, p_ptab + (size_t)l * TABM * 128,
                                    p_agg, n);
        fgemm<<<fgrid, 512, FG_SMEM>>>(p_agg, w1_hi, w1_lo, w2_hi, w2_lo,
                                       w1b, w2b, p_v, p_v, n, ftiles);
    }

    // ---- phase 5: readout ----
    fgemm<<<fgrid, 512, FG_SMEM>>>(p_v,
                                   p_whi + (size_t)24 * 16384, p_wlo + (size_t)24 * 16384,
                                   p_whi + (size_t)26 * 16384, p_wlo + (size_t)26 * 16384,
                                   p_u1b, p_u2b, nullptr, p_t1, n, ftiles);
    cudaMemsetAsync(out, 0, (size_t)out_size * sizeof(float));
    node_out<<<((n + 127) / 128 * 32 + 255) / 256, 256>>>(p_t1, batch, out, n);
}

// round 15
// speedup vs baseline: 1.3508x; 1.0649x over previous
#include <cuda_runtime.h>
#include <cuda_bf16.h>
#include <cuda_fp16.h>
#include <math.h>
#include <stdint.h>

// Problem constants
#define NN 50000
#define EE 800000
#define GG 512
#define LL 6
#define NGAUSS 50
#define NG_PAD 56
#define TABM 1024                  // table intervals over [0, 7]
#define TABROWS (TABM + 1)
#define TAB_MAX 7.0f
#define TAB_INVSTEP ((float)TABM / TAB_MAX)
#define TAB_STEP (TAB_MAX / (float)TABM)
#define SKIP_D 6.97f
#define LN2F 0.69314718055994530942f
#define PIF 3.14159265358979323846f

// ---------------- scratch (device globals; no allocation allowed) -------------
__device__ __align__(256) float g_h[NN * 64];
__device__ __align__(256) float g_hn[NN * 128];      // K=128 padded
__device__ __align__(256) float g_v[NN * 128];
__device__ __align__(256) __half g_vlinh[NN * 128];  // fp16 vlin
__device__ __align__(256) __half g_aggh[NN * 128];   // fp16 agg
__device__ __align__(256) float g_t1[NN * 128];
__device__ __align__(256) float g_dist[EE];
__device__ __align__(256) float g_demb[TABROWS * NG_PAD];
__device__ __align__(256) float g_tabh[TABROWS * 768];   // all 6 layers, N=768
__device__ __align__(256) float g_tables[LL * TABROWS * 128];
__device__ __align__(256) __half2 g_ptab[LL * TABM * 128];  // fp16 (T[i],T[i+1]) pairs
__device__ __align__(256) float g_bnacc[128];
__device__ __align__(256) float g_u1bpad[128];
__device__ __align__(256) float g_u2bpad[128];
__device__ __align__(256) float g_m1all[NG_PAD * 768];
__device__ __align__(256) float g_b1all[768];
// bf16 hi/lo split, pre-transposed weights [slot][n][k]
// slots 0..23: l*4 + {lin,mlp2,v1,v2}; 24: u1 (N-pad); 25: fe2 (K-pad); 26: u2 (N,K-pad)
__device__ __align__(256) __nv_bfloat16 g_wthi[27 * 128 * 128];
__device__ __align__(256) __nv_bfloat16 g_wtlo[27 * 128 * 128];
// CSR-by-destination edge sort; meta = (row:int, fi:float) packed
__device__ __align__(256) int   g_nhist[NN];
__device__ __align__(256) int   g_nstart[NN + 1];
__device__ __align__(256) int   g_ncursor[NN];
__device__ __align__(256) uint2 g_emeta[EE];

// ---------------- helpers ---------------------------------------------------
__device__ __forceinline__ float sspf(float x) {
    return fmaxf(x, 0.0f) + log1pf(expf(-fabsf(x))) - LN2F;
}
__device__ __forceinline__ unsigned long long bcast2(float x) {
    unsigned long long r;
    asm("mov.b64 %0, {%1, %1};" : "=l"(r) : "f"(x));
    return r;
}
__device__ __forceinline__ void ffma2(unsigned long long& d,
                                      unsigned long long a, unsigned long long b) {
    asm("fma.rn.f32x2 %0, %1, %2, %0;" : "+l"(d) : "l"(a), "l"(b));
}
__device__ __forceinline__ void unpack2(unsigned long long v, float& lo, float& hi) {
    asm("mov.b64 {%0, %1}, %2;" : "=f"(lo), "=f"(hi) : "l"(v));
}
__device__ __forceinline__ uint32_t smem_u32(const void* p) {
    uint32_t a;
    asm("{ .reg .u64 t; cvta.to.shared.u64 t, %1; cvt.u32.u64 %0, t; }" : "=r"(a) : "l"(p));
    return a;
}
__device__ __forceinline__ void mma16816(float* c, const uint32_t* a,
                                         uint32_t b0, uint32_t b1) {
    asm volatile(
        "mma.sync.aligned.m16n8k16.row.col.f32.bf16.bf16.f32 "
        "{%0,%1,%2,%3}, {%4,%5,%6,%7}, {%8,%9}, {%0,%1,%2,%3};"
        : "+f"(c[0]), "+f"(c[1]), "+f"(c[2]), "+f"(c[3])
        : "r"(a[0]), "r"(a[1]), "r"(a[2]), "r"(a[3]), "r"(b0), "r"(b1));
}
__device__ __forceinline__ void ldsm4(uint32_t* r, uint32_t addr) {
    asm volatile("ldmatrix.sync.aligned.m8n8.x4.shared.b16 {%0,%1,%2,%3}, [%4];"
        : "=r"(r[0]), "=r"(r[1]), "=r"(r[2]), "=r"(r[3]) : "r"(addr));
}
__device__ __forceinline__ uint32_t packbf2(float x, float y) {
    __nv_bfloat162 h = __float22bfloat162_rn(make_float2(x, y));
    return *(uint32_t*)&h;
}

#define MG_STRIDE 136   // bf16 per smem row (272B) — conflict-free ldmatrix
#define MG_A1 (64 * MG_STRIDE * 2)
#define MG_B1 (128 * MG_STRIDE * 2)
#define MG_SMEM (2 * MG_A1 + 2 * MG_B1)
// fgemm v2: A (128 rows, hi/lo) + W1 (hi/lo) + W2 (hi/lo), all 128x128
#define FG_A1 MG_B1
#define FG_SMEM (6 * FG_A1)

// ================= bf16x3 HMMA GEMM v3 (pipelined A prefetch) ================
// outh: store C as packed fp16 (act must be 0, no res).
__global__ void __launch_bounds__(256, 2) mgemm(
    const float* __restrict__ A, const __nv_bfloat16* __restrict__ Bhi,
    const __nv_bfloat16* __restrict__ Blo, const float* __restrict__ bias,
    const float* __restrict__ res, float* __restrict__ C, int M, int act,
    int tiles_per_mat, int nmats, int lda, int outh) {
    extern __shared__ char smem[];
    __nv_bfloat16* Ahs = (__nv_bfloat16*)(smem);
    __nv_bfloat16* Als = (__nv_bfloat16*)(smem + MG_A1);
    __nv_bfloat16* Bhs = (__nv_bfloat16*)(smem + 2 * MG_A1);
    __nv_bfloat16* Bls = (__nv_bfloat16*)(smem + 2 * MG_A1 + MG_B1);
    const uint32_t sb = smem_u32(smem);
    const uint32_t sAh = sb, sAl = sb + MG_A1;
    const uint32_t sBh = sb + 2 * MG_A1, sBl = sb + 2 * MG_A1 + MG_B1;

    const int t = threadIdx.x;
    const int lane = t & 31;
    const int w = t >> 5;
    const int wm = (w & 3) * 16;
    const int wn = (w >> 2) * 64;
    const int gid = lane >> 2;
    const int tg = lane & 3;

    const int arow_l = t >> 2;
    const int aseg = (t & 3) * 32;

    const int lrow = ((t >> 3) & 1) * 8 + (t & 7);
    const int lkb  = ((t >> 4) & 1) * 16;
    const uint32_t offA0 = (uint32_t)(wm + lrow) * 272 + lkb;
    const int brow = ((t >> 4) & 1) * 8 + (t & 7);
    const int bkb  = ((t >> 3) & 1) * 16;
    uint32_t offB[4];
#pragma unroll
    for (int p = 0; p < 4; p++) offB[p] = (uint32_t)(wn + p * 16 + brow) * 272 + bkb;

    const int total_tiles = tiles_per_mat * nmats;
    int cur_mat = -1;
    const float4 z4 = make_float4(0, 0, 0, 0);

    float4 pa[8];
    if (blockIdx.x < total_tiles) {
        int tl = blockIdx.x;
        int mat = (nmats == 1) ? 0 : (tl / tiles_per_mat);
        int lt  = (nmats == 1) ? tl : (tl % tiles_per_mat);
        int grow = lt * 64 + arow_l;
        bool valid = grow < M;
        const float4* ap = (const float4*)(A + (size_t)(valid ? grow : 0) * lda + mat * 128 + aseg);
#pragma unroll
        for (int c = 0; c < 8; c++) pa[c] = valid ? ap[c] : z4;
    }

    for (int tile = blockIdx.x; tile < total_tiles; tile += gridDim.x) {
        const int mat = (nmats == 1) ? 0 : (tile / tiles_per_mat);
        const int lt  = (nmats == 1) ? tile : (tile % tiles_per_mat);
        const int bm = lt * 64;

        if (mat != cur_mat) {
            cur_mat = mat;
            const __nv_bfloat16* bh = Bhi + (size_t)mat * 4 * 16384;
            const __nv_bfloat16* bl = Blo + (size_t)mat * 4 * 16384;
            int row = t >> 1, half = (t & 1) * 64;
            const uint4* bhp = (const uint4*)(bh + (size_t)row * 128 + half);
            const uint4* blp = (const uint4*)(bl + (size_t)row * 128 + half);
            __nv_bfloat16* dbh = Bhs + row * MG_STRIDE + half;
            __nv_bfloat16* dbl = Bls + row * MG_STRIDE + half;
#pragma unroll
            for (int c = 0; c < 8; c++) {
                *(uint4*)(dbh + c * 8) = bhp[c];
                *(uint4*)(dbl + c * 8) = blp[c];
            }
        }

        {
            __nv_bfloat16* ahp = Ahs + arow_l * MG_STRIDE + aseg;
            __nv_bfloat16* alp = Als + arow_l * MG_STRIDE + aseg;
#pragma unroll
            for (int c = 0; c < 8; c++) {
                float4 v = pa[c];
                uint32_t h0 = packbf2(v.x, v.y);
                uint32_t h1 = packbf2(v.z, v.w);
                __nv_bfloat162* h0p = (__nv_bfloat162*)&h0;
                __nv_bfloat162* h1p = (__nv_bfloat162*)&h1;
                uint32_t l0 = packbf2(v.x - __bfloat162float(h0p->x), v.y - __bfloat162float(h0p->y));
                uint32_t l1 = packbf2(v.z - __bfloat162float(h1p->x), v.w - __bfloat162float(h1p->y));
                *(uint2*)(ahp + c * 4) = make_uint2(h0, h1);
                *(uint2*)(alp + c * 4) = make_uint2(l0, l1);
            }
        }
        __syncthreads();

        {
            int ntile = tile + gridDim.x;
            if (ntile < total_tiles) {
                int nmat = (nmats == 1) ? 0 : (ntile / tiles_per_mat);
                int nlt  = (nmats == 1) ? ntile : (ntile % tiles_per_mat);
                int grow = nlt * 64 + arow_l;
                bool valid = grow < M;
                const float4* ap = (const float4*)(A + (size_t)(valid ? grow : 0) * lda + nmat * 128 + aseg);
#pragma unroll
                for (int c = 0; c < 8; c++) pa[c] = valid ? ap[c] : z4;
            }
        }

        float acc[8][4];
#pragma unroll
        for (int ni = 0; ni < 8; ni++)
#pragma unroll
            for (int q = 0; q < 4; q++) acc[ni][q] = 0.0f;

#pragma unroll
        for (int k0 = 0; k0 < 8; k0++) {
            const uint32_t ko = k0 * 32;
            uint32_t ah[4], al[4];
            ldsm4(ah, sAh + offA0 + ko);
            ldsm4(al, sAl + offA0 + ko);
#pragma unroll
            for (int p = 0; p < 4; p++) {
                uint32_t bh[4], bl[4];
                ldsm4(bh, sBh + offB[p] + ko);
                ldsm4(bl, sBl + offB[p] + ko);
                mma16816(acc[2 * p],     ah, bh[0], bh[1]);
                mma16816(acc[2 * p],     ah, bl[0], bl[1]);
                mma16816(acc[2 * p],     al, bh[0], bh[1]);
                mma16816(acc[2 * p + 1], ah, bh[2], bh[3]);
                mma16816(acc[2 * p + 1], ah, bl[2], bl[3]);
                mma16816(acc[2 * p + 1], al, bh[2], bh[3]);
            }
        }

        const float* mbias = bias ? (bias + (size_t)mat * 128) : nullptr;
        float* mC = C;
        if (nmats > 1) mC = C + (size_t)mat * (size_t)TABROWS * 128;
        {
            int r0 = bm + wm + gid;
            int r1 = r0 + 8;
            float sc0 = 1.0f, sc1 = 1.0f;
            if (act == 3) {
                sc0 = 0.5f * (cosf((float)r0 * TAB_STEP * (PIF / 6.0f)) + 1.0f);
                sc1 = 0.5f * (cosf((float)r1 * TAB_STEP * (PIF / 6.0f)) + 1.0f);
            }
#pragma unroll
            for (int ni = 0; ni < 8; ni++) {
                int cb = wn + ni * 8 + tg * 2;
                float b0 = mbias ? __ldg(mbias + cb) : 0.0f;
                float b1 = mbias ? __ldg(mbias + cb + 1) : 0.0f;
                float* a4 = acc[ni];
                float v00 = a4[0] + b0, v01 = a4[1] + b1;
                float v10 = a4[2] + b0, v11 = a4[3] + b1;
                if (act == 1) {
                    v00 = fmaxf(v00, 0.0f); v01 = fmaxf(v01, 0.0f);
                    v10 = fmaxf(v10, 0.0f); v11 = fmaxf(v11, 0.0f);
                } else if (act == 2) {
                    v00 = sspf(v00); v01 = sspf(v01); v10 = sspf(v10); v11 = sspf(v11);
                } else if (act == 3) {
                    v00 *= sc0; v01 *= sc0; v10 *= sc1; v11 *= sc1;
                }
                if (outh) {
                    __half* hC = (__half*)mC;
                    if (r0 < M)
                        *(__half2*)(hC + (size_t)r0 * 128 + cb) = __floats2half2_rn(v00, v01);
                    if (r1 < M)
                        *(__half2*)(hC + (size_t)r1 * 128 + cb) = __floats2half2_rn(v10, v11);
                } else {
                    if (r0 < M) {
                        if (res) {
                            float2 rr = *(const float2*)(res + (size_t)r0 * 128 + cb);
                            v00 += rr.x; v01 += rr.y;
                        }
                        *(float2*)(mC + (size_t)r0 * 128 + cb) = make_float2(v00, v01);
                    }
                    if (r1 < M) {
                        if (res) {
                            float2 rr = *(const float2*)(res + (size_t)r1 * 128 + cb);
                            v10 += rr.x; v11 += rr.y;
                        }
                        *(float2*)(mC + (size_t)r1 * 128 + cb) = make_float2(v10, v11);
                    }
                }
            }
        }
        __syncthreads();
    }
}

// ===== fused double-GEMM v2 (512 threads, M=128 tiles, 16 warps/SM) ==========
// inh: A is fp16 (stride 128 halves); else fp32 (stride 128 floats).
__global__ void __launch_bounds__(512, 1) fgemm(
    const void* __restrict__ Av,
    const __nv_bfloat16* __restrict__ B1hi, const __nv_bfloat16* __restrict__ B1lo,
    const __nv_bfloat16* __restrict__ B2hi, const __nv_bfloat16* __restrict__ B2lo,
    const float* __restrict__ bias1, const float* __restrict__ bias2,
    const float* __restrict__ res, float* __restrict__ C, int M, int tiles, int inh) {
    extern __shared__ char smem[];
    __nv_bfloat16* Ahs  = (__nv_bfloat16*)(smem);
    __nv_bfloat16* Als  = (__nv_bfloat16*)(smem + FG_A1);
    const uint32_t sb = smem_u32(smem);
    const uint32_t sAh = sb, sAl = sb + FG_A1;
    const uint32_t sB1h = sb + 2 * FG_A1, sB1l = sb + 3 * FG_A1;
    const uint32_t sB2h = sb + 4 * FG_A1, sB2l = sb + 5 * FG_A1;
    __nv_bfloat16* B1hs = (__nv_bfloat16*)(smem + 2 * FG_A1);
    __nv_bfloat16* B1ls = (__nv_bfloat16*)(smem + 3 * FG_A1);
    __nv_bfloat16* B2hs = (__nv_bfloat16*)(smem + 4 * FG_A1);
    __nv_bfloat16* B2ls = (__nv_bfloat16*)(smem + 5 * FG_A1);

    const int t = threadIdx.x;
    const int lane = t & 31;
    const int w = t >> 5;           // 0..15
    const int wm = (w >> 1) * 16;   // 8 M-slots of 16 rows
    const int wn = (w & 1) * 64;    // 2 N-halves
    const int gid = lane >> 2;
    const int tg = lane & 3;
    const int arow_l = t >> 2;      // 0..127
    const int aseg = (t & 3) * 32;
    const int lrow = ((lane >> 3) & 1) * 8 + (lane & 7);
    const int lkb  = ((lane >> 4) & 1) * 16;
    const uint32_t offA0 = (uint32_t)(wm + lrow) * 272 + lkb;
    const int brow = ((lane >> 4) & 1) * 8 + (lane & 7);
    const int bkb  = ((lane >> 3) & 1) * 16;
    uint32_t offB[4];
#pragma unroll
    for (int p = 0; p < 4; p++) offB[p] = (uint32_t)(wn + p * 16 + brow) * 272 + bkb;

    // stage both weight matrices once (512 threads: each does 32 cols/matrix)
    {
        const int srow = t >> 2, shalf = (t & 3) * 32;
        const uint4* b1h = (const uint4*)(B1hi + (size_t)srow * 128 + shalf);
        const uint4* b1l = (const uint4*)(B1lo + (size_t)srow * 128 + shalf);
        const uint4* b2h = (const uint4*)(B2hi + (size_t)srow * 128 + shalf);
        const uint4* b2l = (const uint4*)(B2lo + (size_t)srow * 128 + shalf);
        __nv_bfloat16* d1h = B1hs + srow * MG_STRIDE + shalf;
        __nv_bfloat16* d1l = B1ls + srow * MG_STRIDE + shalf;
        __nv_bfloat16* d2h = B2hs + srow * MG_STRIDE + shalf;
        __nv_bfloat16* d2l = B2ls + srow * MG_STRIDE + shalf;
#pragma unroll
        for (int c = 0; c < 4; c++) {
            *(uint4*)(d1h + c * 8) = b1h[c];
            *(uint4*)(d1l + c * 8) = b1l[c];
            *(uint4*)(d2h + c * 8) = b2h[c];
            *(uint4*)(d2l + c * 8) = b2l[c];
        }
    }

    const float4 z4 = make_float4(0, 0, 0, 0);
    const float* Af = (const float*)Av;
    const __half* Ah16 = (const __half*)Av;

    float4 pa[8];
    auto loadA = [&](int tl) {
        int grow = tl * 128 + arow_l;
        bool valid = grow < M;
        if (inh) {
            const uint4* ap = (const uint4*)(Ah16 + (size_t)(valid ? grow : 0) * 128 + aseg);
#pragma unroll
            for (int c = 0; c < 4; c++) {
                if (valid) {
                    uint4 q = __ldg(ap + c);
                    float2 f0 = __half22float2(*(__half2*)&q.x);
                    float2 f1 = __half22float2(*(__half2*)&q.y);
                    float2 f2 = __half22float2(*(__half2*)&q.z);
                    float2 f3 = __half22float2(*(__half2*)&q.w);
                    pa[2 * c]     = make_float4(f0.x, f0.y, f1.x, f1.y);
                    pa[2 * c + 1] = make_float4(f2.x, f2.y, f3.x, f3.y);
                } else {
                    pa[2 * c] = z4;
                    pa[2 * c + 1] = z4;
                }
            }
        } else {
            const float4* ap = (const float4*)(Af + (size_t)(valid ? grow : 0) * 128 + aseg);
#pragma unroll
            for (int c = 0; c < 8; c++) pa[c] = valid ? ap[c] : z4;
        }
    };

    if (blockIdx.x < tiles) loadA(blockIdx.x);

    for (int tile = blockIdx.x; tile < tiles; tile += gridDim.x) {
        const int bm = tile * 128;

        {
            __nv_bfloat16* ahp = Ahs + arow_l * MG_STRIDE + aseg;
            __nv_bfloat16* alp = Als + arow_l * MG_STRIDE + aseg;
#pragma unroll
            for (int c = 0; c < 8; c++) {
                float4 v = pa[c];
                uint32_t h0 = packbf2(v.x, v.y);
                uint32_t h1 = packbf2(v.z, v.w);
                __nv_bfloat162* h0p = (__nv_bfloat162*)&h0;
                __nv_bfloat162* h1p = (__nv_bfloat162*)&h1;
                uint32_t l0 = packbf2(v.x - __bfloat162float(h0p->x), v.y - __bfloat162float(h0p->y));
                uint32_t l1 = packbf2(v.z - __bfloat162float(h1p->x), v.w - __bfloat162float(h1p->y));
                *(uint2*)(ahp + c * 4) = make_uint2(h0, h1);
                *(uint2*)(alp + c * 4) = make_uint2(l0, l1);
            }
        }
        __syncthreads();

        {
            int ntile = tile + gridDim.x;
            if (ntile < tiles) loadA(ntile);
        }

        float acc[8][4];
#pragma unroll
        for (int ni = 0; ni < 8; ni++)
#pragma unroll
            for (int q = 0; q < 4; q++) acc[ni][q] = 0.0f;

        // ---- MMA1: A @ W1 ----
#pragma unroll
        for (int k0 = 0; k0 < 8; k0++) {
            const uint32_t ko = k0 * 32;
            uint32_t ah[4], al[4];
            ldsm4(ah, sAh + offA0 + ko);
            ldsm4(al, sAl + offA0 + ko);
#pragma unroll
            for (int p = 0; p < 4; p++) {
                uint32_t bh[4], bl[4];
                ldsm4(bh, sB1h + offB[p] + ko);
                ldsm4(bl, sB1l + offB[p] + ko);
                mma16816(acc[2 * p],     ah, bh[0], bh[1]);
                mma16816(acc[2 * p],     ah, bl[0], bl[1]);
                mma16816(acc[2 * p],     al, bh[0], bh[1]);
                mma16816(acc[2 * p + 1], ah, bh[2], bh[3]);
                mma16816(acc[2 * p + 1], ah, bl[2], bl[3]);
                mma16816(acc[2 * p + 1], al, bh[2], bh[3]);
            }
        }
        __syncthreads();

        // ---- epilogue1: t1 = ssp(acc + b1) -> bf16 hi/lo back into A buffers --
        {
            int r0 = wm + gid;
            int r1 = r0 + 8;
#pragma unroll
            for (int ni = 0; ni < 8; ni++) {
                int cb = wn + ni * 8 + tg * 2;
                float b0 = __ldg(bias1 + cb);
                float b1 = __ldg(bias1 + cb + 1);
                float* a4 = acc[ni];
                float v00 = sspf(a4[0] + b0), v01 = sspf(a4[1] + b1);
                float v10 = sspf(a4[2] + b0), v11 = sspf(a4[3] + b1);
                uint32_t h0 = packbf2(v00, v01);
                uint32_t h1 = packbf2(v10, v11);
                __nv_bfloat162* h0p = (__nv_bfloat162*)&h0;
                __nv_bfloat162* h1p = (__nv_bfloat162*)&h1;
                uint32_t l0 = packbf2(v00 - __bfloat162float(h0p->x), v01 - __bfloat162float(h0p->y));
                uint32_t l1 = packbf2(v10 - __bfloat162float(h1p->x), v11 - __bfloat162float(h1p->y));
                *(uint32_t*)(Ahs + r0 * MG_STRIDE + cb) = h0;
                *(uint32_t*)(Ahs + r1 * MG_STRIDE + cb) = h1;
                *(uint32_t*)(Als + r0 * MG_STRIDE + cb) = l0;
                *(uint32_t*)(Als + r1 * MG_STRIDE + cb) = l1;
            }
        }
        __syncthreads();

        // ---- MMA2: t1 @ W2 ----
#pragma unroll
        for (int ni = 0; ni < 8; ni++)
#pragma unroll
            for (int q = 0; q < 4; q++) acc[ni][q] = 0.0f;
#pragma unroll
        for (int k0 = 0; k0 < 8; k0++) {
            const uint32_t ko = k0 * 32;
            uint32_t ah[4], al[4];
            ldsm4(ah, sAh + offA0 + ko);
            ldsm4(al, sAl + offA0 + ko);
#pragma unroll
            for (int p = 0; p < 4; p++) {
                uint32_t bh[4], bl[4];
                ldsm4(bh, sB2h + offB[p] + ko);
                ldsm4(bl, sB2l + offB[p] + ko);
                mma16816(acc[2 * p],     ah, bh[0], bh[1]);
                mma16816(acc[2 * p],     ah, bl[0], bl[1]);
                mma16816(acc[2 * p],     al, bh[0], bh[1]);
                mma16816(acc[2 * p + 1], ah, bh[2], bh[3]);
                mma16816(acc[2 * p + 1], ah, bl[2], bl[3]);
                mma16816(acc[2 * p + 1], al, bh[2], bh[3]);
            }
        }

        // ---- epilogue2: + b2 (+res) -> C ----
        {
            int r0 = bm + wm + gid;
            int r1 = r0 + 8;
#pragma unroll
            for (int ni = 0; ni < 8; ni++) {
                int cb = wn + ni * 8 + tg * 2;
                float b0 = __ldg(bias2 + cb);
                float b1 = __ldg(bias2 + cb + 1);
                float* a4 = acc[ni];
                float v00 = a4[0] + b0, v01 = a4[1] + b1;
                float v10 = a4[2] + b0, v11 = a4[3] + b1;
                if (r0 < M) {
                    if (res) {
                        float2 rr = *(const float2*)(res + (size_t)r0 * 128 + cb);
                        v00 += rr.x; v01 += rr.y;
                    }
                    *(float2*)(C + (size_t)r0 * 128 + cb) = make_float2(v00, v01);
                }
                if (r1 < M) {
                    if (res) {
                        float2 rr = *(const float2*)(res + (size_t)r1 * 128 + cb);
                        v10 += rr.x; v11 += rr.y;
                    }
                    *(float2*)(C + (size_t)r1 * 128 + cb) = make_float2(v10, v11);
                }
            }
        }
        __syncthreads();
    }
}

// ---------------- merged preprocessing --------------------------------------
__global__ void prep_all(const float* __restrict__ lin_w, const float* __restrict__ mlp_w2,
                         const float* __restrict__ v1_w, const float* __restrict__ v2_w,
                         const float* __restrict__ u1_w, const float* __restrict__ fe_w2,
                         const float* __restrict__ u2_w,
                         const float* __restrict__ u1_b, const float* __restrict__ u2_b,
                         const float* __restrict__ mlp_w1, const float* __restrict__ mlp_b1) {
    int idx = blockIdx.x * blockDim.x + threadIdx.x;
    if (idx < 128) {
        g_u1bpad[idx] = (idx < 64) ? u1_b[idx] : 0.0f;
        g_u2bpad[idx] = (idx < 32) ? u2_b[idx] : 0.0f;
        g_bnacc[idx] = 0.0f;
    }
    if (idx < NN) g_nhist[idx] = 0;
    if (idx < 768) g_b1all[idx] = mlp_b1[(idx >> 7) * 128 + (idx & 127)];
    if (idx < NG_PAD * 768) {
        int k = idx / 768;
        int c = idx % 768;
        int l = c >> 7, nn2 = c & 127;
        g_m1all[idx] = (k < NGAUSS) ? mlp_w1[(size_t)l * NGAUSS * 128 + k * 128 + nn2] : 0.0f;
    }
    if (idx < TABROWS * NG_PAD) {
        int m = idx / NG_PAD;
        int g = idx % NG_PAD;
        float val = 0.0f;
        if (g < NGAUSS) {
            float d = (float)m * TAB_STEP;
            float off = (float)g * (6.0f / 49.0f);
            float tt = d - off;
            const float coeff = -0.5f / ((6.0f / 49.0f) * (6.0f / 49.0f));
            val = expf(coeff * tt * tt);
        }
        g_demb[idx] = val;
    }
    if (idx < 27 * 16384) {
        int slot = idx >> 14;
        int r = idx & 16383;
        int n = r >> 7;
        int k = r & 127;
        float a;
        if (slot < 24) {
            int l = slot >> 2, w = slot & 3;
            const float* src = (w == 0) ? lin_w : (w == 1) ? mlp_w2 : (w == 2) ? v1_w : v2_w;
            a = src[(size_t)l * 16384 + k * 128 + n];
        } else if (slot == 24) {
            a = (n < 64) ? u1_w[k * 64 + n] : 0.0f;
        } else if (slot == 25) {
            a = (k < 64) ? fe_w2[k * 128 + n] : 0.0f;
        } else {
            a = (k < 64 && n < 32) ? u2_w[k * 32 + n] : 0.0f;
        }
        __nv_bfloat16 hi = __float2bfloat16_rn(a);
        __nv_bfloat16 lo = __float2bfloat16_rn(a - __bfloat162float(hi));
        g_wthi[idx] = hi;
        g_wtlo[idx] = lo;
    }
}

// ---------------- fp16 pair-table pack ---------------------------------------
__global__ void pack_table() {
    int idx = blockIdx.x * blockDim.x + threadIdx.x;
    if (idx >= LL * TABM * 128) return;
    int c = idx & 127;
    int rest = idx >> 7;
    int i = rest % TABM;
    int l = rest / TABM;
    const float* tab = g_tables + (size_t)l * TABROWS * 128;
    float a = tab[(size_t)i * 128 + c];
    float b = tab[(size_t)(i + 1) * 128 + c];
    g_ptab[idx] = __floats2half2_rn(a, b);
}

// ---------------- edge geometry + per-destination histogram ------------------
__global__ void edge_geom_hist(const int* __restrict__ ei, const float* __restrict__ pos,
                               float* __restrict__ dist, int e_total) {
    int e = blockIdx.x * blockDim.x + threadIdx.x;
    if (e >= e_total) return;
    int r = ei[e];
    int c = ei[e_total + e];
    float dx = pos[r * 3 + 0] - pos[c * 3 + 0];
    float dy = pos[r * 3 + 1] - pos[c * 3 + 1];
    float dz = pos[r * 3 + 2] - pos[c * 3 + 2];
    float d = sqrtf(dx * dx + dy * dy + dz * dz);
    dist[e] = d;
    if (d < SKIP_D) atomicAdd(&g_nhist[c], 1);
}

__global__ void scan_nodes(int n) {
    __shared__ int part[256];
    int t = threadIdx.x;
    int chunk = (n + 255) / 256;
    int lo = t * chunk;
    int hi = min(lo + chunk, n);
    int s = 0;
    for (int i = lo; i < hi; i++) s += g_nhist[i];
    part[t] = s;
    __syncthreads();
    if (t == 0) {
        int acc = 0;
        for (int i = 0; i < 256; i++) { int c = part[i]; part[i] = acc; acc += c; }
    }
    __syncthreads();
    int acc = part[t];
    for (int i = lo; i < hi; i++) {
        int c = g_nhist[i];
        g_nstart[i] = acc;
        g_ncursor[i] = acc;
        acc += c;
    }
    if (hi == n) g_nstart[n] = acc;
}

__global__ void edge_build(const int* __restrict__ ei, const float* __restrict__ dist,
                           int e_total) {
    int e = blockIdx.x * blockDim.x + threadIdx.x;
    if (e >= e_total) return;
    float d = dist[e];
    if (d >= SKIP_D) return;
    int c = ei[e_total + e];
    int p = atomicAdd(&g_ncursor[c], 1);
    float fi = d * TAB_INVSTEP;
    g_emeta[p] = make_uint2((uint32_t)ei[e], __float_as_uint(fi));
}

// ---------------- SIMT fp32 SGEMM with f32x2 (small/odd shapes) -------------
__global__ void __launch_bounds__(256, 2) sgemm(
    const float* __restrict__ A, const float* __restrict__ B,
    const float* __restrict__ bias, const float* __restrict__ res,
    float* __restrict__ C, int M, int N, int K, int Kb, int act) {
    __shared__ float As[2][8][128];
    __shared__ float Bs[2][8][128];
    const int tid = threadIdx.x;
    const int bm = blockIdx.y * 128;
    const int bn = blockIdx.x * 128;
    const int tx = tid & 15;
    const int ty = tid >> 4;
    const int ar = tid >> 1;
    const int ak = (tid & 1) * 4;
    const int bk = tid >> 5;
    const int bn4 = (tid & 31) * 4;
    const int arow = bm + ar;
    const int bcol = bn + bn4;
    const int KT = (K + 7) >> 3;

    unsigned long long acc[8][4];
#pragma unroll
    for (int i = 0; i < 8; i++)
#pragma unroll
        for (int j = 0; j < 4; j++) acc[i][j] = 0ull;

    float4 pa = make_float4(0, 0, 0, 0);
    float4 pb = make_float4(0, 0, 0, 0);
    if (arow < M && ak < K) pa = *(const float4*)(A + (size_t)arow * K + ak);
    if (bk < Kb && bcol < N) pb = *(const float4*)(B + (size_t)bk * N + bcol);
    As[0][ak + 0][ar] = pa.x; As[0][ak + 1][ar] = pa.y;
    As[0][ak + 2][ar] = pa.z; As[0][ak + 3][ar] = pa.w;
    *(float4*)&Bs[0][bk][bn4] = pb;
    __syncthreads();

    for (int kt = 0; kt < KT; kt++) {
        const int s = kt & 1;
        if (kt + 1 < KT) {
            int k0 = (kt + 1) * 8;
            pa = make_float4(0, 0, 0, 0);
            pb = make_float4(0, 0, 0, 0);
            if (arow < M && (k0 + ak) < K) pa = *(const float4*)(A + (size_t)arow * K + k0 + ak);
            if ((k0 + bk) < Kb && bcol < N) pb = *(const float4*)(B + (size_t)(k0 + bk) * N + bcol);
        }
#pragma unroll
        for (int k = 0; k < 8; k++) {
            float a[8];
            *(float4*)&a[0] = *(const float4*)&As[s][k][ty * 8];
            *(float4*)&a[4] = *(const float4*)&As[s][k][ty * 8 + 4];
            ulonglong2 bl = *(const ulonglong2*)&Bs[s][k][tx * 8];
            ulonglong2 bh = *(const ulonglong2*)&Bs[s][k][tx * 8 + 4];
#pragma unroll
            for (int i = 0; i < 8; i++) {
                unsigned long long ai = bcast2(a[i]);
                ffma2(acc[i][0], ai, bl.x);
                ffma2(acc[i][1], ai, bl.y);
                ffma2(acc[i][2], ai, bh.x);
                ffma2(acc[i][3], ai, bh.y);
            }
        }
        if (kt + 1 < KT) {
            const int so = (kt + 1) & 1;
            As[so][ak + 0][ar] = pa.x; As[so][ak + 1][ar] = pa.y;
            As[so][ak + 2][ar] = pa.z; As[so][ak + 3][ar] = pa.w;
            *(float4*)&Bs[so][bk][bn4] = pb;
            __syncthreads();
        }
    }

    const int cbase = bn + tx * 8;
    float bv[8];
#pragma unroll
    for (int j = 0; j < 8; j++) bv[j] = (bias && (cbase + j) < N) ? bias[cbase + j] : 0.0f;

#pragma unroll
    for (int i = 0; i < 8; i++) {
        int row = bm + ty * 8 + i;
        if (row >= M) continue;
        float c[8];
        unpack2(acc[i][0], c[0], c[1]);
        unpack2(acc[i][1], c[2], c[3]);
        unpack2(acc[i][2], c[4], c[5]);
        unpack2(acc[i][3], c[6], c[7]);
#pragma unroll
        for (int j = 0; j < 8; j++) {
            float v = c[j] + bv[j];
            if (act == 1) v = fmaxf(v, 0.0f);
            else if (act == 2) v = sspf(v);
            c[j] = v;
        }
        if (res) {
#pragma unroll
            for (int j = 0; j < 8; j++)
                if ((cbase + j) < N) c[j] += res[(size_t)row * N + cbase + j];
        }
        if (cbase < N)
            *(float4*)(C + (size_t)row * N + cbase) = make_float4(c[0], c[1], c[2], c[3]);
        if (cbase + 4 < N)
            *(float4*)(C + (size_t)row * N + cbase + 4) = make_float4(c[4], c[5], c[6], c[7]);
    }
}

// ---------------- batchnorm ---------------------------------------------------
__global__ void bn_reduce(const float* __restrict__ h, int n) {
    __shared__ float ss[4][64];
    __shared__ float sq[4][64];
    int c = threadIdx.x & 63;
    int g = threadIdx.x >> 6;
    float s = 0.0f, q = 0.0f;
    for (int row = blockIdx.x * 4 + g; row < n; row += gridDim.x * 4) {
        float v = h[row * 64 + c];
        s += v;
        q += v * v;
    }
    ss[g][c] = s;
    sq[g][c] = q;
    __syncthreads();
    if (g == 0) {
        atomicAdd(&g_bnacc[c], ss[0][c] + ss[1][c] + ss[2][c] + ss[3][c]);
        atomicAdd(&g_bnacc[64 + c], sq[0][c] + sq[1][c] + sq[2][c] + sq[3][c]);
    }
}

__global__ void bn_apply(const float* __restrict__ h, float* __restrict__ hn,
                         const float* __restrict__ gamma, const float* __restrict__ beta,
                         int n) {
    int idx = blockIdx.x * blockDim.x + threadIdx.x;
    if (idx >= n * 128) return;
    int c = idx & 127;
    float y = 0.0f;
    if (c < 64) {
        float invN = 1.0f / (float)n;
        float mu = g_bnacc[c] * invN;
        float var = g_bnacc[64 + c] * invN - mu * mu;
        y = (h[(idx >> 7) * 64 + c] - mu) / sqrtf(var + 1e-5f) * gamma[c] + beta[c];
        y = fmaxf(y, 0.0f);
    }
    hn[idx] = y;
}

// --- edge gather: warp/node (fp16 table + fp16 vlin + packed meta + fp16 out) -
__global__ void __launch_bounds__(256) edge_gather(
    const __half* __restrict__ vlinh, const __half2* __restrict__ ptab,
    __half* __restrict__ aggh, int n) {
    int node = (blockIdx.x * blockDim.x + threadIdx.x) >> 5;
    int lane = threadIdx.x & 31;
    if (node >= n) return;
    int j = g_nstart[node];
    int end = g_nstart[node + 1];

    float a0 = 0.0f, a1 = 0.0f, a2 = 0.0f, a3 = 0.0f;

    for (; j + 4 <= end; j += 4) {
        uint2 mt[4]; int ii[4]; float fr[4];
        uint4 tp[4]; uint2 hv[4];
#pragma unroll
        for (int q = 0; q < 4; q++) {
            mt[q] = __ldg(g_emeta + j + q);
            float fi = __uint_as_float(mt[q].y);
            ii[q] = (int)fi;
            fr[q] = fi - (float)ii[q];
        }
#pragma unroll
        for (int q = 0; q < 4; q++) {
            tp[q] = __ldg(reinterpret_cast<const uint4*>(ptab + (size_t)ii[q] * 128) + lane);
            hv[q] = __ldg(reinterpret_cast<const uint2*>(vlinh + (size_t)mt[q].x * 128) + lane);
        }
#pragma unroll
        for (int q = 0; q < 4; q++) {
            float2 p0 = __half22float2(*(__half2*)&tp[q].x);
            float2 p1 = __half22float2(*(__half2*)&tp[q].y);
            float2 p2 = __half22float2(*(__half2*)&tp[q].z);
            float2 p3 = __half22float2(*(__half2*)&tp[q].w);
            float2 v01 = __half22float2(*(__half2*)&hv[q].x);
            float2 v23 = __half22float2(*(__half2*)&hv[q].y);
            a0 = fmaf(v01.x, p0.x + fr[q] * (p0.y - p0.x), a0);
            a1 = fmaf(v01.y, p1.x + fr[q] * (p1.y - p1.x), a1);
            a2 = fmaf(v23.x, p2.x + fr[q] * (p2.y - p2.x), a2);
            a3 = fmaf(v23.y, p3.x + fr[q] * (p3.y - p3.x), a3);
        }
    }
    for (; j < end; j++) {
        uint2 mt = __ldg(g_emeta + j);
        float fi = __uint_as_float(mt.y);
        int   i0 = (int)fi;
        float fr0 = fi - (float)i0;
        uint4 tq = __ldg(reinterpret_cast<const uint4*>(ptab + (size_t)i0 * 128) + lane);
        uint2 hq = __ldg(reinterpret_cast<const uint2*>(vlinh + (size_t)mt.x * 128) + lane);
        float2 p0 = __half22float2(*(__half2*)&tq.x);
        float2 p1 = __half22float2(*(__half2*)&tq.y);
        float2 p2 = __half22float2(*(__half2*)&tq.z);
        float2 p3 = __half22float2(*(__half2*)&tq.w);
        float2 v01 = __half22float2(*(__half2*)&hq.x);
        float2 v23 = __half22float2(*(__half2*)&hq.y);
        a0 = fmaf(v01.x, p0.x + fr0 * (p0.y - p0.x), a0);
        a1 = fmaf(v01.y, p1.x + fr0 * (p1.y - p1.x), a1);
        a2 = fmaf(v23.x, p2.x + fr0 * (p2.y - p2.x), a2);
        a3 = fmaf(v23.y, p3.x + fr0 * (p3.y - p3.x), a3);
    }

    uint2 outp;
    outp.x = *(uint32_t*)&(*(__half2*)&outp.x = __floats2half2_rn(a0, a1), outp.x);
    __half2 o01 = __floats2half2_rn(a0, a1);
    __half2 o23 = __floats2half2_rn(a2, a3);
    uint2 ov = make_uint2(*(uint32_t*)&o01, *(uint32_t*)&o23);
    *(uint2*)(aggh + (size_t)node * 128 + lane * 4) = ov;
}

// ---------------- final per-graph scatter (batch sorted; s stride 128) --------
__global__ void node_out(const float* __restrict__ s, const int* __restrict__ batch,
                         float* __restrict__ out, int n) {
    int w = (blockIdx.x * blockDim.x + threadIdx.x) >> 5;
    int lane = threadIdx.x & 31;
    int start = w * 128;
    if (start >= n) return;
    int end = min(start + 128, n);
    int cur = __ldg(batch + start);
    float acc = 0.0f;
    for (int node = start; node < end; node++) {
        int b = __ldg(batch + node);
        if (b != cur) {
            atomicAdd(&out[cur * 32 + lane], acc);
            acc = 0.0f;
            cur = b;
        }
        acc += s[(size_t)node * 128 + lane];
    }
    atomicAdd(&out[cur * 32 + lane], acc);
}

// ---------------- host ---------------------------------------------------------
static float* sym(const void* s) {
    void* p = nullptr;
    cudaGetSymbolAddress(&p, s);
    return (float*)p;
}

extern "C" void kernel_launch(void* const* d_in, const int* in_sizes, int n_in,
                              void* d_out, int out_size) {
    const float* x       = (const float*)d_in[0];
    const float* pos     = (const float*)d_in[1];
    const int*   batch   = (const int*)d_in[2];
    const int*   ei      = (const int*)d_in[3];
    const float* fe_w1   = (const float*)d_in[4];
    const float* fe_b1   = (const float*)d_in[5];
    const float* bng     = (const float*)d_in[6];
    const float* bnb     = (const float*)d_in[7];
    const float* fe_w2   = (const float*)d_in[8];
    const float* fe_b2   = (const float*)d_in[9];
    const float* lin_w   = (const float*)d_in[10];
    const float* mlp_w1  = (const float*)d_in[11];
    const float* mlp_b1  = (const float*)d_in[12];
    const float* mlp_w2  = (const float*)d_in[13];
    const float* mlp_b2  = (const float*)d_in[14];
    const float* v1_w    = (const float*)d_in[15];
    const float* v1_b    = (const float*)d_in[16];
    const float* v2_w    = (const float*)d_in[17];
    const float* v2_b    = (const float*)d_in[18];
    const float* u1_w    = (const float*)d_in[19];
    const float* u1_b    = (const float*)d_in[20];
    const float* u2_w    = (const float*)d_in[21];
    const float* u2_b    = (const float*)d_in[22];
    float* out = (float*)d_out;

    int n = in_sizes[0] / 28;
    int e = in_sizes[3] / 2;

    float* p_h      = sym(g_h);
    float* p_hn     = sym(g_hn);
    float* p_v      = sym(g_v);
    __half* p_vlinh = (__half*)sym(g_vlinh);
    __half* p_aggh  = (__half*)sym(g_aggh);
    float* p_t1     = sym(g_t1);
    float* p_dist   = sym(g_dist);
    float* p_demb   = sym(g_demb);
    float* p_tabh   = sym(g_tabh);
    float* p_tables = sym(g_tables);
    __half2* p_ptab = (__half2*)sym(g_ptab);
    float* p_u1b    = sym(g_u1bpad);
    float* p_u2b    = sym(g_u2bpad);
    float* p_m1all  = sym(g_m1all);
    float* p_b1all  = sym(g_b1all);
    __nv_bfloat16* p_whi = (__nv_bfloat16*)sym(g_wthi);
    __nv_bfloat16* p_wlo = (__nv_bfloat16*)sym(g_wtlo);

    cudaFuncSetAttribute(mgemm, cudaFuncAttributeMaxDynamicSharedMemorySize, MG_SMEM);
    cudaFuncSetAttribute(fgemm, cudaFuncAttributeMaxDynamicSharedMemorySize, FG_SMEM);

    int sms = 148;
    cudaDeviceGetAttribute(&sms, cudaDevAttrMultiProcessorCount, 0);

    dim3 gemm_t(256);
    auto gemm_grid = [](int M, int N) {
        return dim3((unsigned)((N + 127) / 128), (unsigned)((M + 127) / 128));
    };
    int mtiles = (n + 63) / 64;
    int ftiles = (n + 127) / 128;
    int ttiles = (TABROWS + 63) / 64;
    int mgrid = mtiles < 2 * sms ? mtiles : 2 * sms;
    int fgrid = ftiles < sms ? ftiles : sms;
    int ggrid = (n + 7) / 8;

    // ---- phase 1: merged prep + batched table build + fp16 pair pack ----
    prep_all<<<(27 * 16384 + 255) / 256, 256>>>(lin_w, mlp_w2, v1_w, v2_w, u1_w,
                                                fe_w2, u2_w, u1_b, u2_b, mlp_w1, mlp_b1);
    sgemm<<<gemm_grid(TABROWS, 768), gemm_t>>>(p_demb, p_m1all, p_b1all, nullptr,
                                               p_tabh, TABROWS, 768, NG_PAD, NG_PAD, 2);
    mgemm<<<ttiles * LL, 256, MG_SMEM>>>(p_tabh, p_whi + (size_t)1 * 16384,
                                         p_wlo + (size_t)1 * 16384, mlp_b2, nullptr,
                                         p_tables, TABROWS, 3, ttiles, LL, 768, 0);
    pack_table<<<(LL * TABM * 128 + 255) / 256, 256>>>();

    // ---- phase 2: edge geometry + CSR-by-destination sort ----
    edge_geom_hist<<<(e + 255) / 256, 256>>>(ei, pos, p_dist, e);
    scan_nodes<<<1, 256>>>(n);
    edge_build<<<(e + 255) / 256, 256>>>(ei, p_dist, e);

    // ---- phase 3: feature embedding ----
    sgemm<<<gemm_grid(n, 64), gemm_t>>>(x, fe_w1, fe_b1, nullptr, p_h, n, 64, 28, 28, 0);
    bn_reduce<<<512, 256>>>(p_h, n);
    bn_apply<<<(n * 128 + 255) / 256, 256>>>(p_h, p_hn, bng, bnb, n);
    mgemm<<<mgrid, 256, MG_SMEM>>>(p_hn, p_whi + (size_t)25 * 16384,
                                   p_wlo + (size_t)25 * 16384, fe_b2, nullptr,
                                   p_v, n, 1, mtiles, 1, 128, 0);

    // ---- phase 4: interaction layers ----
    for (int l = 0; l < LL; l++) {
        const float* w1b = v1_b + (size_t)l * 128;
        const float* w2b = v2_b + (size_t)l * 128;
        __nv_bfloat16* lw_hi = p_whi + (size_t)(l * 4 + 0) * 16384;
        __nv_bfloat16* lw_lo = p_wlo + (size_t)(l * 4 + 0) * 16384;
        __nv_bfloat16* w1_hi = p_whi + (size_t)(l * 4 + 2) * 16384;
        __nv_bfloat16* w1_lo = p_wlo + (size_t)(l * 4 + 2) * 16384;
        __nv_bfloat16* w2_hi = p_whi + (size_t)(l * 4 + 3) * 16384;
        __nv_bfloat16* w2_lo = p_wlo + (size_t)(l * 4 + 3) * 16384;

        mgemm<<<mgrid, 256, MG_SMEM>>>(p_v, lw_hi, lw_lo, nullptr, nullptr,
                                       (float*)p_vlinh, n, 0, mtiles, 1, 128, 1);
        edge_gather<<<ggrid, 256>>>(p_vlinh, p_ptab + (size_t)l * TABM * 128,
                                    p_aggh, n);
        fgemm<<<fgrid, 512, FG_SMEM>>>(p_aggh, w1_hi, w1_lo, w2_hi, w2_lo,
                                       w1b, w2b, p_v, p_v, n, ftiles, 1);
    }

    // ---- phase 5: readout ----
    fgemm<<<fgrid, 512, FG_SMEM>>>(p_v,
                                   p_whi + (size_t)24 * 16384, p_wlo + (size_t)24 * 16384,
                                   p_whi + (size_t)26 * 16384, p_wlo + (size_t)26 * 16384,
                                   p_u1b, p_u2b, nullptr, p_t1, n, ftiles, 0);
    cudaMemsetAsync(out, 0, (size_t)out_size * sizeof(float));
    node_out<<<((n + 127) / 128 * 32 + 255) / 256, 256>>>(p_t1, batch, out, n);
}

// round 17
// speedup vs baseline: 1.5843x; 1.1729x over previous
#include <cuda_runtime.h>
#include <cuda_bf16.h>
#include <cuda_fp16.h>
#include <math.h>
#include <stdint.h>

// Problem constants
#define NN 50000
#define EE 800000
#define GG 512
#define LL 6
#define NGAUSS 50
#define NG_PAD 56
#define TABM 1024                  // table intervals over [0, 7]
#define TABROWS (TABM + 1)
#define TAB_MAX 7.0f
#define TAB_INVSTEP ((float)TABM / TAB_MAX)
#define TAB_STEP (TAB_MAX / (float)TABM)
#define SKIP_D 6.97f
#define LN2F 0.69314718055994530942f
#define PIF 3.14159265358979323846f

// ---------------- scratch (device globals; no allocation allowed) -------------
__device__ __align__(256) float g_h[NN * 64];
__device__ __align__(256) float g_hn[NN * 128];      // K=128 padded
__device__ __align__(256) float g_v[NN * 128];
__device__ __align__(256) __half g_vlinh[NN * 128];  // fp16 vlin
__device__ __align__(256) __half g_aggh[NN * 128];   // fp16 agg
__device__ __align__(256) float g_t1[NN * 128];
__device__ __align__(256) float g_dist[EE];
__device__ __align__(256) float g_demb[TABROWS * NG_PAD];
__device__ __align__(256) float g_tabh[TABROWS * 768];   // all 6 layers, N=768
__device__ __align__(256) float g_tables[LL * TABROWS * 128];
__device__ __align__(256) __half2 g_ptab[LL * TABM * 128];  // fp16 (T[i],T[i+1]) pairs
__device__ __align__(256) float g_bnacc[128];
__device__ __align__(256) float g_u1bpad[128];
__device__ __align__(256) float g_u2bpad[128];
__device__ __align__(256) float g_m1all[NG_PAD * 768];
__device__ __align__(256) float g_b1all[768];
// fp16 pre-transposed weights [slot][n][k]
// slots 0..23: l*4 + {lin,mlp2,v1,v2}; 24: u1 (N-pad); 25: fe2 (K-pad); 26: u2 (N,K-pad)
__device__ __align__(256) __half g_wth[27 * 128 * 128];
// CSR-by-destination edge sort; meta = (row:int, fi:float) packed
__device__ __align__(256) int   g_nhist[NN];
__device__ __align__(256) int   g_nstart[NN + 1];
__device__ __align__(256) int   g_ncursor[NN];
__device__ __align__(256) uint2 g_emeta[EE];

// ---------------- helpers ---------------------------------------------------
__device__ __forceinline__ float sspf(float x) {
    return fmaxf(x, 0.0f) + log1pf(expf(-fabsf(x))) - LN2F;
}
__device__ __forceinline__ unsigned long long bcast2(float x) {
    unsigned long long r;
    asm("mov.b64 %0, {%1, %1};" : "=l"(r) : "f"(x));
    return r;
}
__device__ __forceinline__ void ffma2(unsigned long long& d,
                                      unsigned long long a, unsigned long long b) {
    asm("fma.rn.f32x2 %0, %1, %2, %0;" : "+l"(d) : "l"(a), "l"(b));
}
__device__ __forceinline__ void unpack2(unsigned long long v, float& lo, float& hi) {
    asm("mov.b64 {%0, %1}, %2;" : "=f"(lo), "=f"(hi) : "l"(v));
}
__device__ __forceinline__ uint32_t smem_u32(const void* p) {
    uint32_t a;
    asm("{ .reg .u64 t; cvta.to.shared.u64 t, %1; cvt.u32.u64 %0, t; }" : "=r"(a) : "l"(p));
    return a;
}
// fp16 MMA, fp32 accumulate
__device__ __forceinline__ void mma16816(float* c, const uint32_t* a,
                                         uint32_t b0, uint32_t b1) {
    asm volatile(
        "mma.sync.aligned.m16n8k16.row.col.f32.f16.f16.f32 "
        "{%0,%1,%2,%3}, {%4,%5,%6,%7}, {%8,%9}, {%0,%1,%2,%3};"
        : "+f"(c[0]), "+f"(c[1]), "+f"(c[2]), "+f"(c[3])
        : "r"(a[0]), "r"(a[1]), "r"(a[2]), "r"(a[3]), "r"(b0), "r"(b1));
}
__device__ __forceinline__ void ldsm4(uint32_t* r, uint32_t addr) {
    asm volatile("ldmatrix.sync.aligned.m8n8.x4.shared.b16 {%0,%1,%2,%3}, [%4];"
        : "=r"(r[0]), "=r"(r[1]), "=r"(r[2]), "=r"(r[3]) : "r"(addr));
}
__device__ __forceinline__ uint32_t packh2(float x, float y) {
    __half2 h = __floats2half2_rn(x, y);
    return *(uint32_t*)&h;
}

#define MG_STRIDE 136   // fp16 per smem row (272B) — conflict-free ldmatrix
#define MG_A1 (64 * MG_STRIDE * 2)
#define MG_B1 (128 * MG_STRIDE * 2)
// mgemm: A hi/lo (64-row) + B hi (128-row)
#define MG_SMEM (2 * MG_A1 + MG_B1)
// fgemm: A hi/lo (128-row) + W1 hi + W2 hi
#define FG_SMEM (4 * MG_B1)

// ================= fp16x2 HMMA GEMM (pipelined A prefetch) ==================
// outh: store C as packed fp16 (act must be 0, no res).
__global__ void __launch_bounds__(256, 2) mgemm(
    const float* __restrict__ A, const __half* __restrict__ Bh,
    const float* __restrict__ bias,
    const float* __restrict__ res, float* __restrict__ C, int M, int act,
    int tiles_per_mat, int nmats, int lda, int outh) {
    extern __shared__ char smem[];
    __half* Ahs = (__half*)(smem);
    __half* Als = (__half*)(smem + MG_A1);
    __half* Bhs = (__half*)(smem + 2 * MG_A1);
    const uint32_t sb = smem_u32(smem);
    const uint32_t sAh = sb, sAl = sb + MG_A1;
    const uint32_t sBh = sb + 2 * MG_A1;

    const int t = threadIdx.x;
    const int lane = t & 31;
    const int w = t >> 5;
    const int wm = (w & 3) * 16;
    const int wn = (w >> 2) * 64;
    const int gid = lane >> 2;
    const int tg = lane & 3;

    const int arow_l = t >> 2;
    const int aseg = (t & 3) * 32;

    const int lrow = ((t >> 3) & 1) * 8 + (t & 7);
    const int lkb  = ((t >> 4) & 1) * 16;
    const uint32_t offA0 = (uint32_t)(wm + lrow) * 272 + lkb;
    const int brow = ((t >> 4) & 1) * 8 + (t & 7);
    const int bkb  = ((t >> 3) & 1) * 16;
    uint32_t offB[4];
#pragma unroll
    for (int p = 0; p < 4; p++) offB[p] = (uint32_t)(wn + p * 16 + brow) * 272 + bkb;

    const int total_tiles = tiles_per_mat * nmats;
    int cur_mat = -1;
    const float4 z4 = make_float4(0, 0, 0, 0);

    float4 pa[8];
    if (blockIdx.x < total_tiles) {
        int tl = blockIdx.x;
        int mat = (nmats == 1) ? 0 : (tl / tiles_per_mat);
        int lt  = (nmats == 1) ? tl : (tl % tiles_per_mat);
        int grow = lt * 64 + arow_l;
        bool valid = grow < M;
        const float4* ap = (const float4*)(A + (size_t)(valid ? grow : 0) * lda + mat * 128 + aseg);
#pragma unroll
        for (int c = 0; c < 8; c++) pa[c] = valid ? ap[c] : z4;
    }

    for (int tile = blockIdx.x; tile < total_tiles; tile += gridDim.x) {
        const int mat = (nmats == 1) ? 0 : (tile / tiles_per_mat);
        const int lt  = (nmats == 1) ? tile : (tile % tiles_per_mat);
        const int bm = lt * 64;

        if (mat != cur_mat) {
            cur_mat = mat;
            const __half* bh = Bh + (size_t)mat * 4 * 16384;
            int row = t >> 1, half = (t & 1) * 64;
            const uint4* bhp = (const uint4*)(bh + (size_t)row * 128 + half);
            __half* dbh = Bhs + row * MG_STRIDE + half;
#pragma unroll
            for (int c = 0; c < 8; c++) {
                *(uint4*)(dbh + c * 8) = bhp[c];
            }
        }

        {
            __half* ahp = Ahs + arow_l * MG_STRIDE + aseg;
            __half* alp = Als + arow_l * MG_STRIDE + aseg;
#pragma unroll
            for (int c = 0; c < 8; c++) {
                float4 v = pa[c];
                uint32_t h0 = packh2(v.x, v.y);
                uint32_t h1 = packh2(v.z, v.w);
                __half2* h0p = (__half2*)&h0;
                __half2* h1p = (__half2*)&h1;
                uint32_t l0 = packh2(v.x - __half2float(h0p->x), v.y - __half2float(h0p->y));
                uint32_t l1 = packh2(v.z - __half2float(h1p->x), v.w - __half2float(h1p->y));
                *(uint2*)(ahp + c * 4) = make_uint2(h0, h1);
                *(uint2*)(alp + c * 4) = make_uint2(l0, l1);
            }
        }
        __syncthreads();

        {
            int ntile = tile + gridDim.x;
            if (ntile < total_tiles) {
                int nmat = (nmats == 1) ? 0 : (ntile / tiles_per_mat);
                int nlt  = (nmats == 1) ? ntile : (ntile % tiles_per_mat);
                int grow = nlt * 64 + arow_l;
                bool valid = grow < M;
                const float4* ap = (const float4*)(A + (size_t)(valid ? grow : 0) * lda + nmat * 128 + aseg);
#pragma unroll
                for (int c = 0; c < 8; c++) pa[c] = valid ? ap[c] : z4;
            }
        }

        float acc[8][4];
#pragma unroll
        for (int ni = 0; ni < 8; ni++)
#pragma unroll
            for (int q = 0; q < 4; q++) acc[ni][q] = 0.0f;

#pragma unroll
        for (int k0 = 0; k0 < 8; k0++) {
            const uint32_t ko = k0 * 32;
            uint32_t ah[4], al[4];
            ldsm4(ah, sAh + offA0 + ko);
            ldsm4(al, sAl + offA0 + ko);
#pragma unroll
            for (int p = 0; p < 4; p++) {
                uint32_t bh[4];
                ldsm4(bh, sBh + offB[p] + ko);
                mma16816(acc[2 * p],     ah, bh[0], bh[1]);
                mma16816(acc[2 * p],     al, bh[0], bh[1]);
                mma16816(acc[2 * p + 1], ah, bh[2], bh[3]);
                mma16816(acc[2 * p + 1], al, bh[2], bh[3]);
            }
        }

        const float* mbias = bias ? (bias + (size_t)mat * 128) : nullptr;
        float* mC = C;
        if (nmats > 1) mC = C + (size_t)mat * (size_t)TABROWS * 128;
        {
            int r0 = bm + wm + gid;
            int r1 = r0 + 8;
            float sc0 = 1.0f, sc1 = 1.0f;
            if (act == 3) {
                sc0 = 0.5f * (cosf((float)r0 * TAB_STEP * (PIF / 6.0f)) + 1.0f);
                sc1 = 0.5f * (cosf((float)r1 * TAB_STEP * (PIF / 6.0f)) + 1.0f);
            }
#pragma unroll
            for (int ni = 0; ni < 8; ni++) {
                int cb = wn + ni * 8 + tg * 2;
                float b0 = mbias ? __ldg(mbias + cb) : 0.0f;
                float b1 = mbias ? __ldg(mbias + cb + 1) : 0.0f;
                float* a4 = acc[ni];
                float v00 = a4[0] + b0, v01 = a4[1] + b1;
                float v10 = a4[2] + b0, v11 = a4[3] + b1;
                if (act == 1) {
                    v00 = fmaxf(v00, 0.0f); v01 = fmaxf(v01, 0.0f);
                    v10 = fmaxf(v10, 0.0f); v11 = fmaxf(v11, 0.0f);
                } else if (act == 2) {
                    v00 = sspf(v00); v01 = sspf(v01); v10 = sspf(v10); v11 = sspf(v11);
                } else if (act == 3) {
                    v00 *= sc0; v01 *= sc0; v10 *= sc1; v11 *= sc1;
                }
                if (outh) {
                    __half* hC = (__half*)mC;
                    if (r0 < M)
                        *(__half2*)(hC + (size_t)r0 * 128 + cb) = __floats2half2_rn(v00, v01);
                    if (r1 < M)
                        *(__half2*)(hC + (size_t)r1 * 128 + cb) = __floats2half2_rn(v10, v11);
                } else {
                    if (r0 < M) {
                        if (res) {
                            float2 rr = *(const float2*)(res + (size_t)r0 * 128 + cb);
                            v00 += rr.x; v01 += rr.y;
                        }
                        *(float2*)(mC + (size_t)r0 * 128 + cb) = make_float2(v00, v01);
                    }
                    if (r1 < M) {
                        if (res) {
                            float2 rr = *(const float2*)(res + (size_t)r1 * 128 + cb);
                            v10 += rr.x; v11 += rr.y;
                        }
                        *(float2*)(mC + (size_t)r1 * 128 + cb) = make_float2(v10, v11);
                    }
                }
            }
        }
        __syncthreads();
    }
}

// ===== fused double-GEMM fp16x2 (512 threads, M=128 tiles) ===================
// inh: A is fp16 (stride 128 halves); else fp32.
__global__ void __launch_bounds__(512, 1) fgemm(
    const void* __restrict__ Av,
    const __half* __restrict__ B1h, const __half* __restrict__ B2h,
    const float* __restrict__ bias1, const float* __restrict__ bias2,
    const float* __restrict__ res, float* __restrict__ C, int M, int tiles, int inh) {
    extern __shared__ char smem[];
    __half* Ahs  = (__half*)(smem);
    __half* Als  = (__half*)(smem + MG_B1);
    __half* B1hs = (__half*)(smem + 2 * MG_B1);
    __half* B2hs = (__half*)(smem + 3 * MG_B1);
    const uint32_t sb = smem_u32(smem);
    const uint32_t sAh = sb, sAl = sb + MG_B1;
    const uint32_t sB1h = sb + 2 * MG_B1, sB2h = sb + 3 * MG_B1;

    const int t = threadIdx.x;
    const int lane = t & 31;
    const int w = t >> 5;           // 0..15
    const int wm = (w >> 1) * 16;   // 8 M-slots of 16 rows
    const int wn = (w & 1) * 64;    // 2 N-halves
    const int gid = lane >> 2;
    const int tg = lane & 3;
    const int arow_l = t >> 2;      // 0..127
    const int aseg = (t & 3) * 32;
    const int lrow = ((lane >> 3) & 1) * 8 + (lane & 7);
    const int lkb  = ((lane >> 4) & 1) * 16;
    const uint32_t offA0 = (uint32_t)(wm + lrow) * 272 + lkb;
    const int brow = ((lane >> 4) & 1) * 8 + (lane & 7);
    const int bkb  = ((lane >> 3) & 1) * 16;
    uint32_t offB[4];
#pragma unroll
    for (int p = 0; p < 4; p++) offB[p] = (uint32_t)(wn + p * 16 + brow) * 272 + bkb;

    // stage both weight matrices once (512 threads: each does 32 cols/matrix)
    {
        const int srow = t >> 2, shalf = (t & 3) * 32;
        const uint4* b1 = (const uint4*)(B1h + (size_t)srow * 128 + shalf);
        const uint4* b2 = (const uint4*)(B2h + (size_t)srow * 128 + shalf);
        __half* d1 = B1hs + srow * MG_STRIDE + shalf;
        __half* d2 = B2hs + srow * MG_STRIDE + shalf;
#pragma unroll
        for (int c = 0; c < 4; c++) {
            *(uint4*)(d1 + c * 8) = b1[c];
            *(uint4*)(d2 + c * 8) = b2[c];
        }
    }

    const float4 z4 = make_float4(0, 0, 0, 0);
    const float* Af = (const float*)Av;
    const __half* Ah16 = (const __half*)Av;

    float4 pa[8];
    auto loadA = [&](int tl) {
        int grow = tl * 128 + arow_l;
        bool valid = grow < M;
        if (inh) {
            const uint4* ap = (const uint4*)(Ah16 + (size_t)(valid ? grow : 0) * 128 + aseg);
#pragma unroll
            for (int c = 0; c < 4; c++) {
                if (valid) {
                    uint4 q = __ldg(ap + c);
                    float2 f0 = __half22float2(*(__half2*)&q.x);
                    float2 f1 = __half22float2(*(__half2*)&q.y);
                    float2 f2 = __half22float2(*(__half2*)&q.z);
                    float2 f3 = __half22float2(*(__half2*)&q.w);
                    pa[2 * c]     = make_float4(f0.x, f0.y, f1.x, f1.y);
                    pa[2 * c + 1] = make_float4(f2.x, f2.y, f3.x, f3.y);
                } else {
                    pa[2 * c] = z4;
                    pa[2 * c + 1] = z4;
                }
            }
        } else {
            const float4* ap = (const float4*)(Af + (size_t)(valid ? grow : 0) * 128 + aseg);
#pragma unroll
            for (int c = 0; c < 8; c++) pa[c] = valid ? ap[c] : z4;
        }
    };

    if (blockIdx.x < tiles) loadA(blockIdx.x);

    for (int tile = blockIdx.x; tile < tiles; tile += gridDim.x) {
        const int bm = tile * 128;

        {
            __half* ahp = Ahs + arow_l * MG_STRIDE + aseg;
            __half* alp = Als + arow_l * MG_STRIDE + aseg;
#pragma unroll
            for (int c = 0; c < 8; c++) {
                float4 v = pa[c];
                uint32_t h0 = packh2(v.x, v.y);
                uint32_t h1 = packh2(v.z, v.w);
                __half2* h0p = (__half2*)&h0;
                __half2* h1p = (__half2*)&h1;
                uint32_t l0 = packh2(v.x - __half2float(h0p->x), v.y - __half2float(h0p->y));
                uint32_t l1 = packh2(v.z - __half2float(h1p->x), v.w - __half2float(h1p->y));
                *(uint2*)(ahp + c * 4) = make_uint2(h0, h1);
                *(uint2*)(alp + c * 4) = make_uint2(l0, l1);
            }
        }
        __syncthreads();

        {
            int ntile = tile + gridDim.x;
            if (ntile < tiles) loadA(ntile);
        }

        float acc[8][4];
#pragma unroll
        for (int ni = 0; ni < 8; ni++)
#pragma unroll
            for (int q = 0; q < 4; q++) acc[ni][q] = 0.0f;

        // ---- MMA1: A @ W1 ----
#pragma unroll
        for (int k0 = 0; k0 < 8; k0++) {
            const uint32_t ko = k0 * 32;
            uint32_t ah[4], al[4];
            ldsm4(ah, sAh + offA0 + ko);
            ldsm4(al, sAl + offA0 + ko);
#pragma unroll
            for (int p = 0; p < 4; p++) {
                uint32_t bh[4];
                ldsm4(bh, sB1h + offB[p] + ko);
                mma16816(acc[2 * p],     ah, bh[0], bh[1]);
                mma16816(acc[2 * p],     al, bh[0], bh[1]);
                mma16816(acc[2 * p + 1], ah, bh[2], bh[3]);
                mma16816(acc[2 * p + 1], al, bh[2], bh[3]);
            }
        }
        __syncthreads();   // all MMA1 A-reads done before t1 overwrites A buffers

        // ---- epilogue1: t1 = ssp(acc + b1) -> fp16 hi/lo back into A buffers --
        {
            int r0 = wm + gid;
            int r1 = r0 + 8;
#pragma unroll
            for (int ni = 0; ni < 8; ni++) {
                int cb = wn + ni * 8 + tg * 2;
                float b0 = __ldg(bias1 + cb);
                float b1 = __ldg(bias1 + cb + 1);
                float* a4 = acc[ni];
                float v00 = sspf(a4[0] + b0), v01 = sspf(a4[1] + b1);
                float v10 = sspf(a4[2] + b0), v11 = sspf(a4[3] + b1);
                uint32_t h0 = packh2(v00, v01);
                uint32_t h1 = packh2(v10, v11);
                __half2* h0p = (__half2*)&h0;
                __half2* h1p = (__half2*)&h1;
                uint32_t l0 = packh2(v00 - __half2float(h0p->x), v01 - __half2float(h0p->y));
                uint32_t l1 = packh2(v10 - __half2float(h1p->x), v11 - __half2float(h1p->y));
                *(uint32_t*)(Ahs + r0 * MG_STRIDE + cb) = h0;
                *(uint32_t*)(Ahs + r1 * MG_STRIDE + cb) = h1;
                *(uint32_t*)(Als + r0 * MG_STRIDE + cb) = l0;
                *(uint32_t*)(Als + r1 * MG_STRIDE + cb) = l1;
            }
        }
        __syncthreads();   // t1 fully written (cross-warp columns)

        // ---- MMA2: t1 @ W2 ----
#pragma unroll
        for (int ni = 0; ni < 8; ni++)
#pragma unroll
            for (int q = 0; q < 4; q++) acc[ni][q] = 0.0f;
#pragma unroll
        for (int k0 = 0; k0 < 8; k0++) {
            const uint32_t ko = k0 * 32;
            uint32_t ah[4], al[4];
            ldsm4(ah, sAh + offA0 + ko);
            ldsm4(al, sAl + offA0 + ko);
#pragma unroll
            for (int p = 0; p < 4; p++) {
                uint32_t bh[4];
                ldsm4(bh, sB2h + offB[p] + ko);
                mma16816(acc[2 * p],     ah, bh[0], bh[1]);
                mma16816(acc[2 * p],     al, bh[0], bh[1]);
                mma16816(acc[2 * p + 1], ah, bh[2], bh[3]);
                mma16816(acc[2 * p + 1], al, bh[2], bh[3]);
            }
        }

        // ---- epilogue2: + b2 (+res) -> C ----
        {
            int r0 = bm + wm + gid;
            int r1 = r0 + 8;
#pragma unroll
            for (int ni = 0; ni < 8; ni++) {
                int cb = wn + ni * 8 + tg * 2;
                float b0 = __ldg(bias2 + cb);
                float b1 = __ldg(bias2 + cb + 1);
                float* a4 = acc[ni];
                float v00 = a4[0] + b0, v01 = a4[1] + b1;
                float v10 = a4[2] + b0, v11 = a4[3] + b1;
                if (r0 < M) {
                    if (res) {
                        float2 rr = *(const float2*)(res + (size_t)r0 * 128 + cb);
                        v00 += rr.x; v01 += rr.y;
                    }
                    *(float2*)(C + (size_t)r0 * 128 + cb) = make_float2(v00, v01);
                }
                if (r1 < M) {
                    if (res) {
                        float2 rr = *(const float2*)(res + (size_t)r1 * 128 + cb);
                        v10 += rr.x; v11 += rr.y;
                    }
                    *(float2*)(C + (size_t)r1 * 128 + cb) = make_float2(v10, v11);
                }
            }
        }
        __syncthreads();   // protect A buffers before next tile's staging
    }
}

// ---------------- merged preprocessing --------------------------------------
__global__ void prep_all(const float* __restrict__ lin_w, const float* __restrict__ mlp_w2,
                         const float* __restrict__ v1_w, const float* __restrict__ v2_w,
                         const float* __restrict__ u1_w, const float* __restrict__ fe_w2,
                         const float* __restrict__ u2_w,
                         const float* __restrict__ u1_b, const float* __restrict__ u2_b,
                         const float* __restrict__ mlp_w1, const float* __restrict__ mlp_b1) {
    int idx = blockIdx.x * blockDim.x + threadIdx.x;
    if (idx < 128) {
        g_u1bpad[idx] = (idx < 64) ? u1_b[idx] : 0.0f;
        g_u2bpad[idx] = (idx < 32) ? u2_b[idx] : 0.0f;
        g_bnacc[idx] = 0.0f;
    }
    if (idx < NN) g_nhist[idx] = 0;
    if (idx < 768) g_b1all[idx] = mlp_b1[(idx >> 7) * 128 + (idx & 127)];
    if (idx < NG_PAD * 768) {
        int k = idx / 768;
        int c = idx % 768;
        int l = c >> 7, nn2 = c & 127;
        g_m1all[idx] = (k < NGAUSS) ? mlp_w1[(size_t)l * NGAUSS * 128 + k * 128 + nn2] : 0.0f;
    }
    if (idx < TABROWS * NG_PAD) {
        int m = idx / NG_PAD;
        int g = idx % NG_PAD;
        float val = 0.0f;
        if (g < NGAUSS) {
            float d = (float)m * TAB_STEP;
            float off = (float)g * (6.0f / 49.0f);
            float tt = d - off;
            const float coeff = -0.5f / ((6.0f / 49.0f) * (6.0f / 49.0f));
            val = expf(coeff * tt * tt);
        }
        g_demb[idx] = val;
    }
    if (idx < 27 * 16384) {
        int slot = idx >> 14;
        int r = idx & 16383;
        int n = r >> 7;
        int k = r & 127;
        float a;
        if (slot < 24) {
            int l = slot >> 2, w = slot & 3;
            const float* src = (w == 0) ? lin_w : (w == 1) ? mlp_w2 : (w == 2) ? v1_w : v2_w;
            a = src[(size_t)l * 16384 + k * 128 + n];
        } else if (slot == 24) {
            a = (n < 64) ? u1_w[k * 64 + n] : 0.0f;
        } else if (slot == 25) {
            a = (k < 64) ? fe_w2[k * 128 + n] : 0.0f;
        } else {
            a = (k < 64 && n < 32) ? u2_w[k * 32 + n] : 0.0f;
        }
        g_wth[idx] = __float2half_rn(a);
    }
}

// ---------------- fp16 pair-table pack ---------------------------------------
__global__ void pack_table() {
    int idx = blockIdx.x * blockDim.x + threadIdx.x;
    if (idx >= LL * TABM * 128) return;
    int c = idx & 127;
    int rest = idx >> 7;
    int i = rest % TABM;
    int l = rest / TABM;
    const float* tab = g_tables + (size_t)l * TABROWS * 128;
    float a = tab[(size_t)i * 128 + c];
    float b = tab[(size_t)(i + 1) * 128 + c];
    g_ptab[idx] = __floats2half2_rn(a, b);
}

// ---------------- edge geometry + per-destination histogram ------------------
__global__ void edge_geom_hist(const int* __restrict__ ei, const float* __restrict__ pos,
                               float* __restrict__ dist, int e_total) {
    int e = blockIdx.x * blockDim.x + threadIdx.x;
    if (e >= e_total) return;
    int r = ei[e];
    int c = ei[e_total + e];
    float dx = pos[r * 3 + 0] - pos[c * 3 + 0];
    float dy = pos[r * 3 + 1] - pos[c * 3 + 1];
    float dz = pos[r * 3 + 2] - pos[c * 3 + 2];
    float d = sqrtf(dx * dx + dy * dy + dz * dz);
    dist[e] = d;
    if (d < SKIP_D) atomicAdd(&g_nhist[c], 1);
}

__global__ void scan_nodes(int n) {
    __shared__ int part[256];
    int t = threadIdx.x;
    int chunk = (n + 255) / 256;
    int lo = t * chunk;
    int hi = min(lo + chunk, n);
    int s = 0;
    for (int i = lo; i < hi; i++) s += g_nhist[i];
    part[t] = s;
    __syncthreads();
    if (t == 0) {
        int acc = 0;
        for (int i = 0; i < 256; i++) { int c = part[i]; part[i] = acc; acc += c; }
    }
    __syncthreads();
    int acc = part[t];
    for (int i = lo; i < hi; i++) {
        int c = g_nhist[i];
        g_nstart[i] = acc;
        g_ncursor[i] = acc;
        acc += c;
    }
    if (hi == n) g_nstart[n] = acc;
}

__global__ void edge_build(const int* __restrict__ ei, const float* __restrict__ dist,
                           int e_total) {
    int e = blockIdx.x * blockDim.x + threadIdx.x;
    if (e >= e_total) return;
    float d = dist[e];
    if (d >= SKIP_D) return;
    int c = ei[e_total + e];
    int p = atomicAdd(&g_ncursor[c], 1);
    float fi = d * TAB_INVSTEP;
    g_emeta[p] = make_uint2((uint32_t)ei[e], __float_as_uint(fi));
}

// ---------------- SIMT fp32 SGEMM with f32x2 (small/odd shapes) -------------
__global__ void __launch_bounds__(256, 2) sgemm(
    const float* __restrict__ A, const float* __restrict__ B,
    const float* __restrict__ bias, const float* __restrict__ res,
    float* __restrict__ C, int M, int N, int K, int Kb, int act) {
    __shared__ float As[2][8][128];
    __shared__ float Bs[2][8][128];
    const int tid = threadIdx.x;
    const int bm = blockIdx.y * 128;
    const int bn = blockIdx.x * 128;
    const int tx = tid & 15;
    const int ty = tid >> 4;
    const int ar = tid >> 1;
    const int ak = (tid & 1) * 4;
    const int bk = tid >> 5;
    const int bn4 = (tid & 31) * 4;
    const int arow = bm + ar;
    const int bcol = bn + bn4;
    const int KT = (K + 7) >> 3;

    unsigned long long acc[8][4];
#pragma unroll
    for (int i = 0; i < 8; i++)
#pragma unroll
        for (int j = 0; j < 4; j++) acc[i][j] = 0ull;

    float4 pa = make_float4(0, 0, 0, 0);
    float4 pb = make_float4(0, 0, 0, 0);
    if (arow < M && ak < K) pa = *(const float4*)(A + (size_t)arow * K + ak);
    if (bk < Kb && bcol < N) pb = *(const float4*)(B + (size_t)bk * N + bcol);
    As[0][ak + 0][ar] = pa.x; As[0][ak + 1][ar] = pa.y;
    As[0][ak + 2][ar] = pa.z; As[0][ak + 3][ar] = pa.w;
    *(float4*)&Bs[0][bk][bn4] = pb;
    __syncthreads();

    for (int kt = 0; kt < KT; kt++) {
        const int s = kt & 1;
        if (kt + 1 < KT) {
            int k0 = (kt + 1) * 8;
            pa = make_float4(0, 0, 0, 0);
            pb = make_float4(0, 0, 0, 0);
            if (arow < M && (k0 + ak) < K) pa = *(const float4*)(A + (size_t)arow * K + k0 + ak);
            if ((k0 + bk) < Kb && bcol < N) pb = *(const float4*)(B + (size_t)(k0 + bk) * N + bcol);
        }
#pragma unroll
        for (int k = 0; k < 8; k++) {
            float a[8];
            *(float4*)&a[0] = *(const float4*)&As[s][k][ty * 8];
            *(float4*)&a[4] = *(const float4*)&As[s][k][ty * 8 + 4];
            ulonglong2 bl = *(const ulonglong2*)&Bs[s][k][tx * 8];
            ulonglong2 bh = *(const ulonglong2*)&Bs[s][k][tx * 8 + 4];
#pragma unroll
            for (int i = 0; i < 8; i++) {
                unsigned long long ai = bcast2(a[i]);
                ffma2(acc[i][0], ai, bl.x);
                ffma2(acc[i][1], ai, bl.y);
                ffma2(acc[i][2], ai, bh.x);
                ffma2(acc[i][3], ai, bh.y);
            }
        }
        if (kt + 1 < KT) {
            const int so = (kt + 1) & 1;
            As[so][ak + 0][ar] = pa.x; As[so][ak + 1][ar] = pa.y;
            As[so][ak + 2][ar] = pa.z; As[so][ak + 3][ar] = pa.w;
            *(float4*)&Bs[so][bk][bn4] = pb;
            __syncthreads();
        }
    }

    const int cbase = bn + tx * 8;
    float bv[8];
#pragma unroll
    for (int j = 0; j < 8; j++) bv[j] = (bias && (cbase + j) < N) ? bias[cbase + j] : 0.0f;

#pragma unroll
    for (int i = 0; i < 8; i++) {
        int row = bm + ty * 8 + i;
        if (row >= M) continue;
        float c[8];
        unpack2(acc[i][0], c[0], c[1]);
        unpack2(acc[i][1], c[2], c[3]);
        unpack2(acc[i][2], c[4], c[5]);
        unpack2(acc[i][3], c[6], c[7]);
#pragma unroll
        for (int j = 0; j < 8; j++) {
            float v = c[j] + bv[j];
            if (act == 1) v = fmaxf(v, 0.0f);
            else if (act == 2) v = sspf(v);
            c[j] = v;
        }
        if (res) {
#pragma unroll
            for (int j = 0; j < 8; j++)
                if ((cbase + j) < N) c[j] += res[(size_t)row * N + cbase + j];
        }
        if (cbase < N)
            *(float4*)(C + (size_t)row * N + cbase) = make_float4(c[0], c[1], c[2], c[3]);
        if (cbase + 4 < N)
            *(float4*)(C + (size_t)row * N + cbase + 4) = make_float4(c[4], c[5], c[6], c[7]);
    }
}

// ---------------- batchnorm ---------------------------------------------------
__global__ void bn_reduce(const float* __restrict__ h, int n) {
    __shared__ float ss[4][64];
    __shared__ float sq[4][64];
    int c = threadIdx.x & 63;
    int g = threadIdx.x >> 6;
    float s = 0.0f, q = 0.0f;
    for (int row = blockIdx.x * 4 + g; row < n; row += gridDim.x * 4) {
        float v = h[row * 64 + c];
        s += v;
        q += v * v;
    }
    ss[g][c] = s;
    sq[g][c] = q;
    __syncthreads();
    if (g == 0) {
        atomicAdd(&g_bnacc[c], ss[0][c] + ss[1][c] + ss[2][c] + ss[3][c]);
        atomicAdd(&g_bnacc[64 + c], sq[0][c] + sq[1][c] + sq[2][c] + sq[3][c]);
    }
}

__global__ void bn_apply(const float* __restrict__ h, float* __restrict__ hn,
                         const float* __restrict__ gamma, const float* __restrict__ beta,
                         int n) {
    int idx = blockIdx.x * blockDim.x + threadIdx.x;
    if (idx >= n * 128) return;
    int c = idx & 127;
    float y = 0.0f;
    if (c < 64) {
        float invN = 1.0f / (float)n;
        float mu = g_bnacc[c] * invN;
        float var = g_bnacc[64 + c] * invN - mu * mu;
        y = (h[(idx >> 7) * 64 + c] - mu) / sqrtf(var + 1e-5f) * gamma[c] + beta[c];
        y = fmaxf(y, 0.0f);
    }
    hn[idx] = y;
}

// --- edge gather: warp/node (fp16 table + fp16 vlin + packed meta + fp16 out) -
__global__ void __launch_bounds__(256) edge_gather(
    const __half* __restrict__ vlinh, const __half2* __restrict__ ptab,
    __half* __restrict__ aggh, int n) {
    int node = (blockIdx.x * blockDim.x + threadIdx.x) >> 5;
    int lane = threadIdx.x & 31;
    if (node >= n) return;
    int j = g_nstart[node];
    int end = g_nstart[node + 1];

    float a0 = 0.0f, a1 = 0.0f, a2 = 0.0f, a3 = 0.0f;

    for (; j + 4 <= end; j += 4) {
        uint2 mt[4]; int ii[4]; float fr[4];
        uint4 tp[4]; uint2 hv[4];
#pragma unroll
        for (int q = 0; q < 4; q++) {
            mt[q] = __ldg(g_emeta + j + q);
            float fi = __uint_as_float(mt[q].y);
            ii[q] = (int)fi;
            fr[q] = fi - (float)ii[q];
        }
#pragma unroll
        for (int q = 0; q < 4; q++) {
            tp[q] = __ldg(reinterpret_cast<const uint4*>(ptab + (size_t)ii[q] * 128) + lane);
            hv[q] = __ldg(reinterpret_cast<const uint2*>(vlinh + (size_t)mt[q].x * 128) + lane);
        }
#pragma unroll
        for (int q = 0; q < 4; q++) {
            float2 p0 = __half22float2(*(__half2*)&tp[q].x);
            float2 p1 = __half22float2(*(__half2*)&tp[q].y);
            float2 p2 = __half22float2(*(__half2*)&tp[q].z);
            float2 p3 = __half22float2(*(__half2*)&tp[q].w);
            float2 v01 = __half22float2(*(__half2*)&hv[q].x);
            float2 v23 = __half22float2(*(__half2*)&hv[q].y);
            a0 = fmaf(v01.x, p0.x + fr[q] * (p0.y - p0.x), a0);
            a1 = fmaf(v01.y, p1.x + fr[q] * (p1.y - p1.x), a1);
            a2 = fmaf(v23.x, p2.x + fr[q] * (p2.y - p2.x), a2);
            a3 = fmaf(v23.y, p3.x + fr[q] * (p3.y - p3.x), a3);
        }
    }
    for (; j < end; j++) {
        uint2 mt = __ldg(g_emeta + j);
        float fi = __uint_as_float(mt.y);
        int   i0 = (int)fi;
        float fr0 = fi - (float)i0;
        uint4 tq = __ldg(reinterpret_cast<const uint4*>(ptab + (size_t)i0 * 128) + lane);
        uint2 hq = __ldg(reinterpret_cast<const uint2*>(vlinh + (size_t)mt.x * 128) + lane);
        float2 p0 = __half22float2(*(__half2*)&tq.x);
        float2 p1 = __half22float2(*(__half2*)&tq.y);
        float2 p2 = __half22float2(*(__half2*)&tq.z);
        float2 p3 = __half22float2(*(__half2*)&tq.w);
        float2 v01 = __half22float2(*(__half2*)&hq.x);
        float2 v23 = __half22float2(*(__half2*)&hq.y);
        a0 = fmaf(v01.x, p0.x + fr0 * (p0.y - p0.x), a0);
        a1 = fmaf(v01.y, p1.x + fr0 * (p1.y - p1.x), a1);
        a2 = fmaf(v23.x, p2.x + fr0 * (p2.y - p2.x), a2);
        a3 = fmaf(v23.y, p3.x + fr0 * (p3.y - p3.x), a3);
    }

    __half2 o01 = __floats2half2_rn(a0, a1);
    __half2 o23 = __floats2half2_rn(a2, a3);
    uint2 ov = make_uint2(*(uint32_t*)&o01, *(uint32_t*)&o23);
    *(uint2*)(aggh + (size_t)node * 128 + lane * 4) = ov;
}

// ---------------- final per-graph scatter (batch sorted; s stride 128) --------
__global__ void node_out(const float* __restrict__ s, const int* __restrict__ batch,
                         float* __restrict__ out, int n) {
    int w = (blockIdx.x * blockDim.x + threadIdx.x) >> 5;
    int lane = threadIdx.x & 31;
    int start = w * 128;
    if (start >= n) return;
    int end = min(start + 128, n);
    int cur = __ldg(batch + start);
    float acc = 0.0f;
    for (int node = start; node < end; node++) {
        int b = __ldg(batch + node);
        if (b != cur) {
            atomicAdd(&out[cur * 32 + lane], acc);
            acc = 0.0f;
            cur = b;
        }
        acc += s[(size_t)node * 128 + lane];
    }
    atomicAdd(&out[cur * 32 + lane], acc);
}

// ---------------- host ---------------------------------------------------------
static float* sym(const void* s) {
    void* p = nullptr;
    cudaGetSymbolAddress(&p, s);
    return (float*)p;
}

extern "C" void kernel_launch(void* const* d_in, const int* in_sizes, int n_in,
                              void* d_out, int out_size) {
    const float* x       = (const float*)d_in[0];
    const float* pos     = (const float*)d_in[1];
    const int*   batch   = (const int*)d_in[2];
    const int*   ei      = (const int*)d_in[3];
    const float* fe_w1   = (const float*)d_in[4];
    const float* fe_b1   = (const float*)d_in[5];
    const float* bng     = (const float*)d_in[6];
    const float* bnb     = (const float*)d_in[7];
    const float* fe_w2   = (const float*)d_in[8];
    const float* fe_b2   = (const float*)d_in[9];
    const float* lin_w   = (const float*)d_in[10];
    const float* mlp_w1  = (const float*)d_in[11];
    const float* mlp_b1  = (const float*)d_in[12];
    const float* mlp_w2  = (const float*)d_in[13];
    const float* mlp_b2  = (const float*)d_in[14];
    const float* v1_w    = (const float*)d_in[15];
    const float* v1_b    = (const float*)d_in[16];
    const float* v2_w    = (const float*)d_in[17];
    const float* v2_b    = (const float*)d_in[18];
    const float* u1_w    = (const float*)d_in[19];
    const float* u1_b    = (const float*)d_in[20];
    const float* u2_w    = (const float*)d_in[21];
    const float* u2_b    = (const float*)d_in[22];
    float* out = (float*)d_out;

    int n = in_sizes[0] / 28;
    int e = in_sizes[3] / 2;

    float* p_h      = sym(g_h);
    float* p_hn     = sym(g_hn);
    float* p_v      = sym(g_v);
    __half* p_vlinh = (__half*)sym(g_vlinh);
    __half* p_aggh  = (__half*)sym(g_aggh);
    float* p_t1     = sym(g_t1);
    float* p_dist   = sym(g_dist);
    float* p_demb   = sym(g_demb);
    float* p_tabh   = sym(g_tabh);
    float* p_tables = sym(g_tables);
    __half2* p_ptab = (__half2*)sym(g_ptab);
    float* p_u1b    = sym(g_u1bpad);
    float* p_u2b    = sym(g_u2bpad);
    float* p_m1all  = sym(g_m1all);
    float* p_b1all  = sym(g_b1all);
    __half* p_wth   = (__half*)sym(g_wth);

    cudaFuncSetAttribute(mgemm, cudaFuncAttributeMaxDynamicSharedMemorySize, MG_SMEM);
    cudaFuncSetAttribute(fgemm, cudaFuncAttributeMaxDynamicSharedMemorySize, FG_SMEM);

    int sms = 148;
    cudaDeviceGetAttribute(&sms, cudaDevAttrMultiProcessorCount, 0);

    dim3 gemm_t(256);
    auto gemm_grid = [](int M, int N) {
        return dim3((unsigned)((N + 127) / 128), (unsigned)((M + 127) / 128));
    };
    int mtiles = (n + 63) / 64;
    int ftiles = (n + 127) / 128;
    int ttiles = (TABROWS + 63) / 64;
    int mgrid = mtiles < 2 * sms ? mtiles : 2 * sms;
    int fgrid = ftiles < sms ? ftiles : sms;
    int ggrid = (n + 7) / 8;

    // ---- phase 1: merged prep + batched table build + fp16 pair pack ----
    prep_all<<<(27 * 16384 + 255) / 256, 256>>>(lin_w, mlp_w2, v1_w, v2_w, u1_w,
                                                fe_w2, u2_w, u1_b, u2_b, mlp_w1, mlp_b1);
    sgemm<<<gemm_grid(TABROWS, 768), gemm_t>>>(p_demb, p_m1all, p_b1all, nullptr,
                                               p_tabh, TABROWS, 768, NG_PAD, NG_PAD, 2);
    mgemm<<<ttiles * LL, 256, MG_SMEM>>>(p_tabh, p_wth + (size_t)1 * 16384,
                                         mlp_b2, nullptr,
                                         p_tables, TABROWS, 3, ttiles, LL, 768, 0);
    pack_table<<<(LL * TABM * 128 + 255) / 256, 256>>>();

    // ---- phase 2: edge geometry + CSR-by-destination sort ----
    edge_geom_hist<<<(e + 255) / 256, 256>>>(ei, pos, p_dist, e);
    scan_nodes<<<1, 256>>>(n);
    edge_build<<<(e + 255) / 256, 256>>>(ei, p_dist, e);

    // ---- phase 3: feature embedding ----
    sgemm<<<gemm_grid(n, 64), gemm_t>>>(x, fe_w1, fe_b1, nullptr, p_h, n, 64, 28, 28, 0);
    bn_reduce<<<512, 256>>>(p_h, n);
    bn_apply<<<(n * 128 + 255) / 256, 256>>>(p_h, p_hn, bng, bnb, n);
    mgemm<<<mgrid, 256, MG_SMEM>>>(p_hn, p_wth + (size_t)25 * 16384,
                                   fe_b2, nullptr,
                                   p_v, n, 1, mtiles, 1, 128, 0);

    // ---- phase 4: interaction layers ----
    for (int l = 0; l < LL; l++) {
        const float* w1b = v1_b + (size_t)l * 128;
        const float* w2b = v2_b + (size_t)l * 128;
        __half* lw_h = p_wth + (size_t)(l * 4 + 0) * 16384;
        __half* w1_h = p_wth + (size_t)(l * 4 + 2) * 16384;
        __half* w2_h = p_wth + (size_t)(l * 4 + 3) * 16384;

        mgemm<<<mgrid, 256, MG_SMEM>>>(p_v, lw_h, nullptr, nullptr,
                                       (float*)p_vlinh, n, 0, mtiles, 1, 128, 1);
        edge_gather<<<ggrid, 256>>>(p_vlinh, p_ptab + (size_t)l * TABM * 128,
                                    p_aggh, n);
        fgemm<<<fgrid, 512, FG_SMEM>>>(p_aggh, w1_h, w2_h,
                                       w1b, w2b, p_v, p_v, n, ftiles, 1);
    }

    // ---- phase 5: readout ----
    fgemm<<<fgrid, 512, FG_SMEM>>>(p_v,
                                   p_wth + (size_t)24 * 16384,
                                   p_wth + (size_t)26 * 16384,
                                   p_u1b, p_u2b, nullptr, p_t1, n, ftiles, 0);
    cudaMemsetAsync(out, 0, (size_t)out_size * sizeof(float));
    node_out<<<((n + 127) / 128 * 32 + 255) / 256, 256>>>(p_t1, batch, out, n);
}